// round 2
// baseline (speedup 1.0000x reference)
#include <cuda_runtime.h>
#include <cuda_bf16.h>
#include <cstdint>

// ---------------- constants ----------------
#define BB 4
#define SS 2048
#define DD 512
#define HH 8
#define DHH 64
#define WW 128
#define NWIN 16
#define FFD 2048
#define TDD 1536   // 3*D
#define NROWS (BB*SS)   // 8192

// ---------------- scratch (no allocation allowed) ----------------
__device__ float g_qkv [NROWS * TDD];   // global-branch qkv
__device__ float g_qkl [NROWS * TDD];   // local-branch qkv (post-LN, post-rope)
__device__ float g_go  [NROWS * DD];    // global attn out (pre out_proj)
__device__ float g_x   [NROWS * DD];    // LN(src)
__device__ float g_lo  [NROWS * DD];    // local attn out (pre to_out)
__device__ float g_cat [NROWS * 2*DD];  // [go2 | lo2]
__device__ float g_src2[NROWS * DD];
__device__ float g_h1  [NROWS * DD];
__device__ float g_ff1 [NROWS * FFD];
__device__ float g_ff2 [NROWS * DD];

// ---------------- SGEMM: C = A(MxK) * B(NxK)^T + bias, optional relu ----------------
#define GBM 128
#define GBN 128
#define GBK 16

__global__ __launch_bounds__(256) void sgemm_nt(
    const float* __restrict__ A, const float* __restrict__ Bw,
    float* __restrict__ C, const float* __restrict__ bias,
    int M, int N, int K, int lda, int ldb, int ldc, int relu)
{
    __shared__ float As[GBK][GBM + 4];
    __shared__ float Bs[GBK][GBN + 4];

    const int tid = threadIdx.x;
    const int tx = tid & 15;        // 0..15
    const int ty = tid >> 4;        // 0..15
    const int rowBase = blockIdx.y * GBM;
    const int colBase = blockIdx.x * GBN;

    const int lr = tid >> 2;        // 0..63 (row within half-tile)
    const int lf = tid & 3;         // which float4 along k

    float acc[8][8];
    #pragma unroll
    for (int i = 0; i < 8; i++)
        #pragma unroll
        for (int j = 0; j < 8; j++) acc[i][j] = 0.f;

    for (int kt = 0; kt < K; kt += GBK) {
        #pragma unroll
        for (int hlf = 0; hlf < 2; hlf++) {
            int m = lr + hlf * 64;
            float4 va = *(const float4*)&A[(size_t)(rowBase + m) * lda + kt + lf * 4];
            As[lf*4+0][m] = va.x; As[lf*4+1][m] = va.y;
            As[lf*4+2][m] = va.z; As[lf*4+3][m] = va.w;
            float4 vb = *(const float4*)&Bw[(size_t)(colBase + m) * ldb + kt + lf * 4];
            Bs[lf*4+0][m] = vb.x; Bs[lf*4+1][m] = vb.y;
            Bs[lf*4+2][m] = vb.z; Bs[lf*4+3][m] = vb.w;
        }
        __syncthreads();

        #pragma unroll
        for (int k = 0; k < GBK; k++) {
            float a[8], b[8];
            *(float4*)&a[0] = *(const float4*)&As[k][ty*8];
            *(float4*)&a[4] = *(const float4*)&As[k][ty*8+4];
            *(float4*)&b[0] = *(const float4*)&Bs[k][tx*8];
            *(float4*)&b[4] = *(const float4*)&Bs[k][tx*8+4];
            #pragma unroll
            for (int i = 0; i < 8; i++)
                #pragma unroll
                for (int j = 0; j < 8; j++)
                    acc[i][j] += a[i] * b[j];
        }
        __syncthreads();
    }

    #pragma unroll
    for (int i = 0; i < 8; i++) {
        int r = rowBase + ty*8 + i;
        #pragma unroll
        for (int j = 0; j < 8; j++) {
            int c = colBase + tx*8 + j;
            float v = acc[i][j];
            if (bias) v += bias[c];
            if (relu) v = fmaxf(v, 0.f);
            C[(size_t)r * ldc + c] = v;
        }
    }
}

// ---------------- LayerNorm: out = LN(X (+R)) * g + b ; D=512, 128 threads ----------------
__global__ __launch_bounds__(128) void ln_kernel(
    const float* __restrict__ X, const float* __restrict__ R,
    const float* __restrict__ gam, const float* __restrict__ bet,
    float* __restrict__ out)
{
    __shared__ float red[8];
    const int row = blockIdx.x;
    const int tid = threadIdx.x;
    float4 v = ((const float4*)(X + (size_t)row * DD))[tid];
    if (R) {
        float4 r = ((const float4*)(R + (size_t)row * DD))[tid];
        v.x += r.x; v.y += r.y; v.z += r.z; v.w += r.w;
    }
    float s  = v.x + v.y + v.z + v.w;
    float sq = v.x*v.x + v.y*v.y + v.z*v.z + v.w*v.w;
    #pragma unroll
    for (int o = 16; o; o >>= 1) {
        s  += __shfl_xor_sync(0xffffffffu, s,  o);
        sq += __shfl_xor_sync(0xffffffffu, sq, o);
    }
    int w = tid >> 5;
    if ((tid & 31) == 0) { red[w*2] = s; red[w*2+1] = sq; }
    __syncthreads();
    s  = red[0] + red[2] + red[4] + red[6];
    sq = red[1] + red[3] + red[5] + red[7];
    float mean = s * (1.f / DD);
    float var  = sq * (1.f / DD) - mean * mean;
    float inv  = rsqrtf(var + 1e-5f);
    float4 gg = ((const float4*)gam)[tid];
    float4 bb = ((const float4*)bet)[tid];
    float4 r;
    r.x = (v.x - mean) * inv * gg.x + bb.x;
    r.y = (v.y - mean) * inv * gg.y + bb.y;
    r.z = (v.z - mean) * inv * gg.z + bb.z;
    r.w = (v.w - mean) * inv * gg.w + bb.w;
    ((float4*)(out + (size_t)row * DD))[tid] = r;
}

// ---------------- RoPE (in place on q and k halves of g_qkl) ----------------
__global__ __launch_bounds__(256) void rope_kernel(float* __restrict__ qkl)
{
    const int row = blockIdx.x;          // b*S + s
    const int pos = row & (SS - 1);
    const int t = threadIdx.x;           // 256 = H*32
    const int h = t >> 5;
    const int f = t & 31;
    float inv_freq = powf(10000.f, -(float)f * (1.f / 32.f));
    float fr = (float)pos * inv_freq;
    float c, sn;
    sincosf(fr, &sn, &c);
    float* base = qkl + (size_t)row * TDD + h * DHH + f;
    // q part
    float x1 = base[0], x2 = base[32];
    base[0]  = x1 * c - x2 * sn;
    base[32] = x2 * c + x1 * sn;
    // k part
    float* kb = base + DD;
    x1 = kb[0]; x2 = kb[32];
    kb[0]  = x1 * c - x2 * sn;
    kb[32] = x2 * c + x1 * sn;
}

// ---------------- Global attention (flash, no mask) ----------------
// grid (S/128, H, B), 128 threads, thread = one query row
#define TKEY 32
__global__ __launch_bounds__(128) void gattn_kernel(
    const float* __restrict__ qkv, float* __restrict__ go)
{
    __shared__ float ks[TKEY][DHH];
    __shared__ float vs[TKEY][DHH];
    const int b = blockIdx.z, h = blockIdx.y;
    const int tid = threadIdx.x;
    const int qrow = blockIdx.x * 128 + tid;
    const float scale = 0.125f;

    float q[DHH];
    {
        const float* qp = qkv + ((size_t)(b * SS + qrow)) * TDD + h * DHH;
        #pragma unroll
        for (int d4 = 0; d4 < 16; d4++) {
            float4 tq = *(const float4*)(qp + d4 * 4);
            q[d4*4+0] = tq.x * scale; q[d4*4+1] = tq.y * scale;
            q[d4*4+2] = tq.z * scale; q[d4*4+3] = tq.w * scale;
        }
    }
    float o[DHH];
    #pragma unroll
    for (int d = 0; d < DHH; d++) o[d] = 0.f;
    float m = -1e30f, l = 0.f;

    for (int kt = 0; kt < SS; kt += TKEY) {
        __syncthreads();
        #pragma unroll
        for (int r = 0; r < 4; r++) {
            int idx = tid + r * 128;          // float4 units, 0..511
            int krow = idx >> 4, f4 = idx & 15;
            const float* src = qkv + ((size_t)(b * SS + kt + krow)) * TDD + DD + h * DHH + f4 * 4;
            *(float4*)&ks[krow][f4*4] = *(const float4*)src;
            *(float4*)&vs[krow][f4*4] = *(const float4*)(src + DD);
        }
        __syncthreads();

        for (int ch = 0; ch < TKEY; ch += 8) {
            float sreg[8];
            #pragma unroll
            for (int j = 0; j < 8; j++) {
                float accd = 0.f;
                #pragma unroll
                for (int d4 = 0; d4 < 16; d4++) {
                    float4 k4 = *(const float4*)&ks[ch + j][d4*4];
                    accd += q[d4*4+0]*k4.x + q[d4*4+1]*k4.y + q[d4*4+2]*k4.z + q[d4*4+3]*k4.w;
                }
                sreg[j] = accd;
            }
            float cmax = sreg[0];
            #pragma unroll
            for (int j = 1; j < 8; j++) cmax = fmaxf(cmax, sreg[j]);
            float mn = fmaxf(m, cmax);
            float corr = __expf(m - mn);
            l *= corr;
            #pragma unroll
            for (int d = 0; d < DHH; d++) o[d] *= corr;
            #pragma unroll
            for (int j = 0; j < 8; j++) {
                float p = __expf(sreg[j] - mn);
                l += p;
                #pragma unroll
                for (int d4 = 0; d4 < 16; d4++) {
                    float4 v4 = *(const float4*)&vs[ch + j][d4*4];
                    o[d4*4+0] += p * v4.x; o[d4*4+1] += p * v4.y;
                    o[d4*4+2] += p * v4.z; o[d4*4+3] += p * v4.w;
                }
            }
            m = mn;
        }
    }
    float invl = 1.f / l;
    float* op = go + ((size_t)(b * SS + qrow)) * DD + h * DHH;
    #pragma unroll
    for (int d4 = 0; d4 < 16; d4++) {
        float4 r;
        r.x = o[d4*4+0]*invl; r.y = o[d4*4+1]*invl;
        r.z = o[d4*4+2]*invl; r.w = o[d4*4+3]*invl;
        *(float4*)(op + d4*4) = r;
    }
}

// ---------------- Local windowed attention (flash, masked) ----------------
// grid (NWIN, H, B), 128 threads, thread = query row i within window n
__global__ __launch_bounds__(128) void lattn_kernel(
    const float* __restrict__ qkl, float* __restrict__ lo)
{
    __shared__ float ks[TKEY][DHH];
    __shared__ float vs[TKEY][DHH];
    const int b = blockIdx.z, h = blockIdx.y, n = blockIdx.x;
    const int i = threadIdx.x;
    const int qrow = n * WW + i;
    const float scale = 0.125f;

    float q[DHH];
    {
        const float* qp = qkl + ((size_t)(b * SS + qrow)) * TDD + h * DHH;
        #pragma unroll
        for (int d4 = 0; d4 < 16; d4++) {
            float4 tq = *(const float4*)(qp + d4 * 4);
            q[d4*4+0] = tq.x * scale; q[d4*4+1] = tq.y * scale;
            q[d4*4+2] = tq.z * scale; q[d4*4+3] = tq.w * scale;
        }
    }
    float o[DHH];
    #pragma unroll
    for (int d = 0; d < DHH; d++) o[d] = 0.f;
    float m = -1e30f, l = 0.f;

    const int ktStart = (n == 0) ? WW : 0;   // window-coord over [0, 2W)
    for (int kt = ktStart; kt < 2 * WW; kt += TKEY) {
        __syncthreads();
        #pragma unroll
        for (int r = 0; r < 4; r++) {
            int idx = threadIdx.x + r * 128;
            int krow = idx >> 4, f4 = idx & 15;
            int seqrow = n * WW - WW + kt + krow;   // >= 0 given ktStart
            const float* src = qkl + ((size_t)(b * SS + seqrow)) * TDD + DD + h * DHH + f4 * 4;
            *(float4*)&ks[krow][f4*4] = *(const float4*)src;
            *(float4*)&vs[krow][f4*4] = *(const float4*)(src + DD);
        }
        __syncthreads();

        for (int ch = 0; ch < TKEY; ch += 8) {
            float sreg[8];
            #pragma unroll
            for (int j = 0; j < 8; j++) {
                float accd = 0.f;
                #pragma unroll
                for (int d4 = 0; d4 < 16; d4++) {
                    float4 k4 = *(const float4*)&ks[ch + j][d4*4];
                    accd += q[d4*4+0]*k4.x + q[d4*4+1]*k4.y + q[d4*4+2]*k4.z + q[d4*4+3]*k4.w;
                }
                int jw = kt + ch + j;                 // window coord
                if (jw >= WW && (jw - WW) > i) accd = -1e30f;  // causal inside current window
                sreg[j] = accd;
            }
            float cmax = sreg[0];
            #pragma unroll
            for (int j = 1; j < 8; j++) cmax = fmaxf(cmax, sreg[j]);
            float mn = fmaxf(m, cmax);
            float corr = __expf(m - mn);
            l *= corr;
            #pragma unroll
            for (int d = 0; d < DHH; d++) o[d] *= corr;
            #pragma unroll
            for (int j = 0; j < 8; j++) {
                float p = __expf(sreg[j] - mn);
                l += p;
                #pragma unroll
                for (int d4 = 0; d4 < 16; d4++) {
                    float4 v4 = *(const float4*)&vs[ch + j][d4*4];
                    o[d4*4+0] += p * v4.x; o[d4*4+1] += p * v4.y;
                    o[d4*4+2] += p * v4.z; o[d4*4+3] += p * v4.w;
                }
            }
            m = mn;
        }
    }
    float invl = 1.f / l;
    float* op = lo + ((size_t)(b * SS + qrow)) * DD + h * DHH;
    #pragma unroll
    for (int d4 = 0; d4 < 16; d4++) {
        float4 r;
        r.x = o[d4*4+0]*invl; r.y = o[d4*4+1]*invl;
        r.z = o[d4*4+2]*invl; r.w = o[d4*4+3]*invl;
        *(float4*)(op + d4*4) = r;
    }
}

// ---------------- launch ----------------
extern "C" void kernel_launch(void* const* d_in, const int* in_sizes, int n_in,
                              void* d_out, int out_size)
{
    (void)in_sizes; (void)n_in; (void)out_size;
    const float* src        = (const float*)d_in[0];
    const float* in_proj_w  = (const float*)d_in[1];
    const float* in_proj_b  = (const float*)d_in[2];
    const float* out_proj_w = (const float*)d_in[3];
    const float* out_proj_b = (const float*)d_in[4];
    const float* ln_g       = (const float*)d_in[5];
    const float* ln_b       = (const float*)d_in[6];
    const float* qkv_w      = (const float*)d_in[7];
    const float* to_out_w   = (const float*)d_in[8];
    const float* gl_w       = (const float*)d_in[9];
    const float* gl_b       = (const float*)d_in[10];
    const float* norm1_g    = (const float*)d_in[11];
    const float* norm1_b    = (const float*)d_in[12];
    const float* lin1_w     = (const float*)d_in[13];
    const float* lin1_b     = (const float*)d_in[14];
    const float* lin2_w     = (const float*)d_in[15];
    const float* lin2_b     = (const float*)d_in[16];
    const float* norm2_g    = (const float*)d_in[17];
    const float* norm2_b    = (const float*)d_in[18];
    float* outp = (float*)d_out;

    float *p_qkv, *p_qkl, *p_go, *p_x, *p_lo, *p_cat, *p_src2, *p_h1, *p_ff1, *p_ff2;
    cudaGetSymbolAddress((void**)&p_qkv,  g_qkv);
    cudaGetSymbolAddress((void**)&p_qkl,  g_qkl);
    cudaGetSymbolAddress((void**)&p_go,   g_go);
    cudaGetSymbolAddress((void**)&p_x,    g_x);
    cudaGetSymbolAddress((void**)&p_lo,   g_lo);
    cudaGetSymbolAddress((void**)&p_cat,  g_cat);
    cudaGetSymbolAddress((void**)&p_src2, g_src2);
    cudaGetSymbolAddress((void**)&p_h1,   g_h1);
    cudaGetSymbolAddress((void**)&p_ff1,  g_ff1);
    cudaGetSymbolAddress((void**)&p_ff2,  g_ff2);

    // 1. qkv = src @ in_proj_w^T + in_proj_b       (8192 x 1536 x 512)
    sgemm_nt<<<dim3(TDD/GBN, NROWS/GBM), 256>>>(src, in_proj_w, p_qkv, in_proj_b,
                                                NROWS, TDD, DD, DD, DD, TDD, 0);
    // 2. global attention -> g_go
    gattn_kernel<<<dim3(SS/128, HH, BB), 128>>>(p_qkv, p_go);
    // 3. go2 = g_go @ out_proj_w^T + out_proj_b -> cat[:, 0:512]
    sgemm_nt<<<dim3(DD/GBN, NROWS/GBM), 256>>>(p_go, out_proj_w, p_cat, out_proj_b,
                                               NROWS, DD, DD, DD, DD, 2*DD, 0);
    // 4. x = LN(src)
    ln_kernel<<<NROWS, 128>>>(src, nullptr, ln_g, ln_b, p_x);
    // 5. qkl = x @ qkv_w^T
    sgemm_nt<<<dim3(TDD/GBN, NROWS/GBM), 256>>>(p_x, qkv_w, p_qkl, nullptr,
                                                NROWS, TDD, DD, DD, DD, TDD, 0);
    // 6. rope on q,k parts of qkl
    rope_kernel<<<NROWS, 256>>>(p_qkl);
    // 7. local attention -> g_lo
    lattn_kernel<<<dim3(NWIN, HH, BB), 128>>>(p_qkl, p_lo);
    // 8. lo2 = g_lo @ to_out_w^T -> cat[:, 512:1024]
    sgemm_nt<<<dim3(DD/GBN, NROWS/GBM), 256>>>(p_lo, to_out_w, p_cat + DD, nullptr,
                                               NROWS, DD, DD, DD, DD, 2*DD, 0);
    // 9. src2 = cat @ gl_w^T + gl_b               (8192 x 512 x 1024)
    sgemm_nt<<<dim3(DD/GBN, NROWS/GBM), 256>>>(p_cat, gl_w, p_src2, gl_b,
                                               NROWS, DD, 2*DD, 2*DD, 2*DD, DD, 0);
    // 10. h1 = LN(src + src2)
    ln_kernel<<<NROWS, 128>>>(p_src2, src, norm1_g, norm1_b, p_h1);
    // 11. ff1 = relu(h1 @ lin1_w^T + lin1_b)      (8192 x 2048 x 512)
    sgemm_nt<<<dim3(FFD/GBN, NROWS/GBM), 256>>>(p_h1, lin1_w, p_ff1, lin1_b,
                                                NROWS, FFD, DD, DD, DD, FFD, 1);
    // 12. ff2 = ff1 @ lin2_w^T + lin2_b           (8192 x 512 x 2048)
    sgemm_nt<<<dim3(DD/GBN, NROWS/GBM), 256>>>(p_ff1, lin2_w, p_ff2, lin2_b,
                                               NROWS, DD, FFD, FFD, FFD, DD, 0);
    // 13. out = LN(h1 + ff2)
    ln_kernel<<<NROWS, 128>>>(p_ff2, p_h1, norm2_g, norm2_b, outp);
}

// round 7
// speedup vs baseline: 1.4360x; 1.4360x over previous
#include <cuda_runtime.h>
#include <cuda_bf16.h>
#include <cstdint>

// ---------------- constants ----------------
#define BB 4
#define SS 2048
#define DD 512
#define HH 8
#define DHH 64
#define WW 128
#define NWIN 16
#define FFD 2048
#define TDD 1536   // 3*D
#define NROWS (BB*SS)   // 8192

// ---------------- fp32 scratch ----------------
__device__ float g_qkv [NROWS * TDD];
__device__ float g_qkl [NROWS * TDD];
__device__ float g_go  [NROWS * DD];
__device__ float g_x   [NROWS * DD];
__device__ float g_lo  [NROWS * DD];
__device__ float g_cat [NROWS * 2*DD];
__device__ float g_src2[NROWS * DD];
__device__ float g_h1  [NROWS * DD];
__device__ float g_ff1 [NROWS * FFD];
__device__ float g_ff2 [NROWS * DD];

// ---------------- bf16 hi/lo split buffers ----------------
__device__ __nv_bfloat16 c_src_h[NROWS*DD],   c_src_l[NROWS*DD];
__device__ __nv_bfloat16 c_go_h [NROWS*DD],   c_go_l [NROWS*DD];
__device__ __nv_bfloat16 c_x_h  [NROWS*DD],   c_x_l  [NROWS*DD];
__device__ __nv_bfloat16 c_lo_h [NROWS*DD],   c_lo_l [NROWS*DD];
__device__ __nv_bfloat16 c_cat_h[NROWS*2*DD], c_cat_l[NROWS*2*DD];
__device__ __nv_bfloat16 c_h1_h [NROWS*DD],   c_h1_l [NROWS*DD];
__device__ __nv_bfloat16 c_ff1_h[NROWS*FFD],  c_ff1_l[NROWS*FFD];
__device__ __nv_bfloat16 c_w1_h[TDD*DD],  c_w1_l[TDD*DD];
__device__ __nv_bfloat16 c_w2_h[DD*DD],   c_w2_l[DD*DD];
__device__ __nv_bfloat16 c_w3_h[TDD*DD],  c_w3_l[TDD*DD];
__device__ __nv_bfloat16 c_w4_h[DD*DD],   c_w4_l[DD*DD];
__device__ __nv_bfloat16 c_w5_h[DD*2*DD], c_w5_l[DD*2*DD];
__device__ __nv_bfloat16 c_w6_h[FFD*DD],  c_w6_l[FFD*DD];
__device__ __nv_bfloat16 c_w7_h[DD*FFD],  c_w7_l[DD*FFD];

// ---------------- helpers ----------------
__device__ __forceinline__ uint32_t smem_u32(const void* p) {
    uint32_t a;
    asm("{ .reg .u64 t; cvta.to.shared.u64 t, %1; cvt.u32.u64 %0, t; }" : "=r"(a) : "l"(p));
    return a;
}

__device__ __forceinline__ void ldsm4(uint32_t* r, uint32_t a) {
    asm volatile("ldmatrix.sync.aligned.m8n8.x4.shared.b16 {%0,%1,%2,%3}, [%4];"
                 : "=r"(r[0]), "=r"(r[1]), "=r"(r[2]), "=r"(r[3]) : "r"(a));
}

__device__ __forceinline__ void mma16816(float* d, const uint32_t* a, const uint32_t* b) {
    asm volatile(
        "mma.sync.aligned.m16n8k16.row.col.f32.bf16.bf16.f32 "
        "{%0,%1,%2,%3}, {%4,%5,%6,%7}, {%8,%9}, {%0,%1,%2,%3};"
        : "+f"(d[0]), "+f"(d[1]), "+f"(d[2]), "+f"(d[3])
        : "r"(a[0]), "r"(a[1]), "r"(a[2]), "r"(a[3]), "r"(b[0]), "r"(b[1]));
}

// ---------------- hi/lo split conversion ----------------
__global__ __launch_bounds__(256) void cvt_kernel(
    const float* __restrict__ X, __nv_bfloat16* __restrict__ hi,
    __nv_bfloat16* __restrict__ lo, int n4)
{
    int i = blockIdx.x * 256 + threadIdx.x;
    if (i >= n4) return;
    float4 v = ((const float4*)X)[i];
    __nv_bfloat162 h01 = __floats2bfloat162_rn(v.x, v.y);
    __nv_bfloat162 h23 = __floats2bfloat162_rn(v.z, v.w);
    __nv_bfloat162 l01 = __floats2bfloat162_rn(v.x - __low2float(h01), v.y - __high2float(h01));
    __nv_bfloat162 l23 = __floats2bfloat162_rn(v.z - __low2float(h23), v.w - __high2float(h23));
    ((__nv_bfloat162*)hi)[2*i]   = h01;
    ((__nv_bfloat162*)hi)[2*i+1] = h23;
    ((__nv_bfloat162*)lo)[2*i]   = l01;
    ((__nv_bfloat162*)lo)[2*i+1] = l23;
}

// ---------------- mma.sync GEMM: C = A(MxK) * B(NxK)^T  (bf16 hi/lo 3-pass) ----------------
// CTA 128x128, 8 warps (warp tile 32x64), K chunk 32, double-buffered cp.async.
#define KC 32
#define ROWB 80                       // smem bytes per row (64B data + 16B pad)
#define TILEB (128*ROWB)              // 10240
#define STG (4*TILEB)                 // Ah, Al, Bh, Bl per stage = 40960
#define MM_SMEM (2*STG)               // 81920

__device__ __forceinline__ void mm_load_chunk(
    const __nv_bfloat16* __restrict__ Ah, const __nv_bfloat16* __restrict__ Al,
    const __nv_bfloat16* __restrict__ Bh, const __nv_bfloat16* __restrict__ Bl,
    int K, int rowBase, int colBase, int tid, int c, uint32_t stageBase)
{
    const __nv_bfloat16* mats[4] = {Ah, Al, Bh, Bl};
    #pragma unroll
    for (int it = 0; it < 8; it++) {
        int t = it >> 1;                       // matrix index (compile-time)
        int v = tid + (it & 1) * 256;          // 0..511
        int r = v >> 2;                        // row 0..127
        int ch = v & 3;                        // 16B chunk in row
        int rb = (t < 2) ? rowBase : colBase;
        const void* g = mats[t] + (size_t)(rb + r) * K + c * KC + ch * 8;
        uint32_t d = stageBase + t * TILEB + r * ROWB + ch * 16;
        asm volatile("cp.async.cg.shared.global [%0], [%1], 16;" :: "r"(d), "l"(g));
    }
    asm volatile("cp.async.commit_group;" ::: "memory");
}

__global__ __launch_bounds__(256, 2) void mm_tc(
    const __nv_bfloat16* __restrict__ Ah, const __nv_bfloat16* __restrict__ Al,
    const __nv_bfloat16* __restrict__ Bh, const __nv_bfloat16* __restrict__ Bl,
    float* __restrict__ C, const float* __restrict__ bias,
    int K, int ldc, int colOff, int relu)
{
    extern __shared__ char mm_smem[];
    const int tid = threadIdx.x;
    const int wid = tid >> 5, lane = tid & 31;
    const int wm = wid >> 1, wn = wid & 1;    // warp at rows wm*32, cols wn*64
    const int rowBase = blockIdx.y * 128;
    const int colBase = blockIdx.x * 128;
    const uint32_t sb = smem_u32(mm_smem);

    // ldmatrix per-lane addressing
    const int lrA = (lane & 7) + ((lane >> 3) & 1) * 8;   // A: row offset
    const int lcA = (lane >> 4) * 16;                     // A: byte offset in k-step
    const int lrB = (lane & 7) + (lane >> 4) * 8;         // B: row offset
    const int lcB = ((lane >> 3) & 1) * 16;               // B: byte offset

    float acc[2][8][4];
    #pragma unroll
    for (int i = 0; i < 2; i++)
        #pragma unroll
        for (int j = 0; j < 8; j++)
            #pragma unroll
            for (int e = 0; e < 4; e++) acc[i][j][e] = 0.f;

    const int CC = K / KC;
    mm_load_chunk(Ah, Al, Bh, Bl, K, rowBase, colBase, tid, 0, sb);

    for (int c = 0; c < CC; c++) {
        int s = c & 1;
        if (c + 1 < CC) {
            mm_load_chunk(Ah, Al, Bh, Bl, K, rowBase, colBase, tid, c + 1, sb + (s ^ 1) * STG);
            asm volatile("cp.async.wait_group 1;" ::: "memory");
        } else {
            asm volatile("cp.async.wait_group 0;" ::: "memory");
        }
        __syncthreads();

        uint32_t base = sb + s * STG;
        #pragma unroll
        for (int p = 0; p < 3; p++) {
            uint32_t aB = base + ((p == 1) ? TILEB : 0);
            uint32_t bB = base + ((p == 2) ? 3 * TILEB : 2 * TILEB);
            #pragma unroll
            for (int ks = 0; ks < 2; ks++) {
                uint32_t af[2][4];
                #pragma unroll
                for (int i = 0; i < 2; i++)
                    ldsm4(af[i], aB + (uint32_t)(wm * 32 + i * 16 + lrA) * ROWB + ks * 32 + lcA);
                uint32_t bf[8][2];
                #pragma unroll
                for (int j2 = 0; j2 < 4; j2++) {
                    uint32_t r4[4];
                    ldsm4(r4, bB + (uint32_t)(wn * 64 + j2 * 16 + lrB) * ROWB + ks * 32 + lcB);
                    bf[2*j2][0]   = r4[0]; bf[2*j2][1]   = r4[1];
                    bf[2*j2+1][0] = r4[2]; bf[2*j2+1][1] = r4[3];
                }
                #pragma unroll
                for (int i = 0; i < 2; i++)
                    #pragma unroll
                    for (int j = 0; j < 8; j++)
                        mma16816(acc[i][j], af[i], bf[j]);
            }
        }
        __syncthreads();
    }

    // epilogue
    #pragma unroll
    for (int i = 0; i < 2; i++) {
        int row0 = rowBase + wm * 32 + i * 16 + (lane >> 2);
        #pragma unroll
        for (int j = 0; j < 8; j++) {
            int col = colBase + wn * 64 + j * 8 + (lane & 3) * 2;
            float b0 = 0.f, b1 = 0.f;
            if (bias) { b0 = bias[col]; b1 = bias[col + 1]; }
            float2 v0 = make_float2(acc[i][j][0] + b0, acc[i][j][1] + b1);
            float2 v1 = make_float2(acc[i][j][2] + b0, acc[i][j][3] + b1);
            if (relu) {
                v0.x = fmaxf(v0.x, 0.f); v0.y = fmaxf(v0.y, 0.f);
                v1.x = fmaxf(v1.x, 0.f); v1.y = fmaxf(v1.y, 0.f);
            }
            *(float2*)(C + (size_t)row0 * ldc + colOff + col) = v0;
            *(float2*)(C + (size_t)(row0 + 8) * ldc + colOff + col) = v1;
        }
    }
}

// ---------------- LayerNorm ----------------
__global__ __launch_bounds__(128) void ln_kernel(
    const float* __restrict__ X, const float* __restrict__ R,
    const float* __restrict__ gam, const float* __restrict__ bet,
    float* __restrict__ out)
{
    __shared__ float red[8];
    const int row = blockIdx.x;
    const int tid = threadIdx.x;
    float4 v = ((const float4*)(X + (size_t)row * DD))[tid];
    if (R) {
        float4 r = ((const float4*)(R + (size_t)row * DD))[tid];
        v.x += r.x; v.y += r.y; v.z += r.z; v.w += r.w;
    }
    float s  = v.x + v.y + v.z + v.w;
    float sq = v.x*v.x + v.y*v.y + v.z*v.z + v.w*v.w;
    #pragma unroll
    for (int o = 16; o; o >>= 1) {
        s  += __shfl_xor_sync(0xffffffffu, s,  o);
        sq += __shfl_xor_sync(0xffffffffu, sq, o);
    }
    int w = tid >> 5;
    if ((tid & 31) == 0) { red[w*2] = s; red[w*2+1] = sq; }
    __syncthreads();
    s  = red[0] + red[2] + red[4] + red[6];
    sq = red[1] + red[3] + red[5] + red[7];
    float mean = s * (1.f / DD);
    float var  = sq * (1.f / DD) - mean * mean;
    float inv  = rsqrtf(var + 1e-5f);
    float4 gg = ((const float4*)gam)[tid];
    float4 bb = ((const float4*)bet)[tid];
    float4 r;
    r.x = (v.x - mean) * inv * gg.x + bb.x;
    r.y = (v.y - mean) * inv * gg.y + bb.y;
    r.z = (v.z - mean) * inv * gg.z + bb.z;
    r.w = (v.w - mean) * inv * gg.w + bb.w;
    ((float4*)(out + (size_t)row * DD))[tid] = r;
}

// ---------------- RoPE ----------------
__global__ __launch_bounds__(256) void rope_kernel(float* __restrict__ qkl)
{
    const int row = blockIdx.x;
    const int pos = row & (SS - 1);
    const int t = threadIdx.x;
    const int h = t >> 5;
    const int f = t & 31;
    float inv_freq = powf(10000.f, -(float)f * (1.f / 32.f));
    float fr = (float)pos * inv_freq;
    float c, sn;
    sincosf(fr, &sn, &c);
    float* base = qkl + (size_t)row * TDD + h * DHH + f;
    float x1 = base[0], x2 = base[32];
    base[0]  = x1 * c - x2 * sn;
    base[32] = x2 * c + x1 * sn;
    float* kb = base + DD;
    x1 = kb[0]; x2 = kb[32];
    kb[0]  = x1 * c - x2 * sn;
    kb[32] = x2 * c + x1 * sn;
}

// ---------------- Global attention (flash, no mask) ----------------
#define TKEY 32
__global__ __launch_bounds__(128) void gattn_kernel(
    const float* __restrict__ qkv, float* __restrict__ go)
{
    __shared__ float ks[TKEY][DHH];
    __shared__ float vs[TKEY][DHH];
    const int b = blockIdx.z, h = blockIdx.y;
    const int tid = threadIdx.x;
    const int qrow = blockIdx.x * 128 + tid;
    const float scale = 0.125f;

    float q[DHH];
    {
        const float* qp = qkv + ((size_t)(b * SS + qrow)) * TDD + h * DHH;
        #pragma unroll
        for (int d4 = 0; d4 < 16; d4++) {
            float4 tq = *(const float4*)(qp + d4 * 4);
            q[d4*4+0] = tq.x * scale; q[d4*4+1] = tq.y * scale;
            q[d4*4+2] = tq.z * scale; q[d4*4+3] = tq.w * scale;
        }
    }
    float o[DHH];
    #pragma unroll
    for (int d = 0; d < DHH; d++) o[d] = 0.f;
    float m = -1e30f, l = 0.f;

    for (int kt = 0; kt < SS; kt += TKEY) {
        __syncthreads();
        #pragma unroll
        for (int r = 0; r < 4; r++) {
            int idx = tid + r * 128;
            int krow = idx >> 4, f4 = idx & 15;
            const float* src = qkv + ((size_t)(b * SS + kt + krow)) * TDD + DD + h * DHH + f4 * 4;
            *(float4*)&ks[krow][f4*4] = *(const float4*)src;
            *(float4*)&vs[krow][f4*4] = *(const float4*)(src + DD);
        }
        __syncthreads();

        for (int ch = 0; ch < TKEY; ch += 8) {
            float sreg[8];
            #pragma unroll
            for (int j = 0; j < 8; j++) {
                float accd = 0.f;
                #pragma unroll
                for (int d4 = 0; d4 < 16; d4++) {
                    float4 k4 = *(const float4*)&ks[ch + j][d4*4];
                    accd += q[d4*4+0]*k4.x + q[d4*4+1]*k4.y + q[d4*4+2]*k4.z + q[d4*4+3]*k4.w;
                }
                sreg[j] = accd;
            }
            float cmax = sreg[0];
            #pragma unroll
            for (int j = 1; j < 8; j++) cmax = fmaxf(cmax, sreg[j]);
            float mn = fmaxf(m, cmax);
            float corr = __expf(m - mn);
            l *= corr;
            #pragma unroll
            for (int d = 0; d < DHH; d++) o[d] *= corr;
            #pragma unroll
            for (int j = 0; j < 8; j++) {
                float p = __expf(sreg[j] - mn);
                l += p;
                #pragma unroll
                for (int d4 = 0; d4 < 16; d4++) {
                    float4 v4 = *(const float4*)&vs[ch + j][d4*4];
                    o[d4*4+0] += p * v4.x; o[d4*4+1] += p * v4.y;
                    o[d4*4+2] += p * v4.z; o[d4*4+3] += p * v4.w;
                }
            }
            m = mn;
        }
    }
    float invl = 1.f / l;
    float* op = go + ((size_t)(b * SS + qrow)) * DD + h * DHH;
    #pragma unroll
    for (int d4 = 0; d4 < 16; d4++) {
        float4 r;
        r.x = o[d4*4+0]*invl; r.y = o[d4*4+1]*invl;
        r.z = o[d4*4+2]*invl; r.w = o[d4*4+3]*invl;
        *(float4*)(op + d4*4) = r;
    }
}

// ---------------- Local windowed attention (flash, masked) ----------------
__global__ __launch_bounds__(128) void lattn_kernel(
    const float* __restrict__ qkl, float* __restrict__ lo)
{
    __shared__ float ks[TKEY][DHH];
    __shared__ float vs[TKEY][DHH];
    const int b = blockIdx.z, h = blockIdx.y, n = blockIdx.x;
    const int i = threadIdx.x;
    const int qrow = n * WW + i;
    const float scale = 0.125f;

    float q[DHH];
    {
        const float* qp = qkl + ((size_t)(b * SS + qrow)) * TDD + h * DHH;
        #pragma unroll
        for (int d4 = 0; d4 < 16; d4++) {
            float4 tq = *(const float4*)(qp + d4 * 4);
            q[d4*4+0] = tq.x * scale; q[d4*4+1] = tq.y * scale;
            q[d4*4+2] = tq.z * scale; q[d4*4+3] = tq.w * scale;
        }
    }
    float o[DHH];
    #pragma unroll
    for (int d = 0; d < DHH; d++) o[d] = 0.f;
    float m = -1e30f, l = 0.f;

    const int ktStart = (n == 0) ? WW : 0;
    for (int kt = ktStart; kt < 2 * WW; kt += TKEY) {
        __syncthreads();
        #pragma unroll
        for (int r = 0; r < 4; r++) {
            int idx = threadIdx.x + r * 128;
            int krow = idx >> 4, f4 = idx & 15;
            int seqrow = n * WW - WW + kt + krow;
            const float* src = qkl + ((size_t)(b * SS + seqrow)) * TDD + DD + h * DHH + f4 * 4;
            *(float4*)&ks[krow][f4*4] = *(const float4*)src;
            *(float4*)&vs[krow][f4*4] = *(const float4*)(src + DD);
        }
        __syncthreads();

        for (int ch = 0; ch < TKEY; ch += 8) {
            float sreg[8];
            #pragma unroll
            for (int j = 0; j < 8; j++) {
                float accd = 0.f;
                #pragma unroll
                for (int d4 = 0; d4 < 16; d4++) {
                    float4 k4 = *(const float4*)&ks[ch + j][d4*4];
                    accd += q[d4*4+0]*k4.x + q[d4*4+1]*k4.y + q[d4*4+2]*k4.z + q[d4*4+3]*k4.w;
                }
                int jw = kt + ch + j;
                if (jw >= WW && (jw - WW) > i) accd = -1e30f;
                sreg[j] = accd;
            }
            float cmax = sreg[0];
            #pragma unroll
            for (int j = 1; j < 8; j++) cmax = fmaxf(cmax, sreg[j]);
            float mn = fmaxf(m, cmax);
            float corr = __expf(m - mn);
            l *= corr;
            #pragma unroll
            for (int d = 0; d < DHH; d++) o[d] *= corr;
            #pragma unroll
            for (int j = 0; j < 8; j++) {
                float p = __expf(sreg[j] - mn);
                l += p;
                #pragma unroll
                for (int d4 = 0; d4 < 16; d4++) {
                    float4 v4 = *(const float4*)&vs[ch + j][d4*4];
                    o[d4*4+0] += p * v4.x; o[d4*4+1] += p * v4.y;
                    o[d4*4+2] += p * v4.z; o[d4*4+3] += p * v4.w;
                }
            }
            m = mn;
        }
    }
    float invl = 1.f / l;
    float* op = lo + ((size_t)(b * SS + qrow)) * DD + h * DHH;
    #pragma unroll
    for (int d4 = 0; d4 < 16; d4++) {
        float4 r;
        r.x = o[d4*4+0]*invl; r.y = o[d4*4+1]*invl;
        r.z = o[d4*4+2]*invl; r.w = o[d4*4+3]*invl;
        *(float4*)(op + d4*4) = r;
    }
}

// ---------------- launch ----------------
static void cvt_launch(const float* x, __nv_bfloat16* h, __nv_bfloat16* l, int n) {
    int n4 = n / 4;
    cvt_kernel<<<(n4 + 255) / 256, 256>>>(x, h, l, n4);
}

extern "C" void kernel_launch(void* const* d_in, const int* in_sizes, int n_in,
                              void* d_out, int out_size)
{
    (void)in_sizes; (void)n_in; (void)out_size;
    const float* src        = (const float*)d_in[0];
    const float* in_proj_b  = (const float*)d_in[2];
    const float* out_proj_b = (const float*)d_in[4];
    const float* ln_g       = (const float*)d_in[5];
    const float* ln_b       = (const float*)d_in[6];
    const float* gl_b       = (const float*)d_in[10];
    const float* norm1_g    = (const float*)d_in[11];
    const float* norm1_b    = (const float*)d_in[12];
    const float* lin1_b     = (const float*)d_in[14];
    const float* lin2_b     = (const float*)d_in[16];
    const float* norm2_g    = (const float*)d_in[17];
    const float* norm2_b    = (const float*)d_in[18];
    float* outp = (float*)d_out;

    cudaFuncSetAttribute(mm_tc, cudaFuncAttributeMaxDynamicSharedMemorySize, MM_SMEM);

    float *p_qkv, *p_qkl, *p_go, *p_x, *p_lo, *p_cat, *p_src2, *p_h1, *p_ff1, *p_ff2;
    cudaGetSymbolAddress((void**)&p_qkv,  g_qkv);
    cudaGetSymbolAddress((void**)&p_qkl,  g_qkl);
    cudaGetSymbolAddress((void**)&p_go,   g_go);
    cudaGetSymbolAddress((void**)&p_x,    g_x);
    cudaGetSymbolAddress((void**)&p_lo,   g_lo);
    cudaGetSymbolAddress((void**)&p_cat,  g_cat);
    cudaGetSymbolAddress((void**)&p_src2, g_src2);
    cudaGetSymbolAddress((void**)&p_h1,   g_h1);
    cudaGetSymbolAddress((void**)&p_ff1,  g_ff1);
    cudaGetSymbolAddress((void**)&p_ff2,  g_ff2);

    __nv_bfloat16 *srcH,*srcL,*goH,*goL,*xH,*xL,*loH,*loL,*catH,*catL,*h1H,*h1L,*ff1H,*ff1L;
    __nv_bfloat16 *w1H,*w1L,*w2H,*w2L,*w3H,*w3L,*w4H,*w4L,*w5H,*w5L,*w6H,*w6L,*w7H,*w7L;
    cudaGetSymbolAddress((void**)&srcH, c_src_h); cudaGetSymbolAddress((void**)&srcL, c_src_l);
    cudaGetSymbolAddress((void**)&goH,  c_go_h);  cudaGetSymbolAddress((void**)&goL,  c_go_l);
    cudaGetSymbolAddress((void**)&xH,   c_x_h);   cudaGetSymbolAddress((void**)&xL,   c_x_l);
    cudaGetSymbolAddress((void**)&loH,  c_lo_h);  cudaGetSymbolAddress((void**)&loL,  c_lo_l);
    cudaGetSymbolAddress((void**)&catH, c_cat_h); cudaGetSymbolAddress((void**)&catL, c_cat_l);
    cudaGetSymbolAddress((void**)&h1H,  c_h1_h);  cudaGetSymbolAddress((void**)&h1L,  c_h1_l);
    cudaGetSymbolAddress((void**)&ff1H, c_ff1_h); cudaGetSymbolAddress((void**)&ff1L, c_ff1_l);
    cudaGetSymbolAddress((void**)&w1H, c_w1_h); cudaGetSymbolAddress((void**)&w1L, c_w1_l);
    cudaGetSymbolAddress((void**)&w2H, c_w2_h); cudaGetSymbolAddress((void**)&w2L, c_w2_l);
    cudaGetSymbolAddress((void**)&w3H, c_w3_h); cudaGetSymbolAddress((void**)&w3L, c_w3_l);
    cudaGetSymbolAddress((void**)&w4H, c_w4_h); cudaGetSymbolAddress((void**)&w4L, c_w4_l);
    cudaGetSymbolAddress((void**)&w5H, c_w5_h); cudaGetSymbolAddress((void**)&w5L, c_w5_l);
    cudaGetSymbolAddress((void**)&w6H, c_w6_h); cudaGetSymbolAddress((void**)&w6L, c_w6_l);
    cudaGetSymbolAddress((void**)&w7H, c_w7_h); cudaGetSymbolAddress((void**)&w7L, c_w7_l);

    // weight + src conversions
    cvt_launch((const float*)d_in[1],  w1H, w1L, TDD*DD);
    cvt_launch((const float*)d_in[3],  w2H, w2L, DD*DD);
    cvt_launch((const float*)d_in[7],  w3H, w3L, TDD*DD);
    cvt_launch((const float*)d_in[8],  w4H, w4L, DD*DD);
    cvt_launch((const float*)d_in[9],  w5H, w5L, DD*2*DD);
    cvt_launch((const float*)d_in[13], w6H, w6L, FFD*DD);
    cvt_launch((const float*)d_in[15], w7H, w7L, DD*FFD);
    cvt_launch(src, srcH, srcL, NROWS*DD);

    // 1. qkv = src @ in_proj_w^T + b   (8192 x 1536 x 512)
    mm_tc<<<dim3(TDD/128, NROWS/128), 256, MM_SMEM>>>(srcH, srcL, w1H, w1L,
        p_qkv, in_proj_b, DD, TDD, 0, 0);
    // 2. global attention
    gattn_kernel<<<dim3(SS/128, HH, BB), 128>>>(p_qkv, p_go);
    cvt_launch(p_go, goH, goL, NROWS*DD);
    // 3. go2 = go @ out_proj_w^T + b -> cat[:, 0:512]
    mm_tc<<<dim3(DD/128, NROWS/128), 256, MM_SMEM>>>(goH, goL, w2H, w2L,
        p_cat, out_proj_b, DD, 2*DD, 0, 0);
    // 4. x = LN(src)
    ln_kernel<<<NROWS, 128>>>(src, nullptr, ln_g, ln_b, p_x);
    cvt_launch(p_x, xH, xL, NROWS*DD);
    // 5. qkl = x @ qkv_w^T
    mm_tc<<<dim3(TDD/128, NROWS/128), 256, MM_SMEM>>>(xH, xL, w3H, w3L,
        p_qkl, nullptr, DD, TDD, 0, 0);
    // 6. rope
    rope_kernel<<<NROWS, 256>>>(p_qkl);
    // 7. local attention
    lattn_kernel<<<dim3(NWIN, HH, BB), 128>>>(p_qkl, p_lo);
    cvt_launch(p_lo, loH, loL, NROWS*DD);
    // 8. lo2 = lo @ to_out_w^T -> cat[:, 512:1024]
    mm_tc<<<dim3(DD/128, NROWS/128), 256, MM_SMEM>>>(loH, loL, w4H, w4L,
        p_cat, nullptr, DD, 2*DD, DD, 0);
    cvt_launch(p_cat, catH, catL, NROWS*2*DD);
    // 9. src2 = cat @ gl_w^T + gl_b   (8192 x 512 x 1024)
    mm_tc<<<dim3(DD/128, NROWS/128), 256, MM_SMEM>>>(catH, catL, w5H, w5L,
        p_src2, gl_b, 2*DD, DD, 0, 0);
    // 10. h1 = LN(src + src2)
    ln_kernel<<<NROWS, 128>>>(p_src2, src, norm1_g, norm1_b, p_h1);
    cvt_launch(p_h1, h1H, h1L, NROWS*DD);
    // 11. ff1 = relu(h1 @ lin1_w^T + b)   (8192 x 2048 x 512)
    mm_tc<<<dim3(FFD/128, NROWS/128), 256, MM_SMEM>>>(h1H, h1L, w6H, w6L,
        p_ff1, lin1_b, DD, FFD, 0, 1);
    cvt_launch(p_ff1, ff1H, ff1L, NROWS*FFD);
    // 12. ff2 = ff1 @ lin2_w^T + b   (8192 x 512 x 2048)
    mm_tc<<<dim3(DD/128, NROWS/128), 256, MM_SMEM>>>(ff1H, ff1L, w7H, w7L,
        p_ff2, lin2_b, FFD, DD, 0, 0);
    // 13. out = LN(h1 + ff2)
    ln_kernel<<<NROWS, 128>>>(p_ff2, p_h1, norm2_g, norm2_b, outp);
}

// round 12
// speedup vs baseline: 2.7629x; 1.9240x over previous
#include <cuda_runtime.h>
#include <cuda_bf16.h>
#include <cstdint>

// ---------------- constants ----------------
#define BB 4
#define SS 2048
#define DD 512
#define HH 8
#define DHH 64
#define WW 128
#define NWIN 16
#define FFD 2048
#define TDD 1536   // 3*D
#define NROWS (BB*SS)   // 8192

// ---------------- fp32 scratch ----------------
__device__ float g_qkl [NROWS * TDD];
__device__ float g_x   [NROWS * DD];
__device__ float g_src2[NROWS * DD];
__device__ float g_h1  [NROWS * DD];
__device__ float g_ff2 [NROWS * DD];

// ---------------- bf16 hi/lo split buffers ----------------
__device__ __nv_bfloat16 c_src_h[NROWS*DD],   c_src_l[NROWS*DD];
__device__ __nv_bfloat16 c_qkv_h[NROWS*TDD],  c_qkv_l[NROWS*TDD];
__device__ __nv_bfloat16 c_go_h [NROWS*DD],   c_go_l [NROWS*DD];
__device__ __nv_bfloat16 c_x_h  [NROWS*DD],   c_x_l  [NROWS*DD];
__device__ __nv_bfloat16 c_lo_h [NROWS*DD],   c_lo_l [NROWS*DD];
__device__ __nv_bfloat16 c_cat_h[NROWS*2*DD], c_cat_l[NROWS*2*DD];
__device__ __nv_bfloat16 c_h1_h [NROWS*DD],   c_h1_l [NROWS*DD];
__device__ __nv_bfloat16 c_ff1_h[NROWS*FFD],  c_ff1_l[NROWS*FFD];
__device__ __nv_bfloat16 c_w1_h[TDD*DD],  c_w1_l[TDD*DD];
__device__ __nv_bfloat16 c_w2_h[DD*DD],   c_w2_l[DD*DD];
__device__ __nv_bfloat16 c_w3_h[TDD*DD],  c_w3_l[TDD*DD];
__device__ __nv_bfloat16 c_w4_h[DD*DD],   c_w4_l[DD*DD];
__device__ __nv_bfloat16 c_w5_h[DD*2*DD], c_w5_l[DD*2*DD];
__device__ __nv_bfloat16 c_w6_h[FFD*DD],  c_w6_l[FFD*DD];
__device__ __nv_bfloat16 c_w7_h[DD*FFD],  c_w7_l[DD*FFD];

// ---------------- helpers ----------------
__device__ __forceinline__ uint32_t smem_u32(const void* p) {
    uint32_t a;
    asm("{ .reg .u64 t; cvta.to.shared.u64 t, %1; cvt.u32.u64 %0, t; }" : "=r"(a) : "l"(p));
    return a;
}

__device__ __forceinline__ void ldsm4(uint32_t* r, uint32_t a) {
    asm volatile("ldmatrix.sync.aligned.m8n8.x4.shared.b16 {%0,%1,%2,%3}, [%4];"
                 : "=r"(r[0]), "=r"(r[1]), "=r"(r[2]), "=r"(r[3]) : "r"(a));
}

__device__ __forceinline__ void ldsm4t(uint32_t* r, uint32_t a) {
    asm volatile("ldmatrix.sync.aligned.m8n8.x4.trans.shared.b16 {%0,%1,%2,%3}, [%4];"
                 : "=r"(r[0]), "=r"(r[1]), "=r"(r[2]), "=r"(r[3]) : "r"(a));
}

__device__ __forceinline__ void mma16816(float* d, const uint32_t* a, const uint32_t* b) {
    asm volatile(
        "mma.sync.aligned.m16n8k16.row.col.f32.bf16.bf16.f32 "
        "{%0,%1,%2,%3}, {%4,%5,%6,%7}, {%8,%9}, {%0,%1,%2,%3};"
        : "+f"(d[0]), "+f"(d[1]), "+f"(d[2]), "+f"(d[3])
        : "r"(a[0]), "r"(a[1]), "r"(a[2]), "r"(a[3]), "r"(b[0]), "r"(b[1]));
}

__device__ __forceinline__ uint32_t packbf2(float a, float b) {
    __nv_bfloat162 t = __floats2bfloat162_rn(a, b);
    return *(uint32_t*)&t;
}

// ---------------- hi/lo split conversion ----------------
__global__ __launch_bounds__(256) void cvt_kernel(
    const float* __restrict__ X, __nv_bfloat16* __restrict__ hi,
    __nv_bfloat16* __restrict__ lo, int n4)
{
    int i = blockIdx.x * 256 + threadIdx.x;
    if (i >= n4) return;
    float4 v = ((const float4*)X)[i];
    __nv_bfloat162 h01 = __floats2bfloat162_rn(v.x, v.y);
    __nv_bfloat162 h23 = __floats2bfloat162_rn(v.z, v.w);
    __nv_bfloat162 l01 = __floats2bfloat162_rn(v.x - __low2float(h01), v.y - __high2float(h01));
    __nv_bfloat162 l23 = __floats2bfloat162_rn(v.z - __low2float(h23), v.w - __high2float(h23));
    ((__nv_bfloat162*)hi)[2*i]   = h01;
    ((__nv_bfloat162*)hi)[2*i+1] = h23;
    ((__nv_bfloat162*)lo)[2*i]   = l01;
    ((__nv_bfloat162*)lo)[2*i+1] = l23;
}

// ---------------- mma.sync GEMM: C = A(MxK) * B(NxK)^T  (bf16 hi/lo 3-pass) ----------------
#define KC 32
#define ROWB 80
#define TILEB (128*ROWB)
#define STG (4*TILEB)
#define MM_SMEM (2*STG)

__device__ __forceinline__ void mm_load_chunk(
    const __nv_bfloat16* __restrict__ Ah, const __nv_bfloat16* __restrict__ Al,
    const __nv_bfloat16* __restrict__ Bh, const __nv_bfloat16* __restrict__ Bl,
    int K, int rowBase, int colBase, int tid, int c, uint32_t stageBase)
{
    const __nv_bfloat16* mats[4] = {Ah, Al, Bh, Bl};
    #pragma unroll
    for (int it = 0; it < 8; it++) {
        int t = it >> 1;
        int v = tid + (it & 1) * 256;
        int r = v >> 2;
        int ch = v & 3;
        int rb = (t < 2) ? rowBase : colBase;
        const void* g = mats[t] + (size_t)(rb + r) * K + c * KC + ch * 8;
        uint32_t d = stageBase + t * TILEB + r * ROWB + ch * 16;
        asm volatile("cp.async.cg.shared.global [%0], [%1], 16;" :: "r"(d), "l"(g));
    }
    asm volatile("cp.async.commit_group;" ::: "memory");
}

__global__ __launch_bounds__(256, 2) void mm_tc(
    const __nv_bfloat16* __restrict__ Ah, const __nv_bfloat16* __restrict__ Al,
    const __nv_bfloat16* __restrict__ Bh, const __nv_bfloat16* __restrict__ Bl,
    float* __restrict__ C, const float* __restrict__ bias,
    int K, int ldc, int colOff, int relu,
    __nv_bfloat16* __restrict__ Ch, __nv_bfloat16* __restrict__ Cl)
{
    extern __shared__ char mm_smem[];
    const int tid = threadIdx.x;
    const int wid = tid >> 5, lane = tid & 31;
    const int wm = wid >> 1, wn = wid & 1;
    const int rowBase = blockIdx.y * 128;
    const int colBase = blockIdx.x * 128;
    const uint32_t sb = smem_u32(mm_smem);

    const int lrA = (lane & 15);
    const int lcA = (lane >> 4) * 16;
    const int lrB = (lane & 7) + (lane >> 4) * 8;
    const int lcB = ((lane >> 3) & 1) * 16;

    float acc[2][8][4];
    #pragma unroll
    for (int i = 0; i < 2; i++)
        #pragma unroll
        for (int j = 0; j < 8; j++)
            #pragma unroll
            for (int e = 0; e < 4; e++) acc[i][j][e] = 0.f;

    const int CC = K / KC;
    mm_load_chunk(Ah, Al, Bh, Bl, K, rowBase, colBase, tid, 0, sb);

    for (int c = 0; c < CC; c++) {
        int s = c & 1;
        if (c + 1 < CC) {
            mm_load_chunk(Ah, Al, Bh, Bl, K, rowBase, colBase, tid, c + 1, sb + (s ^ 1) * STG);
            asm volatile("cp.async.wait_group 1;" ::: "memory");
        } else {
            asm volatile("cp.async.wait_group 0;" ::: "memory");
        }
        __syncthreads();

        uint32_t base = sb + s * STG;
        #pragma unroll
        for (int p = 0; p < 3; p++) {
            uint32_t aB = base + ((p == 1) ? TILEB : 0);
            uint32_t bB = base + ((p == 2) ? 3 * TILEB : 2 * TILEB);
            #pragma unroll
            for (int ks = 0; ks < 2; ks++) {
                uint32_t af[2][4];
                #pragma unroll
                for (int i = 0; i < 2; i++)
                    ldsm4(af[i], aB + (uint32_t)(wm * 32 + i * 16 + lrA) * ROWB + ks * 32 + lcA);
                uint32_t bf[8][2];
                #pragma unroll
                for (int j2 = 0; j2 < 4; j2++) {
                    uint32_t r4[4];
                    ldsm4(r4, bB + (uint32_t)(wn * 64 + j2 * 16 + lrB) * ROWB + ks * 32 + lcB);
                    bf[2*j2][0]   = r4[0]; bf[2*j2][1]   = r4[1];
                    bf[2*j2+1][0] = r4[2]; bf[2*j2+1][1] = r4[3];
                }
                #pragma unroll
                for (int i = 0; i < 2; i++)
                    #pragma unroll
                    for (int j = 0; j < 8; j++)
                        mma16816(acc[i][j], af[i], bf[j]);
            }
        }
        __syncthreads();
    }

    // epilogue
    #pragma unroll
    for (int i = 0; i < 2; i++) {
        int row0 = rowBase + wm * 32 + i * 16 + (lane >> 2);
        #pragma unroll
        for (int j = 0; j < 8; j++) {
            int col = colBase + wn * 64 + j * 8 + (lane & 3) * 2;
            float b0 = 0.f, b1 = 0.f;
            if (bias) { b0 = bias[col]; b1 = bias[col + 1]; }
            float2 v0 = make_float2(acc[i][j][0] + b0, acc[i][j][1] + b1);
            float2 v1 = make_float2(acc[i][j][2] + b0, acc[i][j][3] + b1);
            if (relu) {
                v0.x = fmaxf(v0.x, 0.f); v0.y = fmaxf(v0.y, 0.f);
                v1.x = fmaxf(v1.x, 0.f); v1.y = fmaxf(v1.y, 0.f);
            }
            size_t o0 = (size_t)row0 * ldc + colOff + col;
            size_t o1 = (size_t)(row0 + 8) * ldc + colOff + col;
            if (C) {
                *(float2*)(C + o0) = v0;
                *(float2*)(C + o1) = v1;
            }
            if (Ch) {
                __nv_bfloat162 h0 = __floats2bfloat162_rn(v0.x, v0.y);
                __nv_bfloat162 h1v = __floats2bfloat162_rn(v1.x, v1.y);
                __nv_bfloat162 l0 = __floats2bfloat162_rn(v0.x - __low2float(h0), v0.y - __high2float(h0));
                __nv_bfloat162 l1v = __floats2bfloat162_rn(v1.x - __low2float(h1v), v1.y - __high2float(h1v));
                *(__nv_bfloat162*)(Ch + o0) = h0;
                *(__nv_bfloat162*)(Ch + o1) = h1v;
                *(__nv_bfloat162*)(Cl + o0) = l0;
                *(__nv_bfloat162*)(Cl + o1) = l1v;
            }
        }
    }
}

// ---------------- tensor-core global flash attention ----------------
// CTA: 4 warps; Q tile 64 rows (warp=16 rows), K tile 64 keys, DH=64.
// Tiles: 64 rows x 128B data, row stride 144B. Layout: Qh, Ql, then 2 stages of {Kh, Kl, Vh}.
#define AROW 144
#define GA_TILE 9216
#define GA_STG (3*GA_TILE)
#define GA_SMEM (2*GA_TILE + 2*GA_STG)

__device__ __forceinline__ void ga_load_kv(
    const __nv_bfloat16* __restrict__ qkvH, const __nv_bfloat16* __restrict__ qkvL,
    int b, int h, int kt, int tid, uint32_t stBase)
{
    #pragma unroll
    for (int m = 0; m < 3; m++) {
        const __nv_bfloat16* srcb = (m == 1) ? qkvL : qkvH;
        int col = ((m < 2) ? DD : 2 * DD) + h * DHH;
        #pragma unroll
        for (int i = 0; i < 4; i++) {
            int idx = tid + i * 128;           // 0..511 = 64 rows x 8 chunks
            int r = idx >> 3, ch = idx & 7;
            const void* g = srcb + (size_t)(b * SS + kt * 64 + r) * TDD + col + ch * 8;
            uint32_t d = stBase + m * GA_TILE + r * AROW + ch * 16;
            asm volatile("cp.async.cg.shared.global [%0], [%1], 16;" :: "r"(d), "l"(g));
        }
    }
    asm volatile("cp.async.commit_group;" ::: "memory");
}

__global__ __launch_bounds__(128) void gattn_tc(
    const __nv_bfloat16* __restrict__ qkvH, const __nv_bfloat16* __restrict__ qkvL,
    __nv_bfloat16* __restrict__ goH, __nv_bfloat16* __restrict__ goL)
{
    extern __shared__ char ga_smem[];
    const int tid = threadIdx.x, wid = tid >> 5, lane = tid & 31;
    const int qt = blockIdx.x, h = blockIdx.y, b = blockIdx.z;
    const uint32_t sb = smem_u32(ga_smem);

    // Q hi/lo load (group 0): 64 rows x 128B each
    #pragma unroll
    for (int m = 0; m < 2; m++) {
        const __nv_bfloat16* srcb = m ? qkvL : qkvH;
        #pragma unroll
        for (int i = 0; i < 4; i++) {
            int idx = tid + i * 128;
            int r = idx >> 3, ch = idx & 7;
            const void* g = srcb + (size_t)(b * SS + qt * 64 + r) * TDD + h * DHH + ch * 8;
            uint32_t d = sb + m * GA_TILE + r * AROW + ch * 16;
            asm volatile("cp.async.cg.shared.global [%0], [%1], 16;" :: "r"(d), "l"(g));
        }
    }
    asm volatile("cp.async.commit_group;" ::: "memory");
    // first KV stage (group 1)
    ga_load_kv(qkvH, qkvL, b, h, 0, tid, sb + 2 * GA_TILE);

    asm volatile("cp.async.wait_group 1;" ::: "memory");   // Q done
    __syncthreads();

    const int lr16 = lane & 15;
    const int hi16 = lane >> 4;
    uint32_t qfh[4][4], qfl[4][4];
    #pragma unroll
    for (int ks = 0; ks < 4; ks++) {
        uint32_t ab = sb + (uint32_t)(wid * 16 + lr16) * AROW + ks * 32 + hi16 * 16;
        ldsm4(qfh[ks], ab);
        ldsm4(qfl[ks], ab + GA_TILE);
    }

    float oacc[8][4];
    #pragma unroll
    for (int j = 0; j < 8; j++)
        #pragma unroll
        for (int e = 0; e < 4; e++) oacc[j][e] = 0.f;
    float m0 = -1e30f, m1 = -1e30f, l0 = 0.f, l1 = 0.f;
    const int lrB = (lane & 7) + (lane >> 4) * 8;
    const int lcB = ((lane >> 3) & 1) * 16;

    for (int kt = 0; kt < SS / 64; kt++) {
        int s = kt & 1;
        uint32_t st = sb + 2 * GA_TILE + s * GA_STG;
        if (kt + 1 < SS / 64) {
            ga_load_kv(qkvH, qkvL, b, h, kt + 1, tid, sb + 2 * GA_TILE + (s ^ 1) * GA_STG);
            asm volatile("cp.async.wait_group 1;" ::: "memory");
        } else {
            asm volatile("cp.async.wait_group 0;" ::: "memory");
        }
        __syncthreads();

        // S = Q K^T  (3-pass hi/lo)
        float sacc[8][4];
        #pragma unroll
        for (int j = 0; j < 8; j++)
            #pragma unroll
            for (int e = 0; e < 4; e++) sacc[j][e] = 0.f;

        #pragma unroll
        for (int ks = 0; ks < 4; ks++) {
            uint32_t kf[4][4];
            #pragma unroll
            for (int n2 = 0; n2 < 4; n2++)
                ldsm4(kf[n2], st + (uint32_t)(n2 * 16 + lrB) * AROW + ks * 32 + lcB);
            #pragma unroll
            for (int j = 0; j < 8; j++) {
                mma16816(sacc[j], qfh[ks], &kf[j >> 1][(j & 1) * 2]);
                mma16816(sacc[j], qfl[ks], &kf[j >> 1][(j & 1) * 2]);
            }
            uint32_t kg[4][4];
            #pragma unroll
            for (int n2 = 0; n2 < 4; n2++)
                ldsm4(kg[n2], st + GA_TILE + (uint32_t)(n2 * 16 + lrB) * AROW + ks * 32 + lcB);
            #pragma unroll
            for (int j = 0; j < 8; j++)
                mma16816(sacc[j], qfh[ks], &kg[j >> 1][(j & 1) * 2]);
        }

        // online softmax (rows r0=lane>>2 and r0+8)
        float t0 = -1e30f, t1 = -1e30f;
        #pragma unroll
        for (int j = 0; j < 8; j++) {
            sacc[j][0] *= 0.125f; sacc[j][1] *= 0.125f;
            sacc[j][2] *= 0.125f; sacc[j][3] *= 0.125f;
            t0 = fmaxf(t0, fmaxf(sacc[j][0], sacc[j][1]));
            t1 = fmaxf(t1, fmaxf(sacc[j][2], sacc[j][3]));
        }
        t0 = fmaxf(t0, __shfl_xor_sync(0xffffffffu, t0, 1));
        t0 = fmaxf(t0, __shfl_xor_sync(0xffffffffu, t0, 2));
        t1 = fmaxf(t1, __shfl_xor_sync(0xffffffffu, t1, 1));
        t1 = fmaxf(t1, __shfl_xor_sync(0xffffffffu, t1, 2));
        float mn0 = fmaxf(m0, t0), mn1 = fmaxf(m1, t1);
        float c0 = __expf(m0 - mn0), c1 = __expf(m1 - mn1);
        float s0 = 0.f, s1 = 0.f;
        #pragma unroll
        for (int j = 0; j < 8; j++) {
            sacc[j][0] = __expf(sacc[j][0] - mn0);
            sacc[j][1] = __expf(sacc[j][1] - mn0);
            sacc[j][2] = __expf(sacc[j][2] - mn1);
            sacc[j][3] = __expf(sacc[j][3] - mn1);
            s0 += sacc[j][0] + sacc[j][1];
            s1 += sacc[j][2] + sacc[j][3];
        }
        s0 += __shfl_xor_sync(0xffffffffu, s0, 1);
        s0 += __shfl_xor_sync(0xffffffffu, s0, 2);
        s1 += __shfl_xor_sync(0xffffffffu, s1, 1);
        s1 += __shfl_xor_sync(0xffffffffu, s1, 2);
        l0 = l0 * c0 + s0;
        l1 = l1 * c1 + s1;
        m0 = mn0; m1 = mn1;
        #pragma unroll
        for (int j = 0; j < 8; j++) {
            oacc[j][0] *= c0; oacc[j][1] *= c0;
            oacc[j][2] *= c1; oacc[j][3] *= c1;
        }

        // O += P V
        #pragma unroll
        for (int kp = 0; kp < 4; kp++) {
            uint32_t pf[4];
            pf[0] = packbf2(sacc[2*kp][0],   sacc[2*kp][1]);
            pf[1] = packbf2(sacc[2*kp][2],   sacc[2*kp][3]);
            pf[2] = packbf2(sacc[2*kp+1][0], sacc[2*kp+1][1]);
            pf[3] = packbf2(sacc[2*kp+1][2], sacc[2*kp+1][3]);
            uint32_t vf[4][4];
            #pragma unroll
            for (int n2 = 0; n2 < 4; n2++)
                ldsm4t(vf[n2], st + 2 * GA_TILE + (uint32_t)(kp * 16 + lr16) * AROW + n2 * 32 + hi16 * 16);
            #pragma unroll
            for (int j = 0; j < 8; j++)
                mma16816(oacc[j], pf, &vf[j >> 1][(j & 1) * 2]);
        }
        __syncthreads();
    }

    // epilogue: normalize and write hi/lo bf16
    float il0 = 1.f / l0, il1 = 1.f / l1;
    int r0g = b * SS + qt * 64 + wid * 16 + (lane >> 2);
    __nv_bfloat16* oh0 = goH + (size_t)r0g * DD + h * DHH;
    __nv_bfloat16* ol0 = goL + (size_t)r0g * DD + h * DHH;
    __nv_bfloat16* oh1 = oh0 + (size_t)8 * DD;
    __nv_bfloat16* ol1 = ol0 + (size_t)8 * DD;
    #pragma unroll
    for (int j = 0; j < 8; j++) {
        int col = j * 8 + (lane & 3) * 2;
        float a0 = oacc[j][0] * il0, a1 = oacc[j][1] * il0;
        float b0 = oacc[j][2] * il1, b1 = oacc[j][3] * il1;
        __nv_bfloat162 h0 = __floats2bfloat162_rn(a0, a1);
        __nv_bfloat162 h1v = __floats2bfloat162_rn(b0, b1);
        __nv_bfloat162 lo0 = __floats2bfloat162_rn(a0 - __low2float(h0), a1 - __high2float(h0));
        __nv_bfloat162 lo1 = __floats2bfloat162_rn(b0 - __low2float(h1v), b1 - __high2float(h1v));
        *(__nv_bfloat162*)(oh0 + col) = h0;
        *(__nv_bfloat162*)(ol0 + col) = lo0;
        *(__nv_bfloat162*)(oh1 + col) = h1v;
        *(__nv_bfloat162*)(ol1 + col) = lo1;
    }
}

// ---------------- LayerNorm (optional fused hi/lo output) ----------------
__global__ __launch_bounds__(128) void ln_kernel(
    const float* __restrict__ X, const float* __restrict__ R,
    const float* __restrict__ gam, const float* __restrict__ bet,
    float* __restrict__ out,
    __nv_bfloat16* __restrict__ outH, __nv_bfloat16* __restrict__ outL)
{
    __shared__ float red[8];
    const int row = blockIdx.x;
    const int tid = threadIdx.x;
    float4 v = ((const float4*)(X + (size_t)row * DD))[tid];
    if (R) {
        float4 r = ((const float4*)(R + (size_t)row * DD))[tid];
        v.x += r.x; v.y += r.y; v.z += r.z; v.w += r.w;
    }
    float s  = v.x + v.y + v.z + v.w;
    float sq = v.x*v.x + v.y*v.y + v.z*v.z + v.w*v.w;
    #pragma unroll
    for (int o = 16; o; o >>= 1) {
        s  += __shfl_xor_sync(0xffffffffu, s,  o);
        sq += __shfl_xor_sync(0xffffffffu, sq, o);
    }
    int w = tid >> 5;
    if ((tid & 31) == 0) { red[w*2] = s; red[w*2+1] = sq; }
    __syncthreads();
    s  = red[0] + red[2] + red[4] + red[6];
    sq = red[1] + red[3] + red[5] + red[7];
    float mean = s * (1.f / DD);
    float var  = sq * (1.f / DD) - mean * mean;
    float inv  = rsqrtf(var + 1e-5f);
    float4 gg = ((const float4*)gam)[tid];
    float4 bb = ((const float4*)bet)[tid];
    float4 r;
    r.x = (v.x - mean) * inv * gg.x + bb.x;
    r.y = (v.y - mean) * inv * gg.y + bb.y;
    r.z = (v.z - mean) * inv * gg.z + bb.z;
    r.w = (v.w - mean) * inv * gg.w + bb.w;
    ((float4*)(out + (size_t)row * DD))[tid] = r;
    if (outH) {
        __nv_bfloat162 h01 = __floats2bfloat162_rn(r.x, r.y);
        __nv_bfloat162 h23 = __floats2bfloat162_rn(r.z, r.w);
        __nv_bfloat162 l01 = __floats2bfloat162_rn(r.x - __low2float(h01), r.y - __high2float(h01));
        __nv_bfloat162 l23 = __floats2bfloat162_rn(r.z - __low2float(h23), r.w - __high2float(h23));
        size_t o = (size_t)row * DD + tid * 4;
        *(__nv_bfloat162*)(outH + o)     = h01;
        *(__nv_bfloat162*)(outH + o + 2) = h23;
        *(__nv_bfloat162*)(outL + o)     = l01;
        *(__nv_bfloat162*)(outL + o + 2) = l23;
    }
}

// ---------------- RoPE ----------------
__global__ __launch_bounds__(256) void rope_kernel(float* __restrict__ qkl)
{
    const int row = blockIdx.x;
    const int pos = row & (SS - 1);
    const int t = threadIdx.x;
    const int h = t >> 5;
    const int f = t & 31;
    float inv_freq = powf(10000.f, -(float)f * (1.f / 32.f));
    float fr = (float)pos * inv_freq;
    float c, sn;
    sincosf(fr, &sn, &c);
    float* base = qkl + (size_t)row * TDD + h * DHH + f;
    float x1 = base[0], x2 = base[32];
    base[0]  = x1 * c - x2 * sn;
    base[32] = x2 * c + x1 * sn;
    float* kb = base + DD;
    x1 = kb[0]; x2 = kb[32];
    kb[0]  = x1 * c - x2 * sn;
    kb[32] = x2 * c + x1 * sn;
}

// ---------------- Local windowed attention (flash, masked; hi/lo bf16 out) ----------------
#define TKEY 32
__global__ __launch_bounds__(128) void lattn_kernel(
    const float* __restrict__ qkl,
    __nv_bfloat16* __restrict__ loH, __nv_bfloat16* __restrict__ loL)
{
    __shared__ float ks[TKEY][DHH];
    __shared__ float vs[TKEY][DHH];
    const int b = blockIdx.z, h = blockIdx.y, n = blockIdx.x;
    const int i = threadIdx.x;
    const int qrow = n * WW + i;
    const float scale = 0.125f;

    float q[DHH];
    {
        const float* qp = qkl + ((size_t)(b * SS + qrow)) * TDD + h * DHH;
        #pragma unroll
        for (int d4 = 0; d4 < 16; d4++) {
            float4 tq = *(const float4*)(qp + d4 * 4);
            q[d4*4+0] = tq.x * scale; q[d4*4+1] = tq.y * scale;
            q[d4*4+2] = tq.z * scale; q[d4*4+3] = tq.w * scale;
        }
    }
    float o[DHH];
    #pragma unroll
    for (int d = 0; d < DHH; d++) o[d] = 0.f;
    float m = -1e30f, l = 0.f;

    const int ktStart = (n == 0) ? WW : 0;
    for (int kt = ktStart; kt < 2 * WW; kt += TKEY) {
        __syncthreads();
        #pragma unroll
        for (int r = 0; r < 4; r++) {
            int idx = threadIdx.x + r * 128;
            int krow = idx >> 4, f4 = idx & 15;
            int seqrow = n * WW - WW + kt + krow;
            const float* src = qkl + ((size_t)(b * SS + seqrow)) * TDD + DD + h * DHH + f4 * 4;
            *(float4*)&ks[krow][f4*4] = *(const float4*)src;
            *(float4*)&vs[krow][f4*4] = *(const float4*)(src + DD);
        }
        __syncthreads();

        for (int ch = 0; ch < TKEY; ch += 8) {
            float sreg[8];
            #pragma unroll
            for (int j = 0; j < 8; j++) {
                float accd = 0.f;
                #pragma unroll
                for (int d4 = 0; d4 < 16; d4++) {
                    float4 k4 = *(const float4*)&ks[ch + j][d4*4];
                    accd += q[d4*4+0]*k4.x + q[d4*4+1]*k4.y + q[d4*4+2]*k4.z + q[d4*4+3]*k4.w;
                }
                int jw = kt + ch + j;
                if (jw >= WW && (jw - WW) > i) accd = -1e30f;
                sreg[j] = accd;
            }
            float cmax = sreg[0];
            #pragma unroll
            for (int j = 1; j < 8; j++) cmax = fmaxf(cmax, sreg[j]);
            float mn = fmaxf(m, cmax);
            float corr = __expf(m - mn);
            l *= corr;
            #pragma unroll
            for (int d = 0; d < DHH; d++) o[d] *= corr;
            #pragma unroll
            for (int j = 0; j < 8; j++) {
                float p = __expf(sreg[j] - mn);
                l += p;
                #pragma unroll
                for (int d4 = 0; d4 < 16; d4++) {
                    float4 v4 = *(const float4*)&vs[ch + j][d4*4];
                    o[d4*4+0] += p * v4.x; o[d4*4+1] += p * v4.y;
                    o[d4*4+2] += p * v4.z; o[d4*4+3] += p * v4.w;
                }
            }
            m = mn;
        }
    }
    float invl = 1.f / l;
    __nv_bfloat16* oh = loH + ((size_t)(b * SS + qrow)) * DD + h * DHH;
    __nv_bfloat16* ol = loL + ((size_t)(b * SS + qrow)) * DD + h * DHH;
    #pragma unroll
    for (int d2 = 0; d2 < 32; d2++) {
        float a = o[2*d2] * invl, bb2 = o[2*d2+1] * invl;
        __nv_bfloat162 hp = __floats2bfloat162_rn(a, bb2);
        __nv_bfloat162 lp = __floats2bfloat162_rn(a - __low2float(hp), bb2 - __high2float(hp));
        *(__nv_bfloat162*)(oh + 2*d2) = hp;
        *(__nv_bfloat162*)(ol + 2*d2) = lp;
    }
}

// ---------------- launch ----------------
static void cvt_launch(const float* x, __nv_bfloat16* h, __nv_bfloat16* l, int n) {
    int n4 = n / 4;
    cvt_kernel<<<(n4 + 255) / 256, 256>>>(x, h, l, n4);
}

extern "C" void kernel_launch(void* const* d_in, const int* in_sizes, int n_in,
                              void* d_out, int out_size)
{
    (void)in_sizes; (void)n_in; (void)out_size;
    const float* src        = (const float*)d_in[0];
    const float* in_proj_b  = (const float*)d_in[2];
    const float* out_proj_b = (const float*)d_in[4];
    const float* ln_g       = (const float*)d_in[5];
    const float* ln_b       = (const float*)d_in[6];
    const float* gl_b       = (const float*)d_in[10];
    const float* norm1_g    = (const float*)d_in[11];
    const float* norm1_b    = (const float*)d_in[12];
    const float* lin1_b     = (const float*)d_in[14];
    const float* lin2_b     = (const float*)d_in[16];
    const float* norm2_g    = (const float*)d_in[17];
    const float* norm2_b    = (const float*)d_in[18];
    float* outp = (float*)d_out;

    cudaFuncSetAttribute(mm_tc, cudaFuncAttributeMaxDynamicSharedMemorySize, MM_SMEM);
    cudaFuncSetAttribute(gattn_tc, cudaFuncAttributeMaxDynamicSharedMemorySize, GA_SMEM);

    float *p_qkl, *p_x, *p_src2, *p_h1, *p_ff2;
    cudaGetSymbolAddress((void**)&p_qkl,  g_qkl);
    cudaGetSymbolAddress((void**)&p_x,    g_x);
    cudaGetSymbolAddress((void**)&p_src2, g_src2);
    cudaGetSymbolAddress((void**)&p_h1,   g_h1);
    cudaGetSymbolAddress((void**)&p_ff2,  g_ff2);

    __nv_bfloat16 *srcH,*srcL,*qkvH,*qkvL,*goH,*goL,*xH,*xL,*loH,*loL,*catH,*catL,*h1H,*h1L,*ff1H,*ff1L;
    __nv_bfloat16 *w1H,*w1L,*w2H,*w2L,*w3H,*w3L,*w4H,*w4L,*w5H,*w5L,*w6H,*w6L,*w7H,*w7L;
    cudaGetSymbolAddress((void**)&srcH, c_src_h); cudaGetSymbolAddress((void**)&srcL, c_src_l);
    cudaGetSymbolAddress((void**)&qkvH, c_qkv_h); cudaGetSymbolAddress((void**)&qkvL, c_qkv_l);
    cudaGetSymbolAddress((void**)&goH,  c_go_h);  cudaGetSymbolAddress((void**)&goL,  c_go_l);
    cudaGetSymbolAddress((void**)&xH,   c_x_h);   cudaGetSymbolAddress((void**)&xL,   c_x_l);
    cudaGetSymbolAddress((void**)&loH,  c_lo_h);  cudaGetSymbolAddress((void**)&loL,  c_lo_l);
    cudaGetSymbolAddress((void**)&catH, c_cat_h); cudaGetSymbolAddress((void**)&catL, c_cat_l);
    cudaGetSymbolAddress((void**)&h1H,  c_h1_h);  cudaGetSymbolAddress((void**)&h1L,  c_h1_l);
    cudaGetSymbolAddress((void**)&ff1H, c_ff1_h); cudaGetSymbolAddress((void**)&ff1L, c_ff1_l);
    cudaGetSymbolAddress((void**)&w1H, c_w1_h); cudaGetSymbolAddress((void**)&w1L, c_w1_l);
    cudaGetSymbolAddress((void**)&w2H, c_w2_h); cudaGetSymbolAddress((void**)&w2L, c_w2_l);
    cudaGetSymbolAddress((void**)&w3H, c_w3_h); cudaGetSymbolAddress((void**)&w3L, c_w3_l);
    cudaGetSymbolAddress((void**)&w4H, c_w4_h); cudaGetSymbolAddress((void**)&w4L, c_w4_l);
    cudaGetSymbolAddress((void**)&w5H, c_w5_h); cudaGetSymbolAddress((void**)&w5L, c_w5_l);
    cudaGetSymbolAddress((void**)&w6H, c_w6_h); cudaGetSymbolAddress((void**)&w6L, c_w6_l);
    cudaGetSymbolAddress((void**)&w7H, c_w7_h); cudaGetSymbolAddress((void**)&w7L, c_w7_l);

    // weight + src conversions
    cvt_launch((const float*)d_in[1],  w1H, w1L, TDD*DD);
    cvt_launch((const float*)d_in[3],  w2H, w2L, DD*DD);
    cvt_launch((const float*)d_in[7],  w3H, w3L, TDD*DD);
    cvt_launch((const float*)d_in[8],  w4H, w4L, DD*DD);
    cvt_launch((const float*)d_in[9],  w5H, w5L, DD*2*DD);
    cvt_launch((const float*)d_in[13], w6H, w6L, FFD*DD);
    cvt_launch((const float*)d_in[15], w7H, w7L, DD*FFD);
    cvt_launch(src, srcH, srcL, NROWS*DD);

    // 1. qkv = src @ in_proj_w^T + b  -> bf16 hi/lo only
    mm_tc<<<dim3(TDD/128, NROWS/128), 256, MM_SMEM>>>(srcH, srcL, w1H, w1L,
        nullptr, in_proj_b, DD, TDD, 0, 0, qkvH, qkvL);
    // 2. global attention (tensor cores) -> goH/goL
    gattn_tc<<<dim3(SS/64, HH, BB), 128, GA_SMEM>>>(qkvH, qkvL, goH, goL);
    // 3. go2 = go @ out_proj_w^T + b -> catH/L[:, 0:512]
    mm_tc<<<dim3(DD/128, NROWS/128), 256, MM_SMEM>>>(goH, goL, w2H, w2L,
        nullptr, out_proj_b, DD, 2*DD, 0, 0, catH, catL);
    // 4. x = LN(src) -> fp32 + hi/lo
    ln_kernel<<<NROWS, 128>>>(src, nullptr, ln_g, ln_b, p_x, xH, xL);
    // 5. qkl = x @ qkv_w^T -> fp32 (for rope + SIMT local attn)
    mm_tc<<<dim3(TDD/128, NROWS/128), 256, MM_SMEM>>>(xH, xL, w3H, w3L,
        p_qkl, nullptr, DD, TDD, 0, 0, nullptr, nullptr);
    // 6. rope
    rope_kernel<<<NROWS, 256>>>(p_qkl);
    // 7. local attention -> loH/loL
    lattn_kernel<<<dim3(NWIN, HH, BB), 128>>>(p_qkl, loH, loL);
    // 8. lo2 = lo @ to_out_w^T -> catH/L[:, 512:1024]
    mm_tc<<<dim3(DD/128, NROWS/128), 256, MM_SMEM>>>(loH, loL, w4H, w4L,
        nullptr, nullptr, DD, 2*DD, DD, 0, catH, catL);
    // 9. src2 = cat @ gl_w^T + gl_b -> fp32
    mm_tc<<<dim3(DD/128, NROWS/128), 256, MM_SMEM>>>(catH, catL, w5H, w5L,
        p_src2, gl_b, 2*DD, DD, 0, 0, nullptr, nullptr);
    // 10. h1 = LN(src + src2) -> fp32 + hi/lo
    ln_kernel<<<NROWS, 128>>>(p_src2, src, norm1_g, norm1_b, p_h1, h1H, h1L);
    // 11. ff1 = relu(h1 @ lin1_w^T + b) -> hi/lo only
    mm_tc<<<dim3(FFD/128, NROWS/128), 256, MM_SMEM>>>(h1H, h1L, w6H, w6L,
        nullptr, lin1_b, DD, FFD, 0, 1, ff1H, ff1L);
    // 12. ff2 = ff1 @ lin2_w^T + b -> fp32
    mm_tc<<<dim3(DD/128, NROWS/128), 256, MM_SMEM>>>(ff1H, ff1L, w7H, w7L,
        p_ff2, lin2_b, FFD, DD, 0, 0, nullptr, nullptr);
    // 13. out = LN(h1 + ff2)
    ln_kernel<<<NROWS, 128>>>(p_ff2, p_h1, norm2_g, norm2_b, outp, nullptr, nullptr);
}

// round 13
// speedup vs baseline: 4.5047x; 1.6304x over previous
#include <cuda_runtime.h>
#include <cuda_fp16.h>
#include <cstdint>

// ---------------- constants ----------------
#define BB 4
#define SS 2048
#define DD 512
#define HH 8
#define DHH 64
#define WW 128
#define NWIN 16
#define FFD 2048
#define TDD 1536   // 3*D
#define NROWS (BB*SS)   // 8192

// ---------------- fp32 scratch ----------------
__device__ float g_qkl [NROWS * TDD];
__device__ float g_src2[NROWS * DD];
__device__ float g_h1  [NROWS * DD];
__device__ float g_ff2 [NROWS * DD];

// ---------------- fp16 hi/lo split buffers (activations) ----------------
__device__ __half c_src_h[NROWS*DD],   c_src_l[NROWS*DD];
__device__ __half c_qkv_h[NROWS*TDD],  c_qkv_l[NROWS*TDD];
__device__ __half c_qkl_h[NROWS*TDD],  c_qkl_l[NROWS*TDD];
__device__ __half c_go_h [NROWS*DD],   c_go_l [NROWS*DD];
__device__ __half c_x_h  [NROWS*DD],   c_x_l  [NROWS*DD];
__device__ __half c_lo_h [NROWS*DD],   c_lo_l [NROWS*DD];
__device__ __half c_cat_h[NROWS*2*DD], c_cat_l[NROWS*2*DD];
__device__ __half c_h1_h [NROWS*DD],   c_h1_l [NROWS*DD];
__device__ __half c_ff1_h[NROWS*FFD],  c_ff1_l[NROWS*FFD];
// weights: hi only
__device__ __half c_w1_h[TDD*DD];
__device__ __half c_w2_h[DD*DD];
__device__ __half c_w3_h[TDD*DD];
__device__ __half c_w4_h[DD*DD];
__device__ __half c_w5_h[DD*2*DD];
__device__ __half c_w6_h[FFD*DD];
__device__ __half c_w7_h[DD*FFD];

// ---------------- helpers ----------------
__device__ __forceinline__ uint32_t smem_u32(const void* p) {
    uint32_t a;
    asm("{ .reg .u64 t; cvta.to.shared.u64 t, %1; cvt.u32.u64 %0, t; }" : "=r"(a) : "l"(p));
    return a;
}

__device__ __forceinline__ void ldsm4(uint32_t* r, uint32_t a) {
    asm volatile("ldmatrix.sync.aligned.m8n8.x4.shared.b16 {%0,%1,%2,%3}, [%4];"
                 : "=r"(r[0]), "=r"(r[1]), "=r"(r[2]), "=r"(r[3]) : "r"(a));
}

__device__ __forceinline__ void ldsm4t(uint32_t* r, uint32_t a) {
    asm volatile("ldmatrix.sync.aligned.m8n8.x4.trans.shared.b16 {%0,%1,%2,%3}, [%4];"
                 : "=r"(r[0]), "=r"(r[1]), "=r"(r[2]), "=r"(r[3]) : "r"(a));
}

__device__ __forceinline__ void mma16816(float* d, const uint32_t* a, const uint32_t* b) {
    asm volatile(
        "mma.sync.aligned.m16n8k16.row.col.f32.f16.f16.f32 "
        "{%0,%1,%2,%3}, {%4,%5,%6,%7}, {%8,%9}, {%0,%1,%2,%3};"
        : "+f"(d[0]), "+f"(d[1]), "+f"(d[2]), "+f"(d[3])
        : "r"(a[0]), "r"(a[1]), "r"(a[2]), "r"(a[3]), "r"(b[0]), "r"(b[1]));
}

__device__ __forceinline__ uint32_t packh2(float a, float b) {
    __half2 t = __floats2half2_rn(a, b);
    return *(uint32_t*)&t;
}

__device__ __forceinline__ void split_store(__half* H, __half* L, size_t off, float a, float b) {
    __half2 h = __floats2half2_rn(a, b);
    __half2 l = __floats2half2_rn(a - __low2float(h), b - __high2float(h));
    *(__half2*)(H + off) = h;
    *(__half2*)(L + off) = l;
}

// ---------------- conversions ----------------
__global__ __launch_bounds__(256) void cvt_hilo(
    const float* __restrict__ X, __half* __restrict__ hi,
    __half* __restrict__ lo, int n4)
{
    int i = blockIdx.x * 256 + threadIdx.x;
    if (i >= n4) return;
    float4 v = ((const float4*)X)[i];
    split_store(hi, lo, (size_t)i * 4,     v.x, v.y);
    split_store(hi, lo, (size_t)i * 4 + 2, v.z, v.w);
}

struct W7 {
    const float* s[7];
    __half* d[7];
    int cum[8];   // cumulative sizes in float4 units
};

__global__ __launch_bounds__(256) void cvt_w7(W7 jobs)
{
    int i = blockIdx.x * 256 + threadIdx.x;
    if (i >= jobs.cum[7]) return;
    int j = 0;
    #pragma unroll
    for (int t = 1; t < 7; t++) if (i >= jobs.cum[t]) j = t;
    int li = i - jobs.cum[j];
    float4 v = ((const float4*)jobs.s[j])[li];
    __half2 h01 = __floats2half2_rn(v.x, v.y);
    __half2 h23 = __floats2half2_rn(v.z, v.w);
    ((__half2*)jobs.d[j])[2*li]   = h01;
    ((__half2*)jobs.d[j])[2*li+1] = h23;
}

// ---------------- mma.sync GEMM: C = A(MxK) * B(NxK)^T  (fp16 A-split 2-pass) ----------------
#define KC 32
#define ROWB 80
#define TILEB (128*ROWB)
#define STG (3*TILEB)
#define MM_SMEM (2*STG)

__device__ __forceinline__ void mm_load_chunk(
    const __half* __restrict__ Ah, const __half* __restrict__ Al,
    const __half* __restrict__ Bh,
    int K, int rowBase, int colBase, int tid, int c, uint32_t stageBase)
{
    const __half* mats[3] = {Ah, Al, Bh};
    #pragma unroll
    for (int it = 0; it < 6; it++) {
        int t = it >> 1;
        int v = tid + (it & 1) * 256;
        int r = v >> 2;
        int ch = v & 3;
        int rb = (t < 2) ? rowBase : colBase;
        const void* g = mats[t] + (size_t)(rb + r) * K + c * KC + ch * 8;
        uint32_t d = stageBase + t * TILEB + r * ROWB + ch * 16;
        asm volatile("cp.async.cg.shared.global [%0], [%1], 16;" :: "r"(d), "l"(g));
    }
    asm volatile("cp.async.commit_group;" ::: "memory");
}

__global__ __launch_bounds__(256, 2) void mm_tc(
    const __half* __restrict__ Ah, const __half* __restrict__ Al,
    const __half* __restrict__ Bh,
    float* __restrict__ C, const float* __restrict__ bias,
    int K, int ldc, int colOff, int relu,
    __half* __restrict__ Ch, __half* __restrict__ Cl)
{
    extern __shared__ char mm_smem[];
    const int tid = threadIdx.x;
    const int wid = tid >> 5, lane = tid & 31;
    const int wm = wid >> 1, wn = wid & 1;
    const int rowBase = blockIdx.y * 128;
    const int colBase = blockIdx.x * 128;
    const uint32_t sb = smem_u32(mm_smem);

    const int lrA = (lane & 15);
    const int lcA = (lane >> 4) * 16;
    const int lrB = (lane & 7) + (lane >> 4) * 8;
    const int lcB = ((lane >> 3) & 1) * 16;

    float acc[2][8][4];
    #pragma unroll
    for (int i = 0; i < 2; i++)
        #pragma unroll
        for (int j = 0; j < 8; j++)
            #pragma unroll
            for (int e = 0; e < 4; e++) acc[i][j][e] = 0.f;

    const int CC = K / KC;
    mm_load_chunk(Ah, Al, Bh, K, rowBase, colBase, tid, 0, sb);

    for (int c = 0; c < CC; c++) {
        int s = c & 1;
        if (c + 1 < CC) {
            mm_load_chunk(Ah, Al, Bh, K, rowBase, colBase, tid, c + 1, sb + (s ^ 1) * STG);
            asm volatile("cp.async.wait_group 1;" ::: "memory");
        } else {
            asm volatile("cp.async.wait_group 0;" ::: "memory");
        }
        __syncthreads();

        uint32_t base = sb + s * STG;
        #pragma unroll
        for (int ks = 0; ks < 2; ks++) {
            uint32_t bf[8][2];
            #pragma unroll
            for (int j2 = 0; j2 < 4; j2++) {
                uint32_t r4[4];
                ldsm4(r4, base + 2 * TILEB + (uint32_t)(wn * 64 + j2 * 16 + lrB) * ROWB + ks * 32 + lcB);
                bf[2*j2][0]   = r4[0]; bf[2*j2][1]   = r4[1];
                bf[2*j2+1][0] = r4[2]; bf[2*j2+1][1] = r4[3];
            }
            uint32_t afh[2][4], afl[2][4];
            #pragma unroll
            for (int i = 0; i < 2; i++) {
                uint32_t ab = base + (uint32_t)(wm * 32 + i * 16 + lrA) * ROWB + ks * 32 + lcA;
                ldsm4(afh[i], ab);
                ldsm4(afl[i], ab + TILEB);
            }
            #pragma unroll
            for (int i = 0; i < 2; i++)
                #pragma unroll
                for (int j = 0; j < 8; j++) {
                    mma16816(acc[i][j], afh[i], bf[j]);
                    mma16816(acc[i][j], afl[i], bf[j]);
                }
        }
        __syncthreads();
    }

    // epilogue
    #pragma unroll
    for (int i = 0; i < 2; i++) {
        int row0 = rowBase + wm * 32 + i * 16 + (lane >> 2);
        #pragma unroll
        for (int j = 0; j < 8; j++) {
            int col = colBase + wn * 64 + j * 8 + (lane & 3) * 2;
            float b0 = 0.f, b1 = 0.f;
            if (bias) { b0 = bias[col]; b1 = bias[col + 1]; }
            float2 v0 = make_float2(acc[i][j][0] + b0, acc[i][j][1] + b1);
            float2 v1 = make_float2(acc[i][j][2] + b0, acc[i][j][3] + b1);
            if (relu) {
                v0.x = fmaxf(v0.x, 0.f); v0.y = fmaxf(v0.y, 0.f);
                v1.x = fmaxf(v1.x, 0.f); v1.y = fmaxf(v1.y, 0.f);
            }
            size_t o0 = (size_t)row0 * ldc + colOff + col;
            size_t o1 = (size_t)(row0 + 8) * ldc + colOff + col;
            if (C) {
                *(float2*)(C + o0) = v0;
                *(float2*)(C + o1) = v1;
            }
            if (Ch) {
                split_store(Ch, Cl, o0, v0.x, v0.y);
                split_store(Ch, Cl, o1, v1.x, v1.y);
            }
        }
    }
}

// ---------------- tensor-core flash attention (global + local windowed) ----------------
// CTA: 4 warps; Q tile 64 rows, K tiles of 64, DH=64. fp16 2-pass QK, 1-pass PV.
// smem: Qh, Ql tiles + 2 stages of {Kh, Vh}. Tile = 64 rows x 128B data, stride 144B.
#define AROW 144
#define GA_TILE 9216
#define GA_STG (2*GA_TILE)
#define GA_SMEM (2*GA_TILE + 2*GA_STG)

__device__ __forceinline__ void at_load_kv(
    const __half* __restrict__ qH, int b, int h, int kt, int tid, uint32_t stBase)
{
    #pragma unroll
    for (int m = 0; m < 2; m++) {
        int col = ((m == 0) ? DD : 2 * DD) + h * DHH;
        #pragma unroll
        for (int i = 0; i < 4; i++) {
            int idx = tid + i * 128;           // 0..511 = 64 rows x 8 chunks
            int r = idx >> 3, ch = idx & 7;
            const void* g = qH + (size_t)(b * SS + kt * 64 + r) * TDD + col + ch * 8;
            uint32_t d = stBase + m * GA_TILE + r * AROW + ch * 16;
            asm volatile("cp.async.cg.shared.global [%0], [%1], 16;" :: "r"(d), "l"(g));
        }
    }
    asm volatile("cp.async.commit_group;" ::: "memory");
}

__global__ __launch_bounds__(128) void attn_tc(
    const __half* __restrict__ qH, const __half* __restrict__ qL,
    __half* __restrict__ oH, __half* __restrict__ oL, int local)
{
    extern __shared__ char ga_smem[];
    const int tid = threadIdx.x, wid = tid >> 5, lane = tid & 31;
    const int qt = blockIdx.x, h = blockIdx.y, b = blockIdx.z;
    const uint32_t sb = smem_u32(ga_smem);

    int ktLo = 0, ktHi = SS / 64 - 1;
    if (local) {
        ktLo = qt - 2 - (qt & 1);
        if (ktLo < 0) ktLo = 0;
        ktHi = qt;
    }

    // Q hi/lo load (group 0)
    #pragma unroll
    for (int m = 0; m < 2; m++) {
        const __half* srcb = m ? qL : qH;
        #pragma unroll
        for (int i = 0; i < 4; i++) {
            int idx = tid + i * 128;
            int r = idx >> 3, ch = idx & 7;
            const void* g = srcb + (size_t)(b * SS + qt * 64 + r) * TDD + h * DHH + ch * 8;
            uint32_t d = sb + m * GA_TILE + r * AROW + ch * 16;
            asm volatile("cp.async.cg.shared.global [%0], [%1], 16;" :: "r"(d), "l"(g));
        }
    }
    asm volatile("cp.async.commit_group;" ::: "memory");
    at_load_kv(qH, b, h, ktLo, tid, sb + 2 * GA_TILE);

    asm volatile("cp.async.wait_group 1;" ::: "memory");   // Q done
    __syncthreads();

    const int lr16 = lane & 15;
    const int hi16 = lane >> 4;
    uint32_t qfh[4][4], qfl[4][4];
    #pragma unroll
    for (int ks = 0; ks < 4; ks++) {
        uint32_t ab = sb + (uint32_t)(wid * 16 + lr16) * AROW + ks * 32 + hi16 * 16;
        ldsm4(qfh[ks], ab);
        ldsm4(qfl[ks], ab + GA_TILE);
    }

    float oacc[8][4];
    #pragma unroll
    for (int j = 0; j < 8; j++)
        #pragma unroll
        for (int e = 0; e < 4; e++) oacc[j][e] = 0.f;
    float m0 = -1e30f, m1 = -1e30f, l0 = 0.f, l1 = 0.f;
    const int lrB = (lane & 7) + (lane >> 4) * 8;
    const int lcB = ((lane >> 3) & 1) * 16;

    for (int kt = ktLo; kt <= ktHi; kt++) {
        int s = (kt - ktLo) & 1;
        uint32_t st = sb + 2 * GA_TILE + s * GA_STG;
        if (kt < ktHi) {
            at_load_kv(qH, b, h, kt + 1, tid, sb + 2 * GA_TILE + (s ^ 1) * GA_STG);
            asm volatile("cp.async.wait_group 1;" ::: "memory");
        } else {
            asm volatile("cp.async.wait_group 0;" ::: "memory");
        }
        __syncthreads();

        // S = Q K^T  (2-pass fp16 hi/lo on Q)
        float sacc[8][4];
        #pragma unroll
        for (int j = 0; j < 8; j++)
            #pragma unroll
            for (int e = 0; e < 4; e++) sacc[j][e] = 0.f;

        #pragma unroll
        for (int ks = 0; ks < 4; ks++) {
            uint32_t kf[4][4];
            #pragma unroll
            for (int n2 = 0; n2 < 4; n2++)
                ldsm4(kf[n2], st + (uint32_t)(n2 * 16 + lrB) * AROW + ks * 32 + lcB);
            #pragma unroll
            for (int j = 0; j < 8; j++) {
                mma16816(sacc[j], qfh[ks], &kf[j >> 1][(j & 1) * 2]);
                mma16816(sacc[j], qfl[ks], &kf[j >> 1][(j & 1) * 2]);
            }
        }

        // scale
        #pragma unroll
        for (int j = 0; j < 8; j++) {
            sacc[j][0] *= 0.125f; sacc[j][1] *= 0.125f;
            sacc[j][2] *= 0.125f; sacc[j][3] *= 0.125f;
        }
        // causal mask on diagonal tile (local attention)
        if (local && kt == ktHi) {
            int r0 = wid * 16 + (lane >> 2);
            #pragma unroll
            for (int j = 0; j < 8; j++) {
                int c = j * 8 + (lane & 3) * 2;
                if (c     > r0)     sacc[j][0] = -1e30f;
                if (c + 1 > r0)     sacc[j][1] = -1e30f;
                if (c     > r0 + 8) sacc[j][2] = -1e30f;
                if (c + 1 > r0 + 8) sacc[j][3] = -1e30f;
            }
        }

        // online softmax (rows r0 and r0+8)
        float t0 = -1e30f, t1 = -1e30f;
        #pragma unroll
        for (int j = 0; j < 8; j++) {
            t0 = fmaxf(t0, fmaxf(sacc[j][0], sacc[j][1]));
            t1 = fmaxf(t1, fmaxf(sacc[j][2], sacc[j][3]));
        }
        t0 = fmaxf(t0, __shfl_xor_sync(0xffffffffu, t0, 1));
        t0 = fmaxf(t0, __shfl_xor_sync(0xffffffffu, t0, 2));
        t1 = fmaxf(t1, __shfl_xor_sync(0xffffffffu, t1, 1));
        t1 = fmaxf(t1, __shfl_xor_sync(0xffffffffu, t1, 2));
        float mn0 = fmaxf(m0, t0), mn1 = fmaxf(m1, t1);
        float c0 = __expf(m0 - mn0), c1 = __expf(m1 - mn1);
        float s0 = 0.f, s1 = 0.f;
        #pragma unroll
        for (int j = 0; j < 8; j++) {
            sacc[j][0] = __expf(sacc[j][0] - mn0);
            sacc[j][1] = __expf(sacc[j][1] - mn0);
            sacc[j][2] = __expf(sacc[j][2] - mn1);
            sacc[j][3] = __expf(sacc[j][3] - mn1);
            s0 += sacc[j][0] + sacc[j][1];
            s1 += sacc[j][2] + sacc[j][3];
        }
        s0 += __shfl_xor_sync(0xffffffffu, s0, 1);
        s0 += __shfl_xor_sync(0xffffffffu, s0, 2);
        s1 += __shfl_xor_sync(0xffffffffu, s1, 1);
        s1 += __shfl_xor_sync(0xffffffffu, s1, 2);
        l0 = l0 * c0 + s0;
        l1 = l1 * c1 + s1;
        m0 = mn0; m1 = mn1;
        #pragma unroll
        for (int j = 0; j < 8; j++) {
            oacc[j][0] *= c0; oacc[j][1] *= c0;
            oacc[j][2] *= c1; oacc[j][3] *= c1;
        }

        // O += P V
        #pragma unroll
        for (int kp = 0; kp < 4; kp++) {
            uint32_t pf[4];
            pf[0] = packh2(sacc[2*kp][0],   sacc[2*kp][1]);
            pf[1] = packh2(sacc[2*kp][2],   sacc[2*kp][3]);
            pf[2] = packh2(sacc[2*kp+1][0], sacc[2*kp+1][1]);
            pf[3] = packh2(sacc[2*kp+1][2], sacc[2*kp+1][3]);
            uint32_t vf[4][4];
            #pragma unroll
            for (int n2 = 0; n2 < 4; n2++)
                ldsm4t(vf[n2], st + GA_TILE + (uint32_t)(kp * 16 + lr16) * AROW + n2 * 32 + hi16 * 16);
            #pragma unroll
            for (int j = 0; j < 8; j++)
                mma16816(oacc[j], pf, &vf[j >> 1][(j & 1) * 2]);
        }
        __syncthreads();
    }

    // epilogue: normalize, write hi/lo fp16
    float il0 = 1.f / l0, il1 = 1.f / l1;
    int r0g = b * SS + qt * 64 + wid * 16 + (lane >> 2);
    size_t o0 = (size_t)r0g * DD + h * DHH;
    size_t o1 = o0 + (size_t)8 * DD;
    #pragma unroll
    for (int j = 0; j < 8; j++) {
        int col = j * 8 + (lane & 3) * 2;
        split_store(oH, oL, o0 + col, oacc[j][0] * il0, oacc[j][1] * il0);
        split_store(oH, oL, o1 + col, oacc[j][2] * il1, oacc[j][3] * il1);
    }
}

// ---------------- LayerNorm (fp32 out optional, fp16 hi/lo out optional) ----------------
__global__ __launch_bounds__(128) void ln_kernel(
    const float* __restrict__ X, const float* __restrict__ R,
    const float* __restrict__ gam, const float* __restrict__ bet,
    float* __restrict__ out,
    __half* __restrict__ outH, __half* __restrict__ outL)
{
    __shared__ float red[8];
    const int row = blockIdx.x;
    const int tid = threadIdx.x;
    float4 v = ((const float4*)(X + (size_t)row * DD))[tid];
    if (R) {
        float4 r = ((const float4*)(R + (size_t)row * DD))[tid];
        v.x += r.x; v.y += r.y; v.z += r.z; v.w += r.w;
    }
    float s  = v.x + v.y + v.z + v.w;
    float sq = v.x*v.x + v.y*v.y + v.z*v.z + v.w*v.w;
    #pragma unroll
    for (int o = 16; o; o >>= 1) {
        s  += __shfl_xor_sync(0xffffffffu, s,  o);
        sq += __shfl_xor_sync(0xffffffffu, sq, o);
    }
    int w = tid >> 5;
    if ((tid & 31) == 0) { red[w*2] = s; red[w*2+1] = sq; }
    __syncthreads();
    s  = red[0] + red[2] + red[4] + red[6];
    sq = red[1] + red[3] + red[5] + red[7];
    float mean = s * (1.f / DD);
    float var  = sq * (1.f / DD) - mean * mean;
    float inv  = rsqrtf(var + 1e-5f);
    float4 gg = ((const float4*)gam)[tid];
    float4 bb = ((const float4*)bet)[tid];
    float4 r;
    r.x = (v.x - mean) * inv * gg.x + bb.x;
    r.y = (v.y - mean) * inv * gg.y + bb.y;
    r.z = (v.z - mean) * inv * gg.z + bb.z;
    r.w = (v.w - mean) * inv * gg.w + bb.w;
    if (out) ((float4*)(out + (size_t)row * DD))[tid] = r;
    if (outH) {
        size_t o = (size_t)row * DD + tid * 4;
        split_store(outH, outL, o,     r.x, r.y);
        split_store(outH, outL, o + 2, r.z, r.w);
    }
}

// ---------------- RoPE: fp32 qkl -> roped q,k + v, fp16 hi/lo ----------------
__global__ __launch_bounds__(256) void rope_hl(
    const float* __restrict__ qkl,
    __half* __restrict__ H, __half* __restrict__ L)
{
    const int row = blockIdx.x;
    const int pos = row & (SS - 1);
    const int t = threadIdx.x;
    const int h = t >> 5;
    const int f = t & 31;
    float inv_freq = powf(10000.f, -(float)f * (1.f / 32.f));
    float fr = (float)pos * inv_freq;
    float c, sn;
    sincosf(fr, &sn, &c);
    size_t base = (size_t)row * TDD + h * DHH + f;

    // q
    float x1 = qkl[base], x2 = qkl[base + 32];
    float r1 = x1 * c - x2 * sn;
    float r2 = x2 * c + x1 * sn;
    __half h1 = __float2half_rn(r1);
    __half h2 = __float2half_rn(r2);
    H[base] = h1;      L[base]      = __float2half_rn(r1 - __half2float(h1));
    H[base + 32] = h2; L[base + 32] = __float2half_rn(r2 - __half2float(h2));
    // k
    x1 = qkl[base + DD]; x2 = qkl[base + DD + 32];
    r1 = x1 * c - x2 * sn;
    r2 = x2 * c + x1 * sn;
    h1 = __float2half_rn(r1);
    h2 = __float2half_rn(r2);
    H[base + DD] = h1;      L[base + DD]      = __float2half_rn(r1 - __half2float(h1));
    H[base + DD + 32] = h2; L[base + DD + 32] = __float2half_rn(r2 - __half2float(h2));
    // v (no rotation)
    r1 = qkl[base + 2 * DD];
    r2 = qkl[base + 2 * DD + 32];
    h1 = __float2half_rn(r1);
    h2 = __float2half_rn(r2);
    H[base + 2 * DD] = h1;      L[base + 2 * DD]      = __float2half_rn(r1 - __half2float(h1));
    H[base + 2 * DD + 32] = h2; L[base + 2 * DD + 32] = __float2half_rn(r2 - __half2float(h2));
}

// ---------------- launch ----------------
extern "C" void kernel_launch(void* const* d_in, const int* in_sizes, int n_in,
                              void* d_out, int out_size)
{
    (void)in_sizes; (void)n_in; (void)out_size;
    const float* src        = (const float*)d_in[0];
    const float* in_proj_b  = (const float*)d_in[2];
    const float* out_proj_b = (const float*)d_in[4];
    const float* ln_g       = (const float*)d_in[5];
    const float* ln_b       = (const float*)d_in[6];
    const float* gl_b       = (const float*)d_in[10];
    const float* norm1_g    = (const float*)d_in[11];
    const float* norm1_b    = (const float*)d_in[12];
    const float* lin1_b     = (const float*)d_in[14];
    const float* lin2_b     = (const float*)d_in[16];
    const float* norm2_g    = (const float*)d_in[17];
    const float* norm2_b    = (const float*)d_in[18];
    float* outp = (float*)d_out;

    cudaFuncSetAttribute(mm_tc, cudaFuncAttributeMaxDynamicSharedMemorySize, MM_SMEM);
    cudaFuncSetAttribute(attn_tc, cudaFuncAttributeMaxDynamicSharedMemorySize, GA_SMEM);

    float *p_qkl, *p_src2, *p_h1, *p_ff2;
    cudaGetSymbolAddress((void**)&p_qkl,  g_qkl);
    cudaGetSymbolAddress((void**)&p_src2, g_src2);
    cudaGetSymbolAddress((void**)&p_h1,   g_h1);
    cudaGetSymbolAddress((void**)&p_ff2,  g_ff2);

    __half *srcH,*srcL,*qkvH,*qkvL,*qklH,*qklL,*goH,*goL,*xH,*xL,*loH,*loL,*catH,*catL,*h1H,*h1L,*ff1H,*ff1L;
    __half *w1H,*w2H,*w3H,*w4H,*w5H,*w6H,*w7H;
    cudaGetSymbolAddress((void**)&srcH, c_src_h); cudaGetSymbolAddress((void**)&srcL, c_src_l);
    cudaGetSymbolAddress((void**)&qkvH, c_qkv_h); cudaGetSymbolAddress((void**)&qkvL, c_qkv_l);
    cudaGetSymbolAddress((void**)&qklH, c_qkl_h); cudaGetSymbolAddress((void**)&qklL, c_qkl_l);
    cudaGetSymbolAddress((void**)&goH,  c_go_h);  cudaGetSymbolAddress((void**)&goL,  c_go_l);
    cudaGetSymbolAddress((void**)&xH,   c_x_h);   cudaGetSymbolAddress((void**)&xL,   c_x_l);
    cudaGetSymbolAddress((void**)&loH,  c_lo_h);  cudaGetSymbolAddress((void**)&loL,  c_lo_l);
    cudaGetSymbolAddress((void**)&catH, c_cat_h); cudaGetSymbolAddress((void**)&catL, c_cat_l);
    cudaGetSymbolAddress((void**)&h1H,  c_h1_h);  cudaGetSymbolAddress((void**)&h1L,  c_h1_l);
    cudaGetSymbolAddress((void**)&ff1H, c_ff1_h); cudaGetSymbolAddress((void**)&ff1L, c_ff1_l);
    cudaGetSymbolAddress((void**)&w1H, c_w1_h);
    cudaGetSymbolAddress((void**)&w2H, c_w2_h);
    cudaGetSymbolAddress((void**)&w3H, c_w3_h);
    cudaGetSymbolAddress((void**)&w4H, c_w4_h);
    cudaGetSymbolAddress((void**)&w5H, c_w5_h);
    cudaGetSymbolAddress((void**)&w6H, c_w6_h);
    cudaGetSymbolAddress((void**)&w7H, c_w7_h);

    // weight conversions (hi only), one launch
    {
        W7 jobs;
        const float* ws[7] = {(const float*)d_in[1], (const float*)d_in[3],
                              (const float*)d_in[7], (const float*)d_in[8],
                              (const float*)d_in[9], (const float*)d_in[13],
                              (const float*)d_in[15]};
        __half* wd[7] = {w1H, w2H, w3H, w4H, w5H, w6H, w7H};
        int sz[7] = {TDD*DD, DD*DD, TDD*DD, DD*DD, DD*2*DD, FFD*DD, DD*FFD};
        int cum = 0;
        for (int j = 0; j < 7; j++) {
            jobs.s[j] = ws[j]; jobs.d[j] = wd[j];
            jobs.cum[j] = cum; cum += sz[j] / 4;
        }
        jobs.cum[7] = cum;
        cvt_w7<<<(cum + 255) / 256, 256>>>(jobs);
    }
    cvt_hilo<<<(NROWS*DD/4 + 255) / 256, 256>>>(src, srcH, srcL, NROWS*DD/4);

    // 1. qkv = src @ in_proj_w^T + b  -> fp16 hi/lo
    mm_tc<<<dim3(TDD/128, NROWS/128), 256, MM_SMEM>>>(srcH, srcL, w1H,
        nullptr, in_proj_b, DD, TDD, 0, 0, qkvH, qkvL);
    // 2. global attention -> goH/goL
    attn_tc<<<dim3(SS/64, HH, BB), 128, GA_SMEM>>>(qkvH, qkvL, goH, goL, 0);
    // 3. go2 = go @ out_proj_w^T + b -> cat[:, 0:512]
    mm_tc<<<dim3(DD/128, NROWS/128), 256, MM_SMEM>>>(goH, goL, w2H,
        nullptr, out_proj_b, DD, 2*DD, 0, 0, catH, catL);
    // 4. x = LN(src) -> hi/lo only
    ln_kernel<<<NROWS, 128>>>(src, nullptr, ln_g, ln_b, nullptr, xH, xL);
    // 5. qkl = x @ qkv_w^T -> fp32 (for rope)
    mm_tc<<<dim3(TDD/128, NROWS/128), 256, MM_SMEM>>>(xH, xL, w3H,
        p_qkl, nullptr, DD, TDD, 0, 0, nullptr, nullptr);
    // 6. rope -> qklH/qklL (roped q,k + v)
    rope_hl<<<NROWS, 256>>>(p_qkl, qklH, qklL);
    // 7. local windowed attention -> loH/loL
    attn_tc<<<dim3(SS/64, HH, BB), 128, GA_SMEM>>>(qklH, qklL, loH, loL, 1);
    // 8. lo2 = lo @ to_out_w^T -> cat[:, 512:1024]
    mm_tc<<<dim3(DD/128, NROWS/128), 256, MM_SMEM>>>(loH, loL, w4H,
        nullptr, nullptr, DD, 2*DD, DD, 0, catH, catL);
    // 9. src2 = cat @ gl_w^T + gl_b -> fp32
    mm_tc<<<dim3(DD/128, NROWS/128), 256, MM_SMEM>>>(catH, catL, w5H,
        p_src2, gl_b, 2*DD, DD, 0, 0, nullptr, nullptr);
    // 10. h1 = LN(src + src2) -> fp32 + hi/lo
    ln_kernel<<<NROWS, 128>>>(p_src2, src, norm1_g, norm1_b, p_h1, h1H, h1L);
    // 11. ff1 = relu(h1 @ lin1_w^T + b) -> hi/lo only
    mm_tc<<<dim3(FFD/128, NROWS/128), 256, MM_SMEM>>>(h1H, h1L, w6H,
        nullptr, lin1_b, DD, FFD, 0, 1, ff1H, ff1L);
    // 12. ff2 = ff1 @ lin2_w^T + b -> fp32
    mm_tc<<<dim3(DD/128, NROWS/128), 256, MM_SMEM>>>(ff1H, ff1L, w7H,
        p_ff2, lin2_b, FFD, DD, 0, 0, nullptr, nullptr);
    // 13. out = LN(h1 + ff2)
    ln_kernel<<<NROWS, 128>>>(p_ff2, p_h1, norm2_g, norm2_b, outp, nullptr, nullptr);
}

// round 14
// speedup vs baseline: 6.7757x; 1.5041x over previous
#include <cuda_runtime.h>
#include <cuda_fp16.h>
#include <cstdint>

// ---------------- constants ----------------
#define BB 4
#define SS 2048
#define DD 512
#define HH 8
#define DHH 64
#define WW 128
#define NWIN 16
#define FFD 2048
#define TDD 1536   // 3*D
#define NROWS (BB*SS)   // 8192

// ---------------- fp32 scratch ----------------
__device__ float g_qkl [NROWS * TDD];
__device__ float g_src2[NROWS * DD];
__device__ float g_h1  [NROWS * DD];
__device__ float g_ff2 [NROWS * DD];

// ---------------- fp16 buffers ----------------
__device__ __half c_src_h[NROWS*DD];
__device__ __half c_qkv_h[NROWS*TDD];
__device__ __half c_qkl_h[NROWS*TDD];
__device__ __half c_go_h [NROWS*DD];
__device__ __half c_x_h  [NROWS*DD];
__device__ __half c_lo_h [NROWS*DD];
__device__ __half c_cat_h[NROWS*2*DD];
__device__ __half c_h1_h [NROWS*DD];
__device__ __half c_ff1_h[NROWS*FFD];
__device__ __half c_w1_h[TDD*DD];
__device__ __half c_w2_h[DD*DD];
__device__ __half c_w3_h[TDD*DD];
__device__ __half c_w4_h[DD*DD];
__device__ __half c_w5_h[DD*2*DD];
__device__ __half c_w6_h[FFD*DD];
__device__ __half c_w7_h[DD*FFD];

// ---------------- helpers ----------------
__device__ __forceinline__ uint32_t smem_u32(const void* p) {
    uint32_t a;
    asm("{ .reg .u64 t; cvta.to.shared.u64 t, %1; cvt.u32.u64 %0, t; }" : "=r"(a) : "l"(p));
    return a;
}

__device__ __forceinline__ void ldsm4(uint32_t* r, uint32_t a) {
    asm volatile("ldmatrix.sync.aligned.m8n8.x4.shared.b16 {%0,%1,%2,%3}, [%4];"
                 : "=r"(r[0]), "=r"(r[1]), "=r"(r[2]), "=r"(r[3]) : "r"(a));
}

__device__ __forceinline__ void ldsm4t(uint32_t* r, uint32_t a) {
    asm volatile("ldmatrix.sync.aligned.m8n8.x4.trans.shared.b16 {%0,%1,%2,%3}, [%4];"
                 : "=r"(r[0]), "=r"(r[1]), "=r"(r[2]), "=r"(r[3]) : "r"(a));
}

__device__ __forceinline__ void mma16816(float* d, const uint32_t* a, const uint32_t* b) {
    asm volatile(
        "mma.sync.aligned.m16n8k16.row.col.f32.f16.f16.f32 "
        "{%0,%1,%2,%3}, {%4,%5,%6,%7}, {%8,%9}, {%0,%1,%2,%3};"
        : "+f"(d[0]), "+f"(d[1]), "+f"(d[2]), "+f"(d[3])
        : "r"(a[0]), "r"(a[1]), "r"(a[2]), "r"(a[3]), "r"(b[0]), "r"(b[1]));
}

__device__ __forceinline__ uint32_t packh2(float a, float b) {
    __half2 t = __floats2half2_rn(a, b);
    return *(uint32_t*)&t;
}

// ---------------- conversions ----------------
__global__ __launch_bounds__(256) void cvt_h(
    const float* __restrict__ X, __half* __restrict__ hi, int n4)
{
    int i = blockIdx.x * 256 + threadIdx.x;
    if (i >= n4) return;
    float4 v = ((const float4*)X)[i];
    ((__half2*)hi)[2*i]   = __floats2half2_rn(v.x, v.y);
    ((__half2*)hi)[2*i+1] = __floats2half2_rn(v.z, v.w);
}

struct W7 {
    const float* s[7];
    __half* d[7];
    int cum[8];
};

__global__ __launch_bounds__(256) void cvt_w7(W7 jobs)
{
    int i = blockIdx.x * 256 + threadIdx.x;
    if (i >= jobs.cum[7]) return;
    int j = 0;
    #pragma unroll
    for (int t = 1; t < 7; t++) if (i >= jobs.cum[t]) j = t;
    int li = i - jobs.cum[j];
    float4 v = ((const float4*)jobs.s[j])[li];
    ((__half2*)jobs.d[j])[2*li]   = __floats2half2_rn(v.x, v.y);
    ((__half2*)jobs.d[j])[2*li+1] = __floats2half2_rn(v.z, v.w);
}

// ---------------- mma.sync GEMM: C = A(MxK) * B(NxK)^T  (fp16 single-pass) ----------------
#define KC 32
#define ROWB 80
#define TILEB (128*ROWB)
#define STG (2*TILEB)
#define MM_SMEM (2*STG)

__device__ __forceinline__ void mm_load_chunk(
    const __half* __restrict__ Ah, const __half* __restrict__ Bh,
    int K, int rowBase, int colBase, int tid, int c, uint32_t stageBase)
{
    const __half* mats[2] = {Ah, Bh};
    #pragma unroll
    for (int it = 0; it < 4; it++) {
        int t = it >> 1;
        int v = tid + (it & 1) * 256;
        int r = v >> 2;
        int ch = v & 3;
        int rb = (t == 0) ? rowBase : colBase;
        const void* g = mats[t] + (size_t)(rb + r) * K + c * KC + ch * 8;
        uint32_t d = stageBase + t * TILEB + r * ROWB + ch * 16;
        asm volatile("cp.async.cg.shared.global [%0], [%1], 16;" :: "r"(d), "l"(g));
    }
    asm volatile("cp.async.commit_group;" ::: "memory");
}

__global__ __launch_bounds__(256, 2) void mm_tc(
    const __half* __restrict__ Ah, const __half* __restrict__ Bh,
    float* __restrict__ C, const float* __restrict__ bias,
    int K, int ldc, int colOff, int relu,
    __half* __restrict__ Ch)
{
    extern __shared__ char mm_smem[];
    const int tid = threadIdx.x;
    const int wid = tid >> 5, lane = tid & 31;
    const int wm = wid >> 1, wn = wid & 1;
    const int rowBase = blockIdx.y * 128;
    const int colBase = blockIdx.x * 128;
    const uint32_t sb = smem_u32(mm_smem);

    const int lrA = (lane & 15);
    const int lcA = (lane >> 4) * 16;
    const int lrB = (lane & 7) + (lane >> 4) * 8;
    const int lcB = ((lane >> 3) & 1) * 16;

    float acc[2][8][4];
    #pragma unroll
    for (int i = 0; i < 2; i++)
        #pragma unroll
        for (int j = 0; j < 8; j++)
            #pragma unroll
            for (int e = 0; e < 4; e++) acc[i][j][e] = 0.f;

    const int CC = K / KC;
    mm_load_chunk(Ah, Bh, K, rowBase, colBase, tid, 0, sb);

    for (int c = 0; c < CC; c++) {
        int s = c & 1;
        if (c + 1 < CC) {
            mm_load_chunk(Ah, Bh, K, rowBase, colBase, tid, c + 1, sb + (s ^ 1) * STG);
            asm volatile("cp.async.wait_group 1;" ::: "memory");
        } else {
            asm volatile("cp.async.wait_group 0;" ::: "memory");
        }
        __syncthreads();

        uint32_t base = sb + s * STG;
        #pragma unroll
        for (int ks = 0; ks < 2; ks++) {
            uint32_t bf[8][2];
            #pragma unroll
            for (int j2 = 0; j2 < 4; j2++) {
                uint32_t r4[4];
                ldsm4(r4, base + TILEB + (uint32_t)(wn * 64 + j2 * 16 + lrB) * ROWB + ks * 32 + lcB);
                bf[2*j2][0]   = r4[0]; bf[2*j2][1]   = r4[1];
                bf[2*j2+1][0] = r4[2]; bf[2*j2+1][1] = r4[3];
            }
            uint32_t af[2][4];
            #pragma unroll
            for (int i = 0; i < 2; i++)
                ldsm4(af[i], base + (uint32_t)(wm * 32 + i * 16 + lrA) * ROWB + ks * 32 + lcA);
            #pragma unroll
            for (int i = 0; i < 2; i++)
                #pragma unroll
                for (int j = 0; j < 8; j++)
                    mma16816(acc[i][j], af[i], bf[j]);
        }
        __syncthreads();
    }

    // epilogue
    #pragma unroll
    for (int i = 0; i < 2; i++) {
        int row0 = rowBase + wm * 32 + i * 16 + (lane >> 2);
        #pragma unroll
        for (int j = 0; j < 8; j++) {
            int col = colBase + wn * 64 + j * 8 + (lane & 3) * 2;
            float b0 = 0.f, b1 = 0.f;
            if (bias) { b0 = bias[col]; b1 = bias[col + 1]; }
            float2 v0 = make_float2(acc[i][j][0] + b0, acc[i][j][1] + b1);
            float2 v1 = make_float2(acc[i][j][2] + b0, acc[i][j][3] + b1);
            if (relu) {
                v0.x = fmaxf(v0.x, 0.f); v0.y = fmaxf(v0.y, 0.f);
                v1.x = fmaxf(v1.x, 0.f); v1.y = fmaxf(v1.y, 0.f);
            }
            size_t o0 = (size_t)row0 * ldc + colOff + col;
            size_t o1 = (size_t)(row0 + 8) * ldc + colOff + col;
            if (C) {
                *(float2*)(C + o0) = v0;
                *(float2*)(C + o1) = v1;
            }
            if (Ch) {
                *(__half2*)(Ch + o0) = __floats2half2_rn(v0.x, v0.y);
                *(__half2*)(Ch + o1) = __floats2half2_rn(v1.x, v1.y);
            }
        }
    }
}

// ---------------- tensor-core flash attention (global + local windowed) ----------------
// CTA: 4 warps; Q tile 64 rows, K tiles of 64, DH=64. fp16 single-pass.
// smem: Q tile + 2 stages of {Kh, Vh}. Tile = 64 rows x 128B data, stride 144B.
#define AROW 144
#define GA_TILE 9216
#define GA_STG (2*GA_TILE)
#define GA_SMEM (GA_TILE + 2*GA_STG)

__device__ __forceinline__ void at_load_kv(
    const __half* __restrict__ qH, int b, int h, int kt, int tid, uint32_t stBase)
{
    #pragma unroll
    for (int m = 0; m < 2; m++) {
        int col = ((m == 0) ? DD : 2 * DD) + h * DHH;
        #pragma unroll
        for (int i = 0; i < 4; i++) {
            int idx = tid + i * 128;           // 0..511 = 64 rows x 8 chunks
            int r = idx >> 3, ch = idx & 7;
            const void* g = qH + (size_t)(b * SS + kt * 64 + r) * TDD + col + ch * 8;
            uint32_t d = stBase + m * GA_TILE + r * AROW + ch * 16;
            asm volatile("cp.async.cg.shared.global [%0], [%1], 16;" :: "r"(d), "l"(g));
        }
    }
    asm volatile("cp.async.commit_group;" ::: "memory");
}

__global__ __launch_bounds__(128) void attn_tc(
    const __half* __restrict__ qH, __half* __restrict__ oH, int local)
{
    extern __shared__ char ga_smem[];
    const int tid = threadIdx.x, wid = tid >> 5, lane = tid & 31;
    const int qt = blockIdx.x, h = blockIdx.y, b = blockIdx.z;
    const uint32_t sb = smem_u32(ga_smem);

    int ktLo = 0, ktHi = SS / 64 - 1;
    if (local) {
        ktLo = qt - 2 - (qt & 1);
        if (ktLo < 0) ktLo = 0;
        ktHi = qt;
    }

    // Q load (group 0)
    #pragma unroll
    for (int i = 0; i < 4; i++) {
        int idx = tid + i * 128;
        int r = idx >> 3, ch = idx & 7;
        const void* g = qH + (size_t)(b * SS + qt * 64 + r) * TDD + h * DHH + ch * 8;
        uint32_t d = sb + r * AROW + ch * 16;
        asm volatile("cp.async.cg.shared.global [%0], [%1], 16;" :: "r"(d), "l"(g));
    }
    asm volatile("cp.async.commit_group;" ::: "memory");
    at_load_kv(qH, b, h, ktLo, tid, sb + GA_TILE);

    asm volatile("cp.async.wait_group 1;" ::: "memory");   // Q done
    __syncthreads();

    const int lr16 = lane & 15;
    const int hi16 = lane >> 4;
    uint32_t qf[4][4];
    #pragma unroll
    for (int ks = 0; ks < 4; ks++)
        ldsm4(qf[ks], sb + (uint32_t)(wid * 16 + lr16) * AROW + ks * 32 + hi16 * 16);

    float oacc[8][4];
    #pragma unroll
    for (int j = 0; j < 8; j++)
        #pragma unroll
        for (int e = 0; e < 4; e++) oacc[j][e] = 0.f;
    float m0 = -1e30f, m1 = -1e30f, l0 = 0.f, l1 = 0.f;
    const int lrB = (lane & 7) + (lane >> 4) * 8;
    const int lcB = ((lane >> 3) & 1) * 16;

    for (int kt = ktLo; kt <= ktHi; kt++) {
        int s = (kt - ktLo) & 1;
        uint32_t st = sb + GA_TILE + s * GA_STG;
        if (kt < ktHi) {
            at_load_kv(qH, b, h, kt + 1, tid, sb + GA_TILE + (s ^ 1) * GA_STG);
            asm volatile("cp.async.wait_group 1;" ::: "memory");
        } else {
            asm volatile("cp.async.wait_group 0;" ::: "memory");
        }
        __syncthreads();

        // S = Q K^T (single-pass fp16)
        float sacc[8][4];
        #pragma unroll
        for (int j = 0; j < 8; j++)
            #pragma unroll
            for (int e = 0; e < 4; e++) sacc[j][e] = 0.f;

        #pragma unroll
        for (int ks = 0; ks < 4; ks++) {
            uint32_t kf[4][4];
            #pragma unroll
            for (int n2 = 0; n2 < 4; n2++)
                ldsm4(kf[n2], st + (uint32_t)(n2 * 16 + lrB) * AROW + ks * 32 + lcB);
            #pragma unroll
            for (int j = 0; j < 8; j++)
                mma16816(sacc[j], qf[ks], &kf[j >> 1][(j & 1) * 2]);
        }

        // scale
        #pragma unroll
        for (int j = 0; j < 8; j++) {
            sacc[j][0] *= 0.125f; sacc[j][1] *= 0.125f;
            sacc[j][2] *= 0.125f; sacc[j][3] *= 0.125f;
        }
        // causal mask on diagonal tile (local attention)
        if (local && kt == ktHi) {
            int r0 = wid * 16 + (lane >> 2);
            #pragma unroll
            for (int j = 0; j < 8; j++) {
                int c = j * 8 + (lane & 3) * 2;
                if (c     > r0)     sacc[j][0] = -1e30f;
                if (c + 1 > r0)     sacc[j][1] = -1e30f;
                if (c     > r0 + 8) sacc[j][2] = -1e30f;
                if (c + 1 > r0 + 8) sacc[j][3] = -1e30f;
            }
        }

        // online softmax (rows r0 and r0+8)
        float t0 = -1e30f, t1 = -1e30f;
        #pragma unroll
        for (int j = 0; j < 8; j++) {
            t0 = fmaxf(t0, fmaxf(sacc[j][0], sacc[j][1]));
            t1 = fmaxf(t1, fmaxf(sacc[j][2], sacc[j][3]));
        }
        t0 = fmaxf(t0, __shfl_xor_sync(0xffffffffu, t0, 1));
        t0 = fmaxf(t0, __shfl_xor_sync(0xffffffffu, t0, 2));
        t1 = fmaxf(t1, __shfl_xor_sync(0xffffffffu, t1, 1));
        t1 = fmaxf(t1, __shfl_xor_sync(0xffffffffu, t1, 2));
        float mn0 = fmaxf(m0, t0), mn1 = fmaxf(m1, t1);
        float c0 = __expf(m0 - mn0), c1 = __expf(m1 - mn1);
        float s0 = 0.f, s1 = 0.f;
        #pragma unroll
        for (int j = 0; j < 8; j++) {
            sacc[j][0] = __expf(sacc[j][0] - mn0);
            sacc[j][1] = __expf(sacc[j][1] - mn0);
            sacc[j][2] = __expf(sacc[j][2] - mn1);
            sacc[j][3] = __expf(sacc[j][3] - mn1);
            s0 += sacc[j][0] + sacc[j][1];
            s1 += sacc[j][2] + sacc[j][3];
        }
        s0 += __shfl_xor_sync(0xffffffffu, s0, 1);
        s0 += __shfl_xor_sync(0xffffffffu, s0, 2);
        s1 += __shfl_xor_sync(0xffffffffu, s1, 1);
        s1 += __shfl_xor_sync(0xffffffffu, s1, 2);
        l0 = l0 * c0 + s0;
        l1 = l1 * c1 + s1;
        m0 = mn0; m1 = mn1;
        #pragma unroll
        for (int j = 0; j < 8; j++) {
            oacc[j][0] *= c0; oacc[j][1] *= c0;
            oacc[j][2] *= c1; oacc[j][3] *= c1;
        }

        // O += P V
        #pragma unroll
        for (int kp = 0; kp < 4; kp++) {
            uint32_t pf[4];
            pf[0] = packh2(sacc[2*kp][0],   sacc[2*kp][1]);
            pf[1] = packh2(sacc[2*kp][2],   sacc[2*kp][3]);
            pf[2] = packh2(sacc[2*kp+1][0], sacc[2*kp+1][1]);
            pf[3] = packh2(sacc[2*kp+1][2], sacc[2*kp+1][3]);
            uint32_t vf[4][4];
            #pragma unroll
            for (int n2 = 0; n2 < 4; n2++)
                ldsm4t(vf[n2], st + GA_TILE + (uint32_t)(kp * 16 + lr16) * AROW + n2 * 32 + hi16 * 16);
            #pragma unroll
            for (int j = 0; j < 8; j++)
                mma16816(oacc[j], pf, &vf[j >> 1][(j & 1) * 2]);
        }
        __syncthreads();
    }

    // epilogue: normalize, write fp16
    float il0 = 1.f / l0, il1 = 1.f / l1;
    int r0g = b * SS + qt * 64 + wid * 16 + (lane >> 2);
    size_t o0 = (size_t)r0g * DD + h * DHH;
    size_t o1 = o0 + (size_t)8 * DD;
    #pragma unroll
    for (int j = 0; j < 8; j++) {
        int col = j * 8 + (lane & 3) * 2;
        *(__half2*)(oH + o0 + col) = __floats2half2_rn(oacc[j][0] * il0, oacc[j][1] * il0);
        *(__half2*)(oH + o1 + col) = __floats2half2_rn(oacc[j][2] * il1, oacc[j][3] * il1);
    }
}

// ---------------- LayerNorm (fp32 out optional, fp16 out optional) ----------------
__global__ __launch_bounds__(128) void ln_kernel(
    const float* __restrict__ X, const float* __restrict__ R,
    const float* __restrict__ gam, const float* __restrict__ bet,
    float* __restrict__ out, __half* __restrict__ outH)
{
    __shared__ float red[8];
    const int row = blockIdx.x;
    const int tid = threadIdx.x;
    float4 v = ((const float4*)(X + (size_t)row * DD))[tid];
    if (R) {
        float4 r = ((const float4*)(R + (size_t)row * DD))[tid];
        v.x += r.x; v.y += r.y; v.z += r.z; v.w += r.w;
    }
    float s  = v.x + v.y + v.z + v.w;
    float sq = v.x*v.x + v.y*v.y + v.z*v.z + v.w*v.w;
    #pragma unroll
    for (int o = 16; o; o >>= 1) {
        s  += __shfl_xor_sync(0xffffffffu, s,  o);
        sq += __shfl_xor_sync(0xffffffffu, sq, o);
    }
    int w = tid >> 5;
    if ((tid & 31) == 0) { red[w*2] = s; red[w*2+1] = sq; }
    __syncthreads();
    s  = red[0] + red[2] + red[4] + red[6];
    sq = red[1] + red[3] + red[5] + red[7];
    float mean = s * (1.f / DD);
    float var  = sq * (1.f / DD) - mean * mean;
    float inv  = rsqrtf(var + 1e-5f);
    float4 gg = ((const float4*)gam)[tid];
    float4 bb = ((const float4*)bet)[tid];
    float4 r;
    r.x = (v.x - mean) * inv * gg.x + bb.x;
    r.y = (v.y - mean) * inv * gg.y + bb.y;
    r.z = (v.z - mean) * inv * gg.z + bb.z;
    r.w = (v.w - mean) * inv * gg.w + bb.w;
    if (out) ((float4*)(out + (size_t)row * DD))[tid] = r;
    if (outH) {
        size_t o = (size_t)row * DD + tid * 4;
        *(__half2*)(outH + o)     = __floats2half2_rn(r.x, r.y);
        *(__half2*)(outH + o + 2) = __floats2half2_rn(r.z, r.w);
    }
}

// ---------------- RoPE: fp32 qkl -> roped q,k + v, fp16 ----------------
__global__ __launch_bounds__(256) void rope_h(
    const float* __restrict__ qkl, __half* __restrict__ H)
{
    const int row = blockIdx.x;
    const int pos = row & (SS - 1);
    const int t = threadIdx.x;
    const int h = t >> 5;
    const int f = t & 31;
    float inv_freq = powf(10000.f, -(float)f * (1.f / 32.f));
    float fr = (float)pos * inv_freq;
    float c, sn;
    sincosf(fr, &sn, &c);
    size_t base = (size_t)row * TDD + h * DHH + f;

    float x1 = qkl[base], x2 = qkl[base + 32];
    H[base]      = __float2half_rn(x1 * c - x2 * sn);
    H[base + 32] = __float2half_rn(x2 * c + x1 * sn);
    x1 = qkl[base + DD]; x2 = qkl[base + DD + 32];
    H[base + DD]      = __float2half_rn(x1 * c - x2 * sn);
    H[base + DD + 32] = __float2half_rn(x2 * c + x1 * sn);
    H[base + 2 * DD]      = __float2half_rn(qkl[base + 2 * DD]);
    H[base + 2 * DD + 32] = __float2half_rn(qkl[base + 2 * DD + 32]);
}

// ---------------- launch ----------------
extern "C" void kernel_launch(void* const* d_in, const int* in_sizes, int n_in,
                              void* d_out, int out_size)
{
    (void)in_sizes; (void)n_in; (void)out_size;
    const float* src        = (const float*)d_in[0];
    const float* in_proj_b  = (const float*)d_in[2];
    const float* out_proj_b = (const float*)d_in[4];
    const float* ln_g       = (const float*)d_in[5];
    const float* ln_b       = (const float*)d_in[6];
    const float* gl_b       = (const float*)d_in[10];
    const float* norm1_g    = (const float*)d_in[11];
    const float* norm1_b    = (const float*)d_in[12];
    const float* lin1_b     = (const float*)d_in[14];
    const float* lin2_b     = (const float*)d_in[16];
    const float* norm2_g    = (const float*)d_in[17];
    const float* norm2_b    = (const float*)d_in[18];
    float* outp = (float*)d_out;

    cudaFuncSetAttribute(mm_tc, cudaFuncAttributeMaxDynamicSharedMemorySize, MM_SMEM);
    cudaFuncSetAttribute(attn_tc, cudaFuncAttributeMaxDynamicSharedMemorySize, GA_SMEM);

    float *p_qkl, *p_src2, *p_h1, *p_ff2;
    cudaGetSymbolAddress((void**)&p_qkl,  g_qkl);
    cudaGetSymbolAddress((void**)&p_src2, g_src2);
    cudaGetSymbolAddress((void**)&p_h1,   g_h1);
    cudaGetSymbolAddress((void**)&p_ff2,  g_ff2);

    __half *srcH,*qkvH,*qklH,*goH,*xH,*loH,*catH,*h1H,*ff1H;
    __half *w1H,*w2H,*w3H,*w4H,*w5H,*w6H,*w7H;
    cudaGetSymbolAddress((void**)&srcH, c_src_h);
    cudaGetSymbolAddress((void**)&qkvH, c_qkv_h);
    cudaGetSymbolAddress((void**)&qklH, c_qkl_h);
    cudaGetSymbolAddress((void**)&goH,  c_go_h);
    cudaGetSymbolAddress((void**)&xH,   c_x_h);
    cudaGetSymbolAddress((void**)&loH,  c_lo_h);
    cudaGetSymbolAddress((void**)&catH, c_cat_h);
    cudaGetSymbolAddress((void**)&h1H,  c_h1_h);
    cudaGetSymbolAddress((void**)&ff1H, c_ff1_h);
    cudaGetSymbolAddress((void**)&w1H, c_w1_h);
    cudaGetSymbolAddress((void**)&w2H, c_w2_h);
    cudaGetSymbolAddress((void**)&w3H, c_w3_h);
    cudaGetSymbolAddress((void**)&w4H, c_w4_h);
    cudaGetSymbolAddress((void**)&w5H, c_w5_h);
    cudaGetSymbolAddress((void**)&w6H, c_w6_h);
    cudaGetSymbolAddress((void**)&w7H, c_w7_h);

    // weight conversions, one launch
    {
        W7 jobs;
        const float* ws[7] = {(const float*)d_in[1], (const float*)d_in[3],
                              (const float*)d_in[7], (const float*)d_in[8],
                              (const float*)d_in[9], (const float*)d_in[13],
                              (const float*)d_in[15]};
        __half* wd[7] = {w1H, w2H, w3H, w4H, w5H, w6H, w7H};
        int sz[7] = {TDD*DD, DD*DD, TDD*DD, DD*DD, DD*2*DD, FFD*DD, DD*FFD};
        int cum = 0;
        for (int j = 0; j < 7; j++) {
            jobs.s[j] = ws[j]; jobs.d[j] = wd[j];
            jobs.cum[j] = cum; cum += sz[j] / 4;
        }
        jobs.cum[7] = cum;
        cvt_w7<<<(cum + 255) / 256, 256>>>(jobs);
    }
    cvt_h<<<(NROWS*DD/4 + 255) / 256, 256>>>(src, srcH, NROWS*DD/4);

    // 1. qkv = src @ in_proj_w^T + b -> fp16
    mm_tc<<<dim3(TDD/128, NROWS/128), 256, MM_SMEM>>>(srcH, w1H,
        nullptr, in_proj_b, DD, TDD, 0, 0, qkvH);
    // 2. global attention -> goH
    attn_tc<<<dim3(SS/64, HH, BB), 128, GA_SMEM>>>(qkvH, goH, 0);
    // 3. go2 = go @ out_proj_w^T + b -> cat[:, 0:512]
    mm_tc<<<dim3(DD/128, NROWS/128), 256, MM_SMEM>>>(goH, w2H,
        nullptr, out_proj_b, DD, 2*DD, 0, 0, catH);
    // 4. x = LN(src) -> fp16
    ln_kernel<<<NROWS, 128>>>(src, nullptr, ln_g, ln_b, nullptr, xH);
    // 5. qkl = x @ qkv_w^T -> fp32 (for rope)
    mm_tc<<<dim3(TDD/128, NROWS/128), 256, MM_SMEM>>>(xH, w3H,
        p_qkl, nullptr, DD, TDD, 0, 0, nullptr);
    // 6. rope -> qklH (roped q,k + v)
    rope_h<<<NROWS, 256>>>(p_qkl, qklH);
    // 7. local windowed attention -> loH
    attn_tc<<<dim3(SS/64, HH, BB), 128, GA_SMEM>>>(qklH, loH, 1);
    // 8. lo2 = lo @ to_out_w^T -> cat[:, 512:1024]
    mm_tc<<<dim3(DD/128, NROWS/128), 256, MM_SMEM>>>(loH, w4H,
        nullptr, nullptr, DD, 2*DD, DD, 0, catH);
    // 9. src2 = cat @ gl_w^T + gl_b -> fp32
    mm_tc<<<dim3(DD/128, NROWS/128), 256, MM_SMEM>>>(catH, w5H,
        p_src2, gl_b, 2*DD, DD, 0, 0, nullptr);
    // 10. h1 = LN(src + src2) -> fp32 + fp16
    ln_kernel<<<NROWS, 128>>>(p_src2, src, norm1_g, norm1_b, p_h1, h1H);
    // 11. ff1 = relu(h1 @ lin1_w^T + b) -> fp16
    mm_tc<<<dim3(FFD/128, NROWS/128), 256, MM_SMEM>>>(h1H, w6H,
        nullptr, lin1_b, DD, FFD, 0, 1, ff1H);
    // 12. ff2 = ff1 @ lin2_w^T + b -> fp32
    mm_tc<<<dim3(DD/128, NROWS/128), 256, MM_SMEM>>>(ff1H, w7H,
        p_ff2, lin2_b, FFD, DD, 0, 0, nullptr);
    // 13. out = LN(h1 + ff2)
    ln_kernel<<<NROWS, 128>>>(p_ff2, p_h1, norm2_g, norm2_b, outp, nullptr);
}

// round 16
// speedup vs baseline: 7.0946x; 1.0471x over previous
#include <cuda_runtime.h>
#include <cuda_fp16.h>
#include <cstdint>

// ---------------- constants ----------------
#define BB 4
#define SS 2048
#define DD 512
#define HH 8
#define DHH 64
#define WW 128
#define NWIN 16
#define FFD 2048
#define TDD 1536   // 3*D
#define NROWS (BB*SS)   // 8192
#define QSCALE 0.18033688f   // 0.125 * log2(e)

// ---------------- fp32 scratch ----------------
__device__ float g_src2[NROWS * DD];
__device__ float g_h1  [NROWS * DD];
__device__ float g_ff2 [NROWS * DD];

// ---------------- fp16 buffers ----------------
__device__ __half c_src_h[NROWS*DD];
__device__ __half c_qkv_h[NROWS*TDD];
__device__ __half c_qkl_h[NROWS*TDD];
__device__ __half c_go_h [NROWS*DD];
__device__ __half c_x_h  [NROWS*DD];
__device__ __half c_lo_h [NROWS*DD];
__device__ __half c_cat_h[NROWS*2*DD];
__device__ __half c_h1_h [NROWS*DD];
__device__ __half c_ff1_h[NROWS*FFD];
__device__ __half c_w1_h[TDD*DD];
__device__ __half c_w2_h[DD*DD];
__device__ __half c_w3_h[TDD*DD];
__device__ __half c_w4_h[DD*DD];
__device__ __half c_w5_h[DD*2*DD];
__device__ __half c_w6_h[FFD*DD];
__device__ __half c_w7_h[DD*FFD];

// ---------------- helpers ----------------
__device__ __forceinline__ uint32_t smem_u32(const void* p) {
    uint32_t a;
    asm("{ .reg .u64 t; cvta.to.shared.u64 t, %1; cvt.u32.u64 %0, t; }" : "=r"(a) : "l"(p));
    return a;
}

__device__ __forceinline__ void ldsm4(uint32_t* r, uint32_t a) {
    asm volatile("ldmatrix.sync.aligned.m8n8.x4.shared.b16 {%0,%1,%2,%3}, [%4];"
                 : "=r"(r[0]), "=r"(r[1]), "=r"(r[2]), "=r"(r[3]) : "r"(a));
}

__device__ __forceinline__ void ldsm4t(uint32_t* r, uint32_t a) {
    asm volatile("ldmatrix.sync.aligned.m8n8.x4.trans.shared.b16 {%0,%1,%2,%3}, [%4];"
                 : "=r"(r[0]), "=r"(r[1]), "=r"(r[2]), "=r"(r[3]) : "r"(a));
}

__device__ __forceinline__ void mma16816(float* d, const uint32_t* a, const uint32_t* b) {
    asm volatile(
        "mma.sync.aligned.m16n8k16.row.col.f32.f16.f16.f32 "
        "{%0,%1,%2,%3}, {%4,%5,%6,%7}, {%8,%9}, {%0,%1,%2,%3};"
        : "+f"(d[0]), "+f"(d[1]), "+f"(d[2]), "+f"(d[3])
        : "r"(a[0]), "r"(a[1]), "r"(a[2]), "r"(a[3]), "r"(b[0]), "r"(b[1]));
}

__device__ __forceinline__ uint32_t packh2(float a, float b) {
    __half2 t = __floats2half2_rn(a, b);
    return *(uint32_t*)&t;
}

__device__ __forceinline__ float ex2(float x) {
    float y;
    asm("ex2.approx.ftz.f32 %0, %1;" : "=f"(y) : "f"(x));
    return y;
}

// ---------------- conversions ----------------
__global__ __launch_bounds__(256) void cvt_h(
    const float* __restrict__ X, __half* __restrict__ hi, int n4)
{
    int i = blockIdx.x * 256 + threadIdx.x;
    if (i >= n4) return;
    float4 v = ((const float4*)X)[i];
    ((__half2*)hi)[2*i]   = __floats2half2_rn(v.x, v.y);
    ((__half2*)hi)[2*i+1] = __floats2half2_rn(v.z, v.w);
}

struct W7 {
    const float* s[7];
    __half* d[7];
    int cum[8];
};

__global__ __launch_bounds__(256) void cvt_w7(W7 jobs)
{
    int i = blockIdx.x * 256 + threadIdx.x;
    if (i >= jobs.cum[7]) return;
    int j = 0;
    #pragma unroll
    for (int t = 1; t < 7; t++) if (i >= jobs.cum[t]) j = t;
    int li = i - jobs.cum[j];
    float4 v = ((const float4*)jobs.s[j])[li];
    ((__half2*)jobs.d[j])[2*li]   = __floats2half2_rn(v.x, v.y);
    ((__half2*)jobs.d[j])[2*li+1] = __floats2half2_rn(v.z, v.w);
}

// ---------------- mma.sync GEMM: C = A(MxK) * B(NxK)^T  (fp16, 3-stage ring) ----------------
#define KC 32
#define ROWB 80
#define TILEB (128*ROWB)
#define STG (2*TILEB)
#define MM_SMEM (3*STG)

__device__ __forceinline__ void mm_load_chunk(
    const __half* __restrict__ Ah, const __half* __restrict__ Bh,
    int K, int rowBase, int colBase, int tid, int c, uint32_t stageBase)
{
    const __half* mats[2] = {Ah, Bh};
    #pragma unroll
    for (int it = 0; it < 4; it++) {
        int t = it >> 1;
        int v = tid + (it & 1) * 256;
        int r = v >> 2;
        int ch = v & 3;
        int rb = (t == 0) ? rowBase : colBase;
        const void* g = mats[t] + (size_t)(rb + r) * K + c * KC + ch * 8;
        uint32_t d = stageBase + t * TILEB + r * ROWB + ch * 16;
        asm volatile("cp.async.cg.shared.global [%0], [%1], 16;" :: "r"(d), "l"(g));
    }
    asm volatile("cp.async.commit_group;" ::: "memory");
}

__global__ __launch_bounds__(256, 2) void mm_tc(
    const __half* __restrict__ Ah, const __half* __restrict__ Bh,
    float* __restrict__ C, const float* __restrict__ bias,
    int K, int ldc, int colOff, int relu,
    __half* __restrict__ Ch, float qscale, int qlim)
{
    extern __shared__ char mm_smem[];
    const int tid = threadIdx.x;
    const int wid = tid >> 5, lane = tid & 31;
    const int wm = wid >> 1, wn = wid & 1;
    const int rowBase = blockIdx.y * 128;
    const int colBase = blockIdx.x * 128;
    const uint32_t sb = smem_u32(mm_smem);

    const int lrA = (lane & 15);
    const int lcA = (lane >> 4) * 16;
    const int lrB = (lane & 7) + (lane >> 4) * 8;
    const int lcB = ((lane >> 3) & 1) * 16;

    float acc[2][8][4];
    #pragma unroll
    for (int i = 0; i < 2; i++)
        #pragma unroll
        for (int j = 0; j < 8; j++)
            #pragma unroll
            for (int e = 0; e < 4; e++) acc[i][j][e] = 0.f;

    const int CC = K / KC;   // >= 16 for all our shapes
    mm_load_chunk(Ah, Bh, K, rowBase, colBase, tid, 0, sb);
    mm_load_chunk(Ah, Bh, K, rowBase, colBase, tid, 1, sb + STG);

    for (int c = 0; c < CC; c++) {
        if (c + 1 < CC) {
            asm volatile("cp.async.wait_group 1;" ::: "memory");
        } else {
            asm volatile("cp.async.wait_group 0;" ::: "memory");
        }
        __syncthreads();
        if (c + 2 < CC)
            mm_load_chunk(Ah, Bh, K, rowBase, colBase, tid, c + 2,
                          sb + (uint32_t)((c + 2) % 3) * STG);

        uint32_t base = sb + (uint32_t)(c % 3) * STG;
        #pragma unroll
        for (int ks = 0; ks < 2; ks++) {
            uint32_t bf[8][2];
            #pragma unroll
            for (int j2 = 0; j2 < 4; j2++) {
                uint32_t r4[4];
                ldsm4(r4, base + TILEB + (uint32_t)(wn * 64 + j2 * 16 + lrB) * ROWB + ks * 32 + lcB);
                bf[2*j2][0]   = r4[0]; bf[2*j2][1]   = r4[1];
                bf[2*j2+1][0] = r4[2]; bf[2*j2+1][1] = r4[3];
            }
            uint32_t af[2][4];
            #pragma unroll
            for (int i = 0; i < 2; i++)
                ldsm4(af[i], base + (uint32_t)(wm * 32 + i * 16 + lrA) * ROWB + ks * 32 + lcA);
            #pragma unroll
            for (int i = 0; i < 2; i++)
                #pragma unroll
                for (int j = 0; j < 8; j++)
                    mma16816(acc[i][j], af[i], bf[j]);
        }
    }

    // epilogue
    #pragma unroll
    for (int i = 0; i < 2; i++) {
        int row0 = rowBase + wm * 32 + i * 16 + (lane >> 2);
        #pragma unroll
        for (int j = 0; j < 8; j++) {
            int col = colBase + wn * 64 + j * 8 + (lane & 3) * 2;
            float b0 = 0.f, b1 = 0.f;
            if (bias) { b0 = bias[col]; b1 = bias[col + 1]; }
            float2 v0 = make_float2(acc[i][j][0] + b0, acc[i][j][1] + b1);
            float2 v1 = make_float2(acc[i][j][2] + b0, acc[i][j][3] + b1);
            if (relu) {
                v0.x = fmaxf(v0.x, 0.f); v0.y = fmaxf(v0.y, 0.f);
                v1.x = fmaxf(v1.x, 0.f); v1.y = fmaxf(v1.y, 0.f);
            }
            if (col < qlim) {   // q columns: fold attention scale (incl. log2e)
                v0.x *= qscale; v0.y *= qscale;
                v1.x *= qscale; v1.y *= qscale;
            }
            size_t o0 = (size_t)row0 * ldc + colOff + col;
            size_t o1 = (size_t)(row0 + 8) * ldc + colOff + col;
            if (C) {
                *(float2*)(C + o0) = v0;
                *(float2*)(C + o1) = v1;
            }
            if (Ch) {
                *(__half2*)(Ch + o0) = __floats2half2_rn(v0.x, v0.y);
                *(__half2*)(Ch + o1) = __floats2half2_rn(v1.x, v1.y);
            }
        }
    }
}

// ---------------- tensor-core flash attention (global + local windowed) ----------------
// CTA: 4 warps; Q tile 64 rows, K tiles of 64, DH=64. fp16 single-pass.
// Q pre-scaled by 0.125*log2e at the producer; softmax uses ex2 directly.
#define AROW 144
#define GA_TILE 9216
#define GA_STG (2*GA_TILE)
#define GA_SMEM (GA_TILE + 2*GA_STG)

__device__ __forceinline__ void at_load_kv(
    const __half* __restrict__ qH, int b, int h, int kt, int tid, uint32_t stBase)
{
    #pragma unroll
    for (int m = 0; m < 2; m++) {
        int col = ((m == 0) ? DD : 2 * DD) + h * DHH;
        #pragma unroll
        for (int i = 0; i < 4; i++) {
            int idx = tid + i * 128;           // 0..511 = 64 rows x 8 chunks
            int r = idx >> 3, ch = idx & 7;
            const void* g = qH + (size_t)(b * SS + kt * 64 + r) * TDD + col + ch * 8;
            uint32_t d = stBase + m * GA_TILE + r * AROW + ch * 16;
            asm volatile("cp.async.cg.shared.global [%0], [%1], 16;" :: "r"(d), "l"(g));
        }
    }
    asm volatile("cp.async.commit_group;" ::: "memory");
}

__global__ __launch_bounds__(128) void attn_tc(
    const __half* __restrict__ qH, __half* __restrict__ oH, int local)
{
    extern __shared__ char ga_smem[];
    const int tid = threadIdx.x, wid = tid >> 5, lane = tid & 31;
    const int qt = blockIdx.x, h = blockIdx.y, b = blockIdx.z;
    const uint32_t sb = smem_u32(ga_smem);

    int ktLo = 0, ktHi = SS / 64 - 1;
    if (local) {
        ktLo = qt - 2 - (qt & 1);
        if (ktLo < 0) ktLo = 0;
        ktHi = qt;
    }

    // Q load (group 0)
    #pragma unroll
    for (int i = 0; i < 4; i++) {
        int idx = tid + i * 128;
        int r = idx >> 3, ch = idx & 7;
        const void* g = qH + (size_t)(b * SS + qt * 64 + r) * TDD + h * DHH + ch * 8;
        uint32_t d = sb + r * AROW + ch * 16;
        asm volatile("cp.async.cg.shared.global [%0], [%1], 16;" :: "r"(d), "l"(g));
    }
    asm volatile("cp.async.commit_group;" ::: "memory");
    at_load_kv(qH, b, h, ktLo, tid, sb + GA_TILE);

    asm volatile("cp.async.wait_group 1;" ::: "memory");   // Q done
    __syncthreads();

    const int lr16 = lane & 15;
    const int hi16 = lane >> 4;
    uint32_t qf[4][4];
    #pragma unroll
    for (int ks = 0; ks < 4; ks++)
        ldsm4(qf[ks], sb + (uint32_t)(wid * 16 + lr16) * AROW + ks * 32 + hi16 * 16);

    float oacc[8][4];
    #pragma unroll
    for (int j = 0; j < 8; j++)
        #pragma unroll
        for (int e = 0; e < 4; e++) oacc[j][e] = 0.f;
    float m0 = -1e30f, m1 = -1e30f, l0 = 0.f, l1 = 0.f;
    const int lrB = (lane & 7) + (lane >> 4) * 8;
    const int lcB = ((lane >> 3) & 1) * 16;

    for (int kt = ktLo; kt <= ktHi; kt++) {
        int s = (kt - ktLo) & 1;
        uint32_t st = sb + GA_TILE + s * GA_STG;
        if (kt < ktHi) {
            at_load_kv(qH, b, h, kt + 1, tid, sb + GA_TILE + (s ^ 1) * GA_STG);
            asm volatile("cp.async.wait_group 1;" ::: "memory");
        } else {
            asm volatile("cp.async.wait_group 0;" ::: "memory");
        }
        __syncthreads();

        // S = Q K^T (single-pass fp16; result already in log2 domain)
        float sacc[8][4];
        #pragma unroll
        for (int j = 0; j < 8; j++)
            #pragma unroll
            for (int e = 0; e < 4; e++) sacc[j][e] = 0.f;

        #pragma unroll
        for (int ks = 0; ks < 4; ks++) {
            uint32_t kf[4][4];
            #pragma unroll
            for (int n2 = 0; n2 < 4; n2++)
                ldsm4(kf[n2], st + (uint32_t)(n2 * 16 + lrB) * AROW + ks * 32 + lcB);
            #pragma unroll
            for (int j = 0; j < 8; j++)
                mma16816(sacc[j], qf[ks], &kf[j >> 1][(j & 1) * 2]);
        }

        // causal mask on diagonal tile (local attention)
        if (local && kt == ktHi) {
            int r0 = wid * 16 + (lane >> 2);
            #pragma unroll
            for (int j = 0; j < 8; j++) {
                int c = j * 8 + (lane & 3) * 2;
                if (c     > r0)     sacc[j][0] = -1e30f;
                if (c + 1 > r0)     sacc[j][1] = -1e30f;
                if (c     > r0 + 8) sacc[j][2] = -1e30f;
                if (c + 1 > r0 + 8) sacc[j][3] = -1e30f;
            }
        }

        // online softmax in log2 domain (rows r0 and r0+8)
        float t0 = -1e30f, t1 = -1e30f;
        #pragma unroll
        for (int j = 0; j < 8; j++) {
            t0 = fmaxf(t0, fmaxf(sacc[j][0], sacc[j][1]));
            t1 = fmaxf(t1, fmaxf(sacc[j][2], sacc[j][3]));
        }
        t0 = fmaxf(t0, __shfl_xor_sync(0xffffffffu, t0, 1));
        t0 = fmaxf(t0, __shfl_xor_sync(0xffffffffu, t0, 2));
        t1 = fmaxf(t1, __shfl_xor_sync(0xffffffffu, t1, 1));
        t1 = fmaxf(t1, __shfl_xor_sync(0xffffffffu, t1, 2));
        float mn0 = fmaxf(m0, t0), mn1 = fmaxf(m1, t1);
        float c0 = ex2(m0 - mn0), c1 = ex2(m1 - mn1);
        float s0 = 0.f, s1 = 0.f;
        #pragma unroll
        for (int j = 0; j < 8; j++) {
            sacc[j][0] = ex2(sacc[j][0] - mn0);
            sacc[j][1] = ex2(sacc[j][1] - mn0);
            sacc[j][2] = ex2(sacc[j][2] - mn1);
            sacc[j][3] = ex2(sacc[j][3] - mn1);
            s0 += sacc[j][0] + sacc[j][1];
            s1 += sacc[j][2] + sacc[j][3];
        }
        s0 += __shfl_xor_sync(0xffffffffu, s0, 1);
        s0 += __shfl_xor_sync(0xffffffffu, s0, 2);
        s1 += __shfl_xor_sync(0xffffffffu, s1, 1);
        s1 += __shfl_xor_sync(0xffffffffu, s1, 2);
        l0 = l0 * c0 + s0;
        l1 = l1 * c1 + s1;
        m0 = mn0; m1 = mn1;
        #pragma unroll
        for (int j = 0; j < 8; j++) {
            oacc[j][0] *= c0; oacc[j][1] *= c0;
            oacc[j][2] *= c1; oacc[j][3] *= c1;
        }

        // O += P V
        #pragma unroll
        for (int kp = 0; kp < 4; kp++) {
            uint32_t pf[4];
            pf[0] = packh2(sacc[2*kp][0],   sacc[2*kp][1]);
            pf[1] = packh2(sacc[2*kp][2],   sacc[2*kp][3]);
            pf[2] = packh2(sacc[2*kp+1][0], sacc[2*kp+1][1]);
            pf[3] = packh2(sacc[2*kp+1][2], sacc[2*kp+1][3]);
            uint32_t vf[4][4];
            #pragma unroll
            for (int n2 = 0; n2 < 4; n2++)
                ldsm4t(vf[n2], st + GA_TILE + (uint32_t)(kp * 16 + lr16) * AROW + n2 * 32 + hi16 * 16);
            #pragma unroll
            for (int j = 0; j < 8; j++)
                mma16816(oacc[j], pf, &vf[j >> 1][(j & 1) * 2]);
        }
        __syncthreads();
    }

    // epilogue: normalize, write fp16
    float il0 = 1.f / l0, il1 = 1.f / l1;
    int r0g = b * SS + qt * 64 + wid * 16 + (lane >> 2);
    size_t o0 = (size_t)r0g * DD + h * DHH;
    size_t o1 = o0 + (size_t)8 * DD;
    #pragma unroll
    for (int j = 0; j < 8; j++) {
        int col = j * 8 + (lane & 3) * 2;
        *(__half2*)(oH + o0 + col) = __floats2half2_rn(oacc[j][0] * il0, oacc[j][1] * il0);
        *(__half2*)(oH + o1 + col) = __floats2half2_rn(oacc[j][2] * il1, oacc[j][3] * il1);
    }
}

// ---------------- LayerNorm (fp32 out optional, fp16 out optional) ----------------
__global__ __launch_bounds__(128) void ln_kernel(
    const float* __restrict__ X, const float* __restrict__ R,
    const float* __restrict__ gam, const float* __restrict__ bet,
    float* __restrict__ out, __half* __restrict__ outH)
{
    __shared__ float red[8];
    const int row = blockIdx.x;
    const int tid = threadIdx.x;
    float4 v = ((const float4*)(X + (size_t)row * DD))[tid];
    if (R) {
        float4 r = ((const float4*)(R + (size_t)row * DD))[tid];
        v.x += r.x; v.y += r.y; v.z += r.z; v.w += r.w;
    }
    float s  = v.x + v.y + v.z + v.w;
    float sq = v.x*v.x + v.y*v.y + v.z*v.z + v.w*v.w;
    #pragma unroll
    for (int o = 16; o; o >>= 1) {
        s  += __shfl_xor_sync(0xffffffffu, s,  o);
        sq += __shfl_xor_sync(0xffffffffu, sq, o);
    }
    int w = tid >> 5;
    if ((tid & 31) == 0) { red[w*2] = s; red[w*2+1] = sq; }
    __syncthreads();
    s  = red[0] + red[2] + red[4] + red[6];
    sq = red[1] + red[3] + red[5] + red[7];
    float mean = s * (1.f / DD);
    float var  = sq * (1.f / DD) - mean * mean;
    float inv  = rsqrtf(var + 1e-5f);
    float4 gg = ((const float4*)gam)[tid];
    float4 bb = ((const float4*)bet)[tid];
    float4 r;
    r.x = (v.x - mean) * inv * gg.x + bb.x;
    r.y = (v.y - mean) * inv * gg.y + bb.y;
    r.z = (v.z - mean) * inv * gg.z + bb.z;
    r.w = (v.w - mean) * inv * gg.w + bb.w;
    if (out) ((float4*)(out + (size_t)row * DD))[tid] = r;
    if (outH) {
        size_t o = (size_t)row * DD + tid * 4;
        *(__half2*)(outH + o)     = __floats2half2_rn(r.x, r.y);
        *(__half2*)(outH + o + 2) = __floats2half2_rn(r.z, r.w);
    }
}

// ---------------- RoPE: in-place fp16 rotation of q,k; q scaled by QSCALE ----------------
__global__ __launch_bounds__(256) void rope_h(__half* __restrict__ H)
{
    const int row = blockIdx.x;
    const int pos = row & (SS - 1);
    const int t = threadIdx.x;
    const int h = t >> 5;
    const int f = t & 31;
    float inv_freq = powf(10000.f, -(float)f * (1.f / 32.f));
    float fr = (float)pos * inv_freq;
    float c, sn;
    sincosf(fr, &sn, &c);
    size_t base = (size_t)row * TDD + h * DHH + f;

    // q (fold attention scale incl. log2e)
    float x1 = __half2float(H[base]), x2 = __half2float(H[base + 32]);
    H[base]      = __float2half_rn((x1 * c - x2 * sn) * QSCALE);
    H[base + 32] = __float2half_rn((x2 * c + x1 * sn) * QSCALE);
    // k
    x1 = __half2float(H[base + DD]); x2 = __half2float(H[base + DD + 32]);
    H[base + DD]      = __float2half_rn(x1 * c - x2 * sn);
    H[base + DD + 32] = __float2half_rn(x2 * c + x1 * sn);
    // v untouched (already written by GEMM)
}

// ---------------- launch ----------------
extern "C" void kernel_launch(void* const* d_in, const int* in_sizes, int n_in,
                              void* d_out, int out_size)
{
    (void)in_sizes; (void)n_in; (void)out_size;
    const float* src        = (const float*)d_in[0];
    const float* in_proj_b  = (const float*)d_in[2];
    const float* out_proj_b = (const float*)d_in[4];
    const float* ln_g       = (const float*)d_in[5];
    const float* ln_b       = (const float*)d_in[6];
    const float* gl_b       = (const float*)d_in[10];
    const float* norm1_g    = (const float*)d_in[11];
    const float* norm1_b    = (const float*)d_in[12];
    const float* lin1_b     = (const float*)d_in[14];
    const float* lin2_b     = (const float*)d_in[16];
    const float* norm2_g    = (const float*)d_in[17];
    const float* norm2_b    = (const float*)d_in[18];
    float* outp = (float*)d_out;

    cudaFuncSetAttribute(mm_tc, cudaFuncAttributeMaxDynamicSharedMemorySize, MM_SMEM);
    cudaFuncSetAttribute(attn_tc, cudaFuncAttributeMaxDynamicSharedMemorySize, GA_SMEM);

    float *p_src2, *p_h1, *p_ff2;
    cudaGetSymbolAddress((void**)&p_src2, g_src2);
    cudaGetSymbolAddress((void**)&p_h1,   g_h1);
    cudaGetSymbolAddress((void**)&p_ff2,  g_ff2);

    __half *srcH,*qkvH,*qklH,*goH,*xH,*loH,*catH,*h1H,*ff1H;
    __half *w1H,*w2H,*w3H,*w4H,*w5H,*w6H,*w7H;
    cudaGetSymbolAddress((void**)&srcH, c_src_h);
    cudaGetSymbolAddress((void**)&qkvH, c_qkv_h);
    cudaGetSymbolAddress((void**)&qklH, c_qkl_h);
    cudaGetSymbolAddress((void**)&goH,  c_go_h);
    cudaGetSymbolAddress((void**)&xH,   c_x_h);
    cudaGetSymbolAddress((void**)&loH,  c_lo_h);
    cudaGetSymbolAddress((void**)&catH, c_cat_h);
    cudaGetSymbolAddress((void**)&h1H,  c_h1_h);
    cudaGetSymbolAddress((void**)&ff1H, c_ff1_h);
    cudaGetSymbolAddress((void**)&w1H, c_w1_h);
    cudaGetSymbolAddress((void**)&w2H, c_w2_h);
    cudaGetSymbolAddress((void**)&w3H, c_w3_h);
    cudaGetSymbolAddress((void**)&w4H, c_w4_h);
    cudaGetSymbolAddress((void**)&w5H, c_w5_h);
    cudaGetSymbolAddress((void**)&w6H, c_w6_h);
    cudaGetSymbolAddress((void**)&w7H, c_w7_h);

    // weight conversions, one launch
    {
        W7 jobs;
        const float* ws[7] = {(const float*)d_in[1], (const float*)d_in[3],
                              (const float*)d_in[7], (const float*)d_in[8],
                              (const float*)d_in[9], (const float*)d_in[13],
                              (const float*)d_in[15]};
        __half* wd[7] = {w1H, w2H, w3H, w4H, w5H, w6H, w7H};
        int sz[7] = {TDD*DD, DD*DD, TDD*DD, DD*DD, DD*2*DD, FFD*DD, DD*FFD};
        int cum = 0;
        for (int j = 0; j < 7; j++) {
            jobs.s[j] = ws[j]; jobs.d[j] = wd[j];
            jobs.cum[j] = cum; cum += sz[j] / 4;
        }
        jobs.cum[7] = cum;
        cvt_w7<<<(cum + 255) / 256, 256>>>(jobs);
    }
    cvt_h<<<(NROWS*DD/4 + 255) / 256, 256>>>(src, srcH, NROWS*DD/4);

    // 1. qkv = src @ in_proj_w^T + b -> fp16, q columns pre-scaled
    mm_tc<<<dim3(TDD/128, NROWS/128), 256, MM_SMEM>>>(srcH, w1H,
        nullptr, in_proj_b, DD, TDD, 0, 0, qkvH, QSCALE, DD);
    // 2. global attention -> goH
    attn_tc<<<dim3(SS/64, HH, BB), 128, GA_SMEM>>>(qkvH, goH, 0);
    // 3. go2 = go @ out_proj_w^T + b -> cat[:, 0:512]
    mm_tc<<<dim3(DD/128, NROWS/128), 256, MM_SMEM>>>(goH, w2H,
        nullptr, out_proj_b, DD, 2*DD, 0, 0, catH, 1.f, 0);
    // 4. x = LN(src) -> fp16
    ln_kernel<<<NROWS, 128>>>(src, nullptr, ln_g, ln_b, nullptr, xH);
    // 5. qkl = x @ qkv_w^T -> fp16 only
    mm_tc<<<dim3(TDD/128, NROWS/128), 256, MM_SMEM>>>(xH, w3H,
        nullptr, nullptr, DD, TDD, 0, 0, qklH, 1.f, 0);
    // 6. rope in place on qklH (q scaled)
    rope_h<<<NROWS, 256>>>(qklH);
    // 7. local windowed attention -> loH
    attn_tc<<<dim3(SS/64, HH, BB), 128, GA_SMEM>>>(qklH, loH, 1);
    // 8. lo2 = lo @ to_out_w^T -> cat[:, 512:1024]
    mm_tc<<<dim3(DD/128, NROWS/128), 256, MM_SMEM>>>(loH, w4H,
        nullptr, nullptr, DD, 2*DD, DD, 0, catH, 1.f, 0);
    // 9. src2 = cat @ gl_w^T + gl_b -> fp32
    mm_tc<<<dim3(DD/128, NROWS/128), 256, MM_SMEM>>>(catH, w5H,
        p_src2, gl_b, 2*DD, DD, 0, 0, nullptr, 1.f, 0);
    // 10. h1 = LN(src + src2) -> fp32 + fp16
    ln_kernel<<<NROWS, 128>>>(p_src2, src, norm1_g, norm1_b, p_h1, h1H);
    // 11. ff1 = relu(h1 @ lin1_w^T + b) -> fp16
    mm_tc<<<dim3(FFD/128, NROWS/128), 256, MM_SMEM>>>(h1H, w6H,
        nullptr, lin1_b, DD, FFD, 0, 1, ff1H, 1.f, 0);
    // 12. ff2 = ff1 @ lin2_w^T + b -> fp32
    mm_tc<<<dim3(DD/128, NROWS/128), 256, MM_SMEM>>>(ff1H, w7H,
        p_ff2, lin2_b, FFD, DD, 0, 0, nullptr, 1.f, 0);
    // 13. out = LN(h1 + ff2)
    ln_kernel<<<NROWS, 128>>>(p_ff2, p_h1, norm2_g, norm2_b, outp, nullptr);
}

// round 17
// speedup vs baseline: 7.3239x; 1.0323x over previous
#include <cuda_runtime.h>
#include <cuda_fp16.h>
#include <cstdint>

// ---------------- constants ----------------
#define BB 4
#define SS 2048
#define DD 512
#define HH 8
#define DHH 64
#define WW 128
#define NWIN 16
#define FFD 2048
#define TDD 1536   // 3*D
#define NROWS (BB*SS)   // 8192
#define QSCALE 0.18033688f   // 0.125 * log2(e)

// ---------------- fp32 scratch ----------------
__device__ float g_src2[NROWS * DD];
__device__ float g_h1  [NROWS * DD];
__device__ float g_ff2 [NROWS * DD];

// ---------------- fp16 buffers ----------------
__device__ __half c_src_h[NROWS*DD];
__device__ __half c_qkv_h[NROWS*TDD];
__device__ __half c_qkl_h[NROWS*TDD];
__device__ __half c_go_h [NROWS*DD];
__device__ __half c_x_h  [NROWS*DD];
__device__ __half c_lo_h [NROWS*DD];
__device__ __half c_cat_h[NROWS*2*DD];
__device__ __half c_h1_h [NROWS*DD];
__device__ __half c_ff1_h[NROWS*FFD];
__device__ __half c_w1_h[TDD*DD];
__device__ __half c_w2_h[DD*DD];
__device__ __half c_w3_h[TDD*DD];
__device__ __half c_w4_h[DD*DD];
__device__ __half c_w5_h[DD*2*DD];
__device__ __half c_w6_h[FFD*DD];
__device__ __half c_w7_h[DD*FFD];

// ---------------- helpers ----------------
__device__ __forceinline__ uint32_t smem_u32(const void* p) {
    uint32_t a;
    asm("{ .reg .u64 t; cvta.to.shared.u64 t, %1; cvt.u32.u64 %0, t; }" : "=r"(a) : "l"(p));
    return a;
}

__device__ __forceinline__ void ldsm4(uint32_t* r, uint32_t a) {
    asm volatile("ldmatrix.sync.aligned.m8n8.x4.shared.b16 {%0,%1,%2,%3}, [%4];"
                 : "=r"(r[0]), "=r"(r[1]), "=r"(r[2]), "=r"(r[3]) : "r"(a));
}

__device__ __forceinline__ void ldsm4t(uint32_t* r, uint32_t a) {
    asm volatile("ldmatrix.sync.aligned.m8n8.x4.trans.shared.b16 {%0,%1,%2,%3}, [%4];"
                 : "=r"(r[0]), "=r"(r[1]), "=r"(r[2]), "=r"(r[3]) : "r"(a));
}

__device__ __forceinline__ void mma16816(float* d, const uint32_t* a, const uint32_t* b) {
    asm volatile(
        "mma.sync.aligned.m16n8k16.row.col.f32.f16.f16.f32 "
        "{%0,%1,%2,%3}, {%4,%5,%6,%7}, {%8,%9}, {%0,%1,%2,%3};"
        : "+f"(d[0]), "+f"(d[1]), "+f"(d[2]), "+f"(d[3])
        : "r"(a[0]), "r"(a[1]), "r"(a[2]), "r"(a[3]), "r"(b[0]), "r"(b[1]));
}

__device__ __forceinline__ uint32_t packh2(float a, float b) {
    __half2 t = __floats2half2_rn(a, b);
    return *(uint32_t*)&t;
}

__device__ __forceinline__ float ex2(float x) {
    float y;
    asm("ex2.approx.ftz.f32 %0, %1;" : "=f"(y) : "f"(x));
    return y;
}

// ---------------- conversions ----------------
__global__ __launch_bounds__(256) void cvt_h(
    const float* __restrict__ X, __half* __restrict__ hi, int n4)
{
    int i = blockIdx.x * 256 + threadIdx.x;
    if (i >= n4) return;
    float4 v = ((const float4*)X)[i];
    ((__half2*)hi)[2*i]   = __floats2half2_rn(v.x, v.y);
    ((__half2*)hi)[2*i+1] = __floats2half2_rn(v.z, v.w);
}

struct W7 {
    const float* s[7];
    __half* d[7];
    int cum[8];
};

__global__ __launch_bounds__(256) void cvt_w7(W7 jobs)
{
    int i = blockIdx.x * 256 + threadIdx.x;
    if (i >= jobs.cum[7]) return;
    int j = 0;
    #pragma unroll
    for (int t = 1; t < 7; t++) if (i >= jobs.cum[t]) j = t;
    int li = i - jobs.cum[j];
    float4 v = ((const float4*)jobs.s[j])[li];
    ((__half2*)jobs.d[j])[2*li]   = __floats2half2_rn(v.x, v.y);
    ((__half2*)jobs.d[j])[2*li+1] = __floats2half2_rn(v.z, v.w);
}

// ---------------- mma.sync GEMM: C = A(MxK) * B(NxK)^T  (fp16, 64x64 warp tile, 3-stage) ----------------
#define KC 32
#define ROWB 80
#define TILEB (128*ROWB)
#define STG (2*TILEB)
#define MM_SMEM (3*STG)

__device__ __forceinline__ void mm_load_chunk(
    const __half* __restrict__ Ah, const __half* __restrict__ Bh,
    int K, int rowBase, int colBase, int tid, int c, uint32_t stageBase)
{
    const __half* mats[2] = {Ah, Bh};
    #pragma unroll
    for (int it = 0; it < 8; it++) {
        int idx = tid + it * 128;         // 0..1023
        int t = idx >> 9;                 // matrix
        int rem = idx & 511;
        int r = rem >> 2;                 // row 0..127
        int ch = rem & 3;                 // 16B chunk
        int rb = (t == 0) ? rowBase : colBase;
        const void* g = mats[t] + (size_t)(rb + r) * K + c * KC + ch * 8;
        uint32_t d = stageBase + t * TILEB + r * ROWB + ch * 16;
        asm volatile("cp.async.cg.shared.global [%0], [%1], 16;" :: "r"(d), "l"(g));
    }
    asm volatile("cp.async.commit_group;" ::: "memory");
}

__global__ __launch_bounds__(128, 2) void mm_tc(
    const __half* __restrict__ Ah, const __half* __restrict__ Bh,
    float* __restrict__ C, const float* __restrict__ bias,
    int K, int ldc, int colOff, int relu,
    __half* __restrict__ Ch, float qscale, int qlim)
{
    extern __shared__ char mm_smem[];
    const int tid = threadIdx.x;
    const int wid = tid >> 5, lane = tid & 31;
    const int wm = wid >> 1, wn = wid & 1;     // warp tile 64x64
    const int rowBase = blockIdx.y * 128;
    const int colBase = blockIdx.x * 128;
    const uint32_t sb = smem_u32(mm_smem);

    const int lrA = (lane & 15);
    const int lcA = (lane >> 4) * 16;
    const int lrB = (lane & 7) + (lane >> 4) * 8;
    const int lcB = ((lane >> 3) & 1) * 16;

    float acc[4][8][4];
    #pragma unroll
    for (int i = 0; i < 4; i++)
        #pragma unroll
        for (int j = 0; j < 8; j++)
            #pragma unroll
            for (int e = 0; e < 4; e++) acc[i][j][e] = 0.f;

    const int CC = K / KC;
    mm_load_chunk(Ah, Bh, K, rowBase, colBase, tid, 0, sb);
    mm_load_chunk(Ah, Bh, K, rowBase, colBase, tid, 1, sb + STG);

    for (int c = 0; c < CC; c++) {
        if (c + 1 < CC) {
            asm volatile("cp.async.wait_group 1;" ::: "memory");
        } else {
            asm volatile("cp.async.wait_group 0;" ::: "memory");
        }
        __syncthreads();
        if (c + 2 < CC)
            mm_load_chunk(Ah, Bh, K, rowBase, colBase, tid, c + 2,
                          sb + (uint32_t)((c + 2) % 3) * STG);

        uint32_t base = sb + (uint32_t)(c % 3) * STG;
        #pragma unroll
        for (int ks = 0; ks < 2; ks++) {
            uint32_t bf[8][2];
            #pragma unroll
            for (int j2 = 0; j2 < 4; j2++) {
                uint32_t r4[4];
                ldsm4(r4, base + TILEB + (uint32_t)(wn * 64 + j2 * 16 + lrB) * ROWB + ks * 32 + lcB);
                bf[2*j2][0]   = r4[0]; bf[2*j2][1]   = r4[1];
                bf[2*j2+1][0] = r4[2]; bf[2*j2+1][1] = r4[3];
            }
            #pragma unroll
            for (int i = 0; i < 4; i++) {
                uint32_t af[4];
                ldsm4(af, base + (uint32_t)(wm * 64 + i * 16 + lrA) * ROWB + ks * 32 + lcA);
                #pragma unroll
                for (int j = 0; j < 8; j++)
                    mma16816(acc[i][j], af, bf[j]);
            }
        }
    }

    // epilogue
    #pragma unroll
    for (int i = 0; i < 4; i++) {
        int row0 = rowBase + wm * 64 + i * 16 + (lane >> 2);
        #pragma unroll
        for (int j = 0; j < 8; j++) {
            int col = colBase + wn * 64 + j * 8 + (lane & 3) * 2;
            float b0 = 0.f, b1 = 0.f;
            if (bias) { b0 = bias[col]; b1 = bias[col + 1]; }
            float2 v0 = make_float2(acc[i][j][0] + b0, acc[i][j][1] + b1);
            float2 v1 = make_float2(acc[i][j][2] + b0, acc[i][j][3] + b1);
            if (relu) {
                v0.x = fmaxf(v0.x, 0.f); v0.y = fmaxf(v0.y, 0.f);
                v1.x = fmaxf(v1.x, 0.f); v1.y = fmaxf(v1.y, 0.f);
            }
            if (col < qlim) {
                v0.x *= qscale; v0.y *= qscale;
                v1.x *= qscale; v1.y *= qscale;
            }
            size_t o0 = (size_t)row0 * ldc + colOff + col;
            size_t o1 = (size_t)(row0 + 8) * ldc + colOff + col;
            if (C) {
                *(float2*)(C + o0) = v0;
                *(float2*)(C + o1) = v1;
            }
            if (Ch) {
                *(__half2*)(Ch + o0) = __floats2half2_rn(v0.x, v0.y);
                *(__half2*)(Ch + o1) = __floats2half2_rn(v1.x, v1.y);
            }
        }
    }
}

// ---------------- tensor-core flash attention (global + local windowed) ----------------
// CTA: 4 warps; Q tile 128 rows (warp = 32 rows, 2 subtiles), K tiles of 64, DH=64.
// Q pre-scaled by 0.125*log2e at the producer; softmax in log2 domain via ex2.
#define AROW 144
#define AT_QTILE (128*AROW)          // 18432
#define AT_KTILE (64*AROW)           // 9216
#define AT_STG (2*AT_KTILE)          // K + V
#define GA_SMEM (AT_QTILE + 2*AT_STG)

__device__ __forceinline__ void at_load_kv(
    const __half* __restrict__ qH, int b, int h, int kt, int tid, uint32_t stBase)
{
    #pragma unroll
    for (int m = 0; m < 2; m++) {
        int col = ((m == 0) ? DD : 2 * DD) + h * DHH;
        #pragma unroll
        for (int i = 0; i < 4; i++) {
            int idx = tid + i * 128;           // 0..511 = 64 rows x 8 chunks
            int r = idx >> 3, ch = idx & 7;
            const void* g = qH + (size_t)(b * SS + kt * 64 + r) * TDD + col + ch * 8;
            uint32_t d = stBase + m * AT_KTILE + r * AROW + ch * 16;
            asm volatile("cp.async.cg.shared.global [%0], [%1], 16;" :: "r"(d), "l"(g));
        }
    }
    asm volatile("cp.async.commit_group;" ::: "memory");
}

__global__ __launch_bounds__(128, 2) void attn_tc(
    const __half* __restrict__ qH, __half* __restrict__ oH, int local)
{
    extern __shared__ char ga_smem[];
    const int tid = threadIdx.x, wid = tid >> 5, lane = tid & 31;
    const int qt = blockIdx.x, h = blockIdx.y, b = blockIdx.z;  // qt = 128-row block
    const uint32_t sb = smem_u32(ga_smem);

    int ktLo = 0, ktHi = SS / 64 - 1;
    if (local) {
        ktLo = 2 * qt - 2;
        if (ktLo < 0) ktLo = 0;
        ktHi = 2 * qt + 1;
    }

    // Q load (group 0): 128 rows x 128B
    #pragma unroll
    for (int i = 0; i < 8; i++) {
        int idx = tid + i * 128;          // 0..1023
        int r = idx >> 3, ch = idx & 7;
        const void* g = qH + (size_t)(b * SS + qt * 128 + r) * TDD + h * DHH + ch * 8;
        uint32_t d = sb + r * AROW + ch * 16;
        asm volatile("cp.async.cg.shared.global [%0], [%1], 16;" :: "r"(d), "l"(g));
    }
    asm volatile("cp.async.commit_group;" ::: "memory");
    at_load_kv(qH, b, h, ktLo, tid, sb + AT_QTILE);

    asm volatile("cp.async.wait_group 1;" ::: "memory");   // Q done
    __syncthreads();

    const int lr16 = lane & 15;
    const int hi16 = lane >> 4;
    uint32_t qf[2][4][4];
    #pragma unroll
    for (int i = 0; i < 2; i++)
        #pragma unroll
        for (int ks = 0; ks < 4; ks++)
            ldsm4(qf[i][ks], sb + (uint32_t)(wid * 32 + i * 16 + lr16) * AROW + ks * 32 + hi16 * 16);

    float oacc[2][8][4];
    #pragma unroll
    for (int i = 0; i < 2; i++)
        #pragma unroll
        for (int j = 0; j < 8; j++)
            #pragma unroll
            for (int e = 0; e < 4; e++) oacc[i][j][e] = 0.f;
    float mrow[2][2] = {{-1e30f, -1e30f}, {-1e30f, -1e30f}};
    float lrow[2][2] = {{0.f, 0.f}, {0.f, 0.f}};
    const int lrB = (lane & 7) + (lane >> 4) * 8;
    const int lcB = ((lane >> 3) & 1) * 16;

    for (int kt = ktLo; kt <= ktHi; kt++) {
        int s = (kt - ktLo) & 1;
        uint32_t st = sb + AT_QTILE + s * AT_STG;
        if (kt < ktHi) {
            at_load_kv(qH, b, h, kt + 1, tid, sb + AT_QTILE + (s ^ 1) * AT_STG);
            asm volatile("cp.async.wait_group 1;" ::: "memory");
        } else {
            asm volatile("cp.async.wait_group 0;" ::: "memory");
        }
        __syncthreads();

        // S = Q K^T (log2 domain)
        float sacc[2][8][4];
        #pragma unroll
        for (int i = 0; i < 2; i++)
            #pragma unroll
            for (int j = 0; j < 8; j++)
                #pragma unroll
                for (int e = 0; e < 4; e++) sacc[i][j][e] = 0.f;

        #pragma unroll
        for (int ks = 0; ks < 4; ks++) {
            uint32_t kf[4][4];
            #pragma unroll
            for (int n2 = 0; n2 < 4; n2++)
                ldsm4(kf[n2], st + (uint32_t)(n2 * 16 + lrB) * AROW + ks * 32 + lcB);
            #pragma unroll
            for (int i = 0; i < 2; i++)
                #pragma unroll
                for (int j = 0; j < 8; j++)
                    mma16816(sacc[i][j], qf[i][ks], &kf[j >> 1][(j & 1) * 2]);
        }

        // causal mask (local attention, current-window key tiles)
        if (local && kt >= 2 * qt) {
            int coff = (kt - 2 * qt) * 64;
            #pragma unroll
            for (int i = 0; i < 2; i++) {
                int r0 = wid * 32 + i * 16 + (lane >> 2);
                #pragma unroll
                for (int j = 0; j < 8; j++) {
                    int c = j * 8 + (lane & 3) * 2 + coff;
                    if (c     > r0)     sacc[i][j][0] = -1e30f;
                    if (c + 1 > r0)     sacc[i][j][1] = -1e30f;
                    if (c     > r0 + 8) sacc[i][j][2] = -1e30f;
                    if (c + 1 > r0 + 8) sacc[i][j][3] = -1e30f;
                }
            }
        }

        // online softmax (log2 domain), per row subtile
        #pragma unroll
        for (int i = 0; i < 2; i++) {
            float t0 = -1e30f, t1 = -1e30f;
            #pragma unroll
            for (int j = 0; j < 8; j++) {
                t0 = fmaxf(t0, fmaxf(sacc[i][j][0], sacc[i][j][1]));
                t1 = fmaxf(t1, fmaxf(sacc[i][j][2], sacc[i][j][3]));
            }
            t0 = fmaxf(t0, __shfl_xor_sync(0xffffffffu, t0, 1));
            t0 = fmaxf(t0, __shfl_xor_sync(0xffffffffu, t0, 2));
            t1 = fmaxf(t1, __shfl_xor_sync(0xffffffffu, t1, 1));
            t1 = fmaxf(t1, __shfl_xor_sync(0xffffffffu, t1, 2));
            float mn0 = fmaxf(mrow[i][0], t0), mn1 = fmaxf(mrow[i][1], t1);
            float c0 = ex2(mrow[i][0] - mn0), c1 = ex2(mrow[i][1] - mn1);
            float s0 = 0.f, s1 = 0.f;
            #pragma unroll
            for (int j = 0; j < 8; j++) {
                sacc[i][j][0] = ex2(sacc[i][j][0] - mn0);
                sacc[i][j][1] = ex2(sacc[i][j][1] - mn0);
                sacc[i][j][2] = ex2(sacc[i][j][2] - mn1);
                sacc[i][j][3] = ex2(sacc[i][j][3] - mn1);
                s0 += sacc[i][j][0] + sacc[i][j][1];
                s1 += sacc[i][j][2] + sacc[i][j][3];
            }
            s0 += __shfl_xor_sync(0xffffffffu, s0, 1);
            s0 += __shfl_xor_sync(0xffffffffu, s0, 2);
            s1 += __shfl_xor_sync(0xffffffffu, s1, 1);
            s1 += __shfl_xor_sync(0xffffffffu, s1, 2);
            lrow[i][0] = lrow[i][0] * c0 + s0;
            lrow[i][1] = lrow[i][1] * c1 + s1;
            mrow[i][0] = mn0; mrow[i][1] = mn1;
            #pragma unroll
            for (int j = 0; j < 8; j++) {
                oacc[i][j][0] *= c0; oacc[i][j][1] *= c0;
                oacc[i][j][2] *= c1; oacc[i][j][3] *= c1;
            }
        }

        // O += P V  (V fragments shared across both row subtiles)
        #pragma unroll
        for (int kp = 0; kp < 4; kp++) {
            uint32_t vf[4][4];
            #pragma unroll
            for (int n2 = 0; n2 < 4; n2++)
                ldsm4t(vf[n2], st + AT_KTILE + (uint32_t)(kp * 16 + lr16) * AROW + n2 * 32 + hi16 * 16);
            #pragma unroll
            for (int i = 0; i < 2; i++) {
                uint32_t pf[4];
                pf[0] = packh2(sacc[i][2*kp][0],   sacc[i][2*kp][1]);
                pf[1] = packh2(sacc[i][2*kp][2],   sacc[i][2*kp][3]);
                pf[2] = packh2(sacc[i][2*kp+1][0], sacc[i][2*kp+1][1]);
                pf[3] = packh2(sacc[i][2*kp+1][2], sacc[i][2*kp+1][3]);
                #pragma unroll
                for (int j = 0; j < 8; j++)
                    mma16816(oacc[i][j], pf, &vf[j >> 1][(j & 1) * 2]);
            }
        }
        __syncthreads();
    }

    // epilogue: normalize, write fp16
    #pragma unroll
    for (int i = 0; i < 2; i++) {
        float il0 = 1.f / lrow[i][0], il1 = 1.f / lrow[i][1];
        int r0g = b * SS + qt * 128 + wid * 32 + i * 16 + (lane >> 2);
        size_t o0 = (size_t)r0g * DD + h * DHH;
        size_t o1 = o0 + (size_t)8 * DD;
        #pragma unroll
        for (int j = 0; j < 8; j++) {
            int col = j * 8 + (lane & 3) * 2;
            *(__half2*)(oH + o0 + col) = __floats2half2_rn(oacc[i][j][0] * il0, oacc[i][j][1] * il0);
            *(__half2*)(oH + o1 + col) = __floats2half2_rn(oacc[i][j][2] * il1, oacc[i][j][3] * il1);
        }
    }
}

// ---------------- LayerNorm (fp32 out optional, fp16 out optional) ----------------
__global__ __launch_bounds__(128) void ln_kernel(
    const float* __restrict__ X, const float* __restrict__ R,
    const float* __restrict__ gam, const float* __restrict__ bet,
    float* __restrict__ out, __half* __restrict__ outH)
{
    __shared__ float red[8];
    const int row = blockIdx.x;
    const int tid = threadIdx.x;
    float4 v = ((const float4*)(X + (size_t)row * DD))[tid];
    if (R) {
        float4 r = ((const float4*)(R + (size_t)row * DD))[tid];
        v.x += r.x; v.y += r.y; v.z += r.z; v.w += r.w;
    }
    float s  = v.x + v.y + v.z + v.w;
    float sq = v.x*v.x + v.y*v.y + v.z*v.z + v.w*v.w;
    #pragma unroll
    for (int o = 16; o; o >>= 1) {
        s  += __shfl_xor_sync(0xffffffffu, s,  o);
        sq += __shfl_xor_sync(0xffffffffu, sq, o);
    }
    int w = tid >> 5;
    if ((tid & 31) == 0) { red[w*2] = s; red[w*2+1] = sq; }
    __syncthreads();
    s  = red[0] + red[2] + red[4] + red[6];
    sq = red[1] + red[3] + red[5] + red[7];
    float mean = s * (1.f / DD);
    float var  = sq * (1.f / DD) - mean * mean;
    float inv  = rsqrtf(var + 1e-5f);
    float4 gg = ((const float4*)gam)[tid];
    float4 bb = ((const float4*)bet)[tid];
    float4 r;
    r.x = (v.x - mean) * inv * gg.x + bb.x;
    r.y = (v.y - mean) * inv * gg.y + bb.y;
    r.z = (v.z - mean) * inv * gg.z + bb.z;
    r.w = (v.w - mean) * inv * gg.w + bb.w;
    if (out) ((float4*)(out + (size_t)row * DD))[tid] = r;
    if (outH) {
        size_t o = (size_t)row * DD + tid * 4;
        *(__half2*)(outH + o)     = __floats2half2_rn(r.x, r.y);
        *(__half2*)(outH + o + 2) = __floats2half2_rn(r.z, r.w);
    }
}

// ---------------- RoPE: in-place fp16 rotation of q,k; q scaled by QSCALE ----------------
__global__ __launch_bounds__(256) void rope_h(__half* __restrict__ H)
{
    const int row = blockIdx.x;
    const int pos = row & (SS - 1);
    const int t = threadIdx.x;
    const int h = t >> 5;
    const int f = t & 31;
    float inv_freq = powf(10000.f, -(float)f * (1.f / 32.f));
    float fr = (float)pos * inv_freq;
    float c, sn;
    sincosf(fr, &sn, &c);
    size_t base = (size_t)row * TDD + h * DHH + f;

    float x1 = __half2float(H[base]), x2 = __half2float(H[base + 32]);
    H[base]      = __float2half_rn((x1 * c - x2 * sn) * QSCALE);
    H[base + 32] = __float2half_rn((x2 * c + x1 * sn) * QSCALE);
    x1 = __half2float(H[base + DD]); x2 = __half2float(H[base + DD + 32]);
    H[base + DD]      = __float2half_rn(x1 * c - x2 * sn);
    H[base + DD + 32] = __float2half_rn(x2 * c + x1 * sn);
}

// ---------------- launch ----------------
extern "C" void kernel_launch(void* const* d_in, const int* in_sizes, int n_in,
                              void* d_out, int out_size)
{
    (void)in_sizes; (void)n_in; (void)out_size;
    const float* src        = (const float*)d_in[0];
    const float* in_proj_b  = (const float*)d_in[2];
    const float* out_proj_b = (const float*)d_in[4];
    const float* ln_g       = (const float*)d_in[5];
    const float* ln_b       = (const float*)d_in[6];
    const float* gl_b       = (const float*)d_in[10];
    const float* norm1_g    = (const float*)d_in[11];
    const float* norm1_b    = (const float*)d_in[12];
    const float* lin1_b     = (const float*)d_in[14];
    const float* lin2_b     = (const float*)d_in[16];
    const float* norm2_g    = (const float*)d_in[17];
    const float* norm2_b    = (const float*)d_in[18];
    float* outp = (float*)d_out;

    cudaFuncSetAttribute(mm_tc, cudaFuncAttributeMaxDynamicSharedMemorySize, MM_SMEM);
    cudaFuncSetAttribute(attn_tc, cudaFuncAttributeMaxDynamicSharedMemorySize, GA_SMEM);

    float *p_src2, *p_h1, *p_ff2;
    cudaGetSymbolAddress((void**)&p_src2, g_src2);
    cudaGetSymbolAddress((void**)&p_h1,   g_h1);
    cudaGetSymbolAddress((void**)&p_ff2,  g_ff2);

    __half *srcH,*qkvH,*qklH,*goH,*xH,*loH,*catH,*h1H,*ff1H;
    __half *w1H,*w2H,*w3H,*w4H,*w5H,*w6H,*w7H;
    cudaGetSymbolAddress((void**)&srcH, c_src_h);
    cudaGetSymbolAddress((void**)&qkvH, c_qkv_h);
    cudaGetSymbolAddress((void**)&qklH, c_qkl_h);
    cudaGetSymbolAddress((void**)&goH,  c_go_h);
    cudaGetSymbolAddress((void**)&xH,   c_x_h);
    cudaGetSymbolAddress((void**)&loH,  c_lo_h);
    cudaGetSymbolAddress((void**)&catH, c_cat_h);
    cudaGetSymbolAddress((void**)&h1H,  c_h1_h);
    cudaGetSymbolAddress((void**)&ff1H, c_ff1_h);
    cudaGetSymbolAddress((void**)&w1H, c_w1_h);
    cudaGetSymbolAddress((void**)&w2H, c_w2_h);
    cudaGetSymbolAddress((void**)&w3H, c_w3_h);
    cudaGetSymbolAddress((void**)&w4H, c_w4_h);
    cudaGetSymbolAddress((void**)&w5H, c_w5_h);
    cudaGetSymbolAddress((void**)&w6H, c_w6_h);
    cudaGetSymbolAddress((void**)&w7H, c_w7_h);

    // weight conversions, one launch
    {
        W7 jobs;
        const float* ws[7] = {(const float*)d_in[1], (const float*)d_in[3],
                              (const float*)d_in[7], (const float*)d_in[8],
                              (const float*)d_in[9], (const float*)d_in[13],
                              (const float*)d_in[15]};
        __half* wd[7] = {w1H, w2H, w3H, w4H, w5H, w6H, w7H};
        int sz[7] = {TDD*DD, DD*DD, TDD*DD, DD*DD, DD*2*DD, FFD*DD, DD*FFD};
        int cum = 0;
        for (int j = 0; j < 7; j++) {
            jobs.s[j] = ws[j]; jobs.d[j] = wd[j];
            jobs.cum[j] = cum; cum += sz[j] / 4;
        }
        jobs.cum[7] = cum;
        cvt_w7<<<(cum + 255) / 256, 256>>>(jobs);
    }
    cvt_h<<<(NROWS*DD/4 + 255) / 256, 256>>>(src, srcH, NROWS*DD/4);

    // 1. qkv = src @ in_proj_w^T + b -> fp16, q columns pre-scaled
    mm_tc<<<dim3(TDD/128, NROWS/128), 128, MM_SMEM>>>(srcH, w1H,
        nullptr, in_proj_b, DD, TDD, 0, 0, qkvH, QSCALE, DD);
    // 2. global attention -> goH
    attn_tc<<<dim3(SS/128, HH, BB), 128, GA_SMEM>>>(qkvH, goH, 0);
    // 3. go2 = go @ out_proj_w^T + b -> cat[:, 0:512]
    mm_tc<<<dim3(DD/128, NROWS/128), 128, MM_SMEM>>>(goH, w2H,
        nullptr, out_proj_b, DD, 2*DD, 0, 0, catH, 1.f, 0);
    // 4. x = LN(src) -> fp16
    ln_kernel<<<NROWS, 128>>>(src, nullptr, ln_g, ln_b, nullptr, xH);
    // 5. qkl = x @ qkv_w^T -> fp16 only
    mm_tc<<<dim3(TDD/128, NROWS/128), 128, MM_SMEM>>>(xH, w3H,
        nullptr, nullptr, DD, TDD, 0, 0, qklH, 1.f, 0);
    // 6. rope in place on qklH (q scaled)
    rope_h<<<NROWS, 256>>>(qklH);
    // 7. local windowed attention -> loH
    attn_tc<<<dim3(SS/128, HH, BB), 128, GA_SMEM>>>(qklH, loH, 1);
    // 8. lo2 = lo @ to_out_w^T -> cat[:, 512:1024]
    mm_tc<<<dim3(DD/128, NROWS/128), 128, MM_SMEM>>>(loH, w4H,
        nullptr, nullptr, DD, 2*DD, DD, 0, catH, 1.f, 0);
    // 9. src2 = cat @ gl_w^T + gl_b -> fp32
    mm_tc<<<dim3(DD/128, NROWS/128), 128, MM_SMEM>>>(catH, w5H,
        p_src2, gl_b, 2*DD, DD, 0, 0, nullptr, 1.f, 0);
    // 10. h1 = LN(src + src2) -> fp32 + fp16
    ln_kernel<<<NROWS, 128>>>(p_src2, src, norm1_g, norm1_b, p_h1, h1H);
    // 11. ff1 = relu(h1 @ lin1_w^T + b) -> fp16
    mm_tc<<<dim3(FFD/128, NROWS/128), 128, MM_SMEM>>>(h1H, w6H,
        nullptr, lin1_b, DD, FFD, 0, 1, ff1H, 1.f, 0);
    // 12. ff2 = ff1 @ lin2_w^T + b -> fp32
    mm_tc<<<dim3(DD/128, NROWS/128), 128, MM_SMEM>>>(ff1H, w7H,
        p_ff2, lin2_b, FFD, DD, 0, 0, nullptr, 1.f, 0);
    // 13. out = LN(h1 + ff2)
    ln_kernel<<<NROWS, 128>>>(p_ff2, p_h1, norm2_g, norm2_b, outp, nullptr);
}